// round 7
// baseline (speedup 1.0000x reference)
#include <cuda_runtime.h>
#include <cuda_bf16.h>
#include <cstdint>

// Problem dims (fixed by the dataset)
#define S_LEN 128
#define B_SZ  16
#define H_DIM 1024
#define E_DIM 1024
#define G4    4096
#define V_SZ  50257
#define V_PAD 50304          // 393 * 128

// ---------------- scratch (device globals; no allocation allowed) ----------
__device__ float g_xW [S_LEN * G4 * B_SZ];       // transposed: [t][j][b]
__device__ float g_hs [S_LEN * B_SZ * H_DIM];
__device__ float g_outbuf[S_LEN * B_SZ * H_DIM];
__device__ float g_hm [B_SZ * H_DIM];
__device__ unsigned int g_flags[128];
__device__ __align__(256) __nv_bfloat16 g_a_hi[S_LEN * B_SZ * H_DIM];
__device__ __align__(256) __nv_bfloat16 g_a_lo[S_LEN * B_SZ * H_DIM];
__device__ __align__(256) __nv_bfloat16 g_b_hi[(size_t)V_PAD * H_DIM];
__device__ __align__(256) __nv_bfloat16 g_b_lo[(size_t)V_PAD * H_DIM];

// ---------------- f32x2 helpers --------------------------------------------
__device__ __forceinline__ unsigned long long dup2(float x) {
    unsigned long long r; asm("mov.b64 %0, {%1, %1};" : "=l"(r) : "f"(x)); return r;
}
__device__ __forceinline__ unsigned long long pk2(float lo, float hi) {
    unsigned long long r; asm("mov.b64 %0, {%1, %2};" : "=l"(r) : "f"(lo), "f"(hi)); return r;
}
__device__ __forceinline__ void fma2(unsigned long long& d,
                                     unsigned long long a, unsigned long long b) {
    asm("fma.rn.f32x2 %0, %1, %2, %0;" : "+l"(d) : "l"(a), "l"(b));
}
__device__ __forceinline__ float2 up2(unsigned long long v) {
    float2 f; asm("mov.b64 {%0, %1}, %2;" : "=f"(f.x), "=f"(f.y) : "l"(v)); return f;
}
__device__ __forceinline__ float sigm(float x) { return 1.0f / (1.0f + expf(-x)); }

__device__ __forceinline__ uint32_t smem_u32(const void* p) {
    uint32_t a;
    asm("{ .reg .u64 t; cvta.to.shared.u64 t, %1; cvt.u32.u64 %0, t; }"
        : "=r"(a) : "l"(p));
    return a;
}
__device__ __forceinline__ unsigned int ld_acq(const unsigned int* p) {
    unsigned int v;
    asm volatile("ld.acquire.gpu.u32 %0, [%1];" : "=r"(v) : "l"(p) : "memory");
    return v;
}
__device__ __forceinline__ void st_rel(unsigned int* p, unsigned int v) {
    asm volatile("st.release.gpu.u32 [%0], %1;" :: "l"(p), "r"(v) : "memory");
}

// ---------------- mma.sync / ldmatrix / cp.async helpers (non-'a' PTX) ------
__device__ __forceinline__ void ldsm_x4(uint32_t* r, uint32_t addr) {
    asm volatile("ldmatrix.sync.aligned.m8n8.x4.shared.b16 {%0,%1,%2,%3}, [%4];"
                 : "=r"(r[0]), "=r"(r[1]), "=r"(r[2]), "=r"(r[3]) : "r"(addr));
}
__device__ __forceinline__ void mma16816(float* c, const uint32_t* a, const uint32_t* b) {
    asm volatile(
        "mma.sync.aligned.m16n8k16.row.col.f32.bf16.bf16.f32 "
        "{%0,%1,%2,%3}, {%4,%5,%6,%7}, {%8,%9}, {%0,%1,%2,%3};"
        : "+f"(c[0]), "+f"(c[1]), "+f"(c[2]), "+f"(c[3])
        : "r"(a[0]), "r"(a[1]), "r"(a[2]), "r"(a[3]), "r"(b[0]), "r"(b[1]));
}
__device__ __forceinline__ void cp16(uint32_t dst, const void* src) {
    asm volatile("cp.async.cg.shared.global [%0], [%1], 16;" :: "r"(dst), "l"(src));
}
#define CP_COMMIT() asm volatile("cp.async.commit_group;" ::: "memory")
#define CP_WAIT1()  asm volatile("cp.async.wait_group 1;" ::: "memory")
#define CP_WAIT0()  asm volatile("cp.async.wait_group 0;" ::: "memory")

// ---------------- generic tiled fp32 GEMM (steps 1,2,5) ---------------------
// MODE 0: C = acc + bias0[n]
// MODE 1: gather-A via gidx; writes TRANSPOSED xW layout [(m/16)*G4+n]*16+(m%16)
// MODE 2: trans/mask epilogue
template <int MODE>
__global__ void __launch_bounds__(256)
gemm_k(const float* __restrict__ A, const float* __restrict__ Bm,
       float* __restrict__ C, int M, int N, int K,
       const float* __restrict__ bias0, const float* __restrict__ bias1,
       const int* __restrict__ gidx, const float* __restrict__ hmv,
       const int* __restrict__ kptr)
{
    constexpr int BM = 128, BN = 128, BK = 16;
    __shared__ float As[BK][BM + 4];
    __shared__ float Bs[BK][BN + 4];

    const int tid = threadIdx.x;
    const int bm = blockIdx.y * BM;
    const int bn = blockIdx.x * BN;
    const int tx = tid & 15;
    const int ty = tid >> 4;
    const int lr = tid >> 2;
    const int lk = (tid & 3) * 4;

    unsigned long long acc[8][4];
#pragma unroll
    for (int i = 0; i < 8; i++)
#pragma unroll
        for (int j = 0; j < 4; j++) acc[i][j] = 0ull;

    const float* arow0;
    const float* arow1;
    {
        int m0 = bm + lr, m1 = bm + lr + 64;
        if (MODE == 1) {
            arow0 = (m0 < M) ? A + (size_t)gidx[m0] * K : nullptr;
            arow1 = (m1 < M) ? A + (size_t)gidx[m1] * K : nullptr;
        } else {
            arow0 = (m0 < M) ? A + (size_t)m0 * K : nullptr;
            arow1 = (m1 < M) ? A + (size_t)m1 * K : nullptr;
        }
    }
    const int n0 = bn + lr, n1 = bn + lr + 64;
    const float* brow0 = (n0 < N) ? Bm + (size_t)n0 * K : nullptr;
    const float* brow1 = (n1 < N) ? Bm + (size_t)n1 * K : nullptr;

    const float4 fz = make_float4(0.f, 0.f, 0.f, 0.f);

    for (int k0 = 0; k0 < K; k0 += BK) {
        float4 a0 = arow0 ? *(const float4*)(arow0 + k0 + lk) : fz;
        float4 a1 = arow1 ? *(const float4*)(arow1 + k0 + lk) : fz;
        float4 b0 = brow0 ? *(const float4*)(brow0 + k0 + lk) : fz;
        float4 b1 = brow1 ? *(const float4*)(brow1 + k0 + lk) : fz;

        __syncthreads();
        As[lk + 0][lr] = a0.x;  As[lk + 1][lr] = a0.y;
        As[lk + 2][lr] = a0.z;  As[lk + 3][lr] = a0.w;
        As[lk + 0][lr + 64] = a1.x;  As[lk + 1][lr + 64] = a1.y;
        As[lk + 2][lr + 64] = a1.z;  As[lk + 3][lr + 64] = a1.w;
        Bs[lk + 0][lr] = b0.x;  Bs[lk + 1][lr] = b0.y;
        Bs[lk + 2][lr] = b0.z;  Bs[lk + 3][lr] = b0.w;
        Bs[lk + 0][lr + 64] = b1.x;  Bs[lk + 1][lr + 64] = b1.y;
        Bs[lk + 2][lr + 64] = b1.z;  Bs[lk + 3][lr + 64] = b1.w;
        __syncthreads();

#pragma unroll
        for (int kk = 0; kk < BK; kk++) {
            float4 av0 = *(const float4*)&As[kk][ty * 8];
            float4 av1 = *(const float4*)&As[kk][ty * 8 + 4];
            float4 bv0 = *(const float4*)&Bs[kk][tx * 8];
            float4 bv1 = *(const float4*)&Bs[kk][tx * 8 + 4];
            unsigned long long a2[8] = {dup2(av0.x), dup2(av0.y), dup2(av0.z), dup2(av0.w),
                                        dup2(av1.x), dup2(av1.y), dup2(av1.z), dup2(av1.w)};
            unsigned long long b2[4] = {pk2(bv0.x, bv0.y), pk2(bv0.z, bv0.w),
                                        pk2(bv1.x, bv1.y), pk2(bv1.z, bv1.w)};
#pragma unroll
            for (int i = 0; i < 8; i++)
#pragma unroll
                for (int j = 0; j < 4; j++) fma2(acc[i][j], a2[i], b2[j]);
        }
    }

    const int kval = (MODE == 2) ? *kptr : 0;

#pragma unroll
    for (int i = 0; i < 8; i++) {
        int m = bm + ty * 8 + i;
        if (m >= M) continue;
        size_t crow = (size_t)m * N;
        int srow = m >> 4;
        int b    = m & 15;
        bool cp = (MODE == 2) && (srow < kval);
#pragma unroll
        for (int j = 0; j < 4; j++) {
            float2 v = up2(acc[i][j]);
            int n = bn + tx * 8 + 2 * j;
            float vals[2] = {v.x, v.y};
#pragma unroll
            for (int u = 0; u < 2; u++) {
                int nn = n + u;
                if (nn >= N) continue;
                float r;
                if (MODE == 0)      r = vals[u] + bias0[nn];
                else if (MODE == 1) r = vals[u] + bias0[nn] + bias1[nn];
                else                r = cp ? A[(size_t)m * K + nn]
                                           : vals[u] + bias0[nn] + hmv[b * H_DIM + nn];
                if (MODE == 1)
                    C[((size_t)srow * G4 + nn) * 16 + b] = r;   // transposed xW
                else
                    C[crow + nn] = r;
            }
        }
    }
}

// ---------------- persistent LSTM scan --------------------------------------
// One launch. 128 blocks x 256 threads; block owns 8 hidden cols x 4 gates.
// Whh slice cached in smem once. Distributed-flag grid barrier:
// each block release-stores its own flag; 128 threads acquire-poll one each.
#define HT_STRIDE 18
#define PF_STRIDE 514
#define LP_W_FLOATS (32 * 1024)
#define LP_HT_FLOATS (H_DIM * HT_STRIDE)          // 18432 >= pf 16448
#define LP_SG 512
#define LP_SMEM ((LP_W_FLOATS + LP_HT_FLOATS + LP_SG) * 4)

__global__ void __launch_bounds__(256, 1)
lstm_scan(const float* __restrict__ h0,
          const float* __restrict__ c0,
          const float* __restrict__ Whh,
          const float* __restrict__ xW,       // [t][j][b]
          float* __restrict__ hs,
          unsigned int* __restrict__ flags)
{
    extern __shared__ float sh[];
    float* Wsm = sh;                              // [32][1024]
    float* hT  = sh + LP_W_FLOATS;                // [1024][18]
    float* pf  = hT;                              // aliases hT: [32][514]
    float* sg  = sh + LP_W_FLOATS + LP_HT_FLOATS; // [32][16]

    const int tid = threadIdx.x;
    const int hb  = blockIdx.x * 8;
    const int kt  = tid & 31;
    const int jt  = tid >> 5;

    // ---- preload W slice into smem (once) ----
#pragma unroll 4
    for (int ll = 0; ll < 32; ll++) {
        int j = (ll >> 3) * H_DIM + hb + (ll & 7);
        ((float4*)(Wsm + ll * H_DIM))[tid] =
            ((const float4*)(Whh + (size_t)j * H_DIM))[tid];
    }

    // ---- cell state in registers (threads 0..127) ----
    float cloc = 0.f;
    const int a_hil = tid >> 4;
    const int a_b   = tid & 15;
    if (tid < 128) cloc = c0[a_b * H_DIM + hb + a_hil];

    const float* wrow[4];
#pragma unroll
    for (int l = 0; l < 4; l++) wrow[l] = Wsm + (jt * 4 + l) * H_DIM + kt;

    const float* hsrc = h0;

    for (int t = 0; t < S_LEN; t++) {
        // ---- stage h transposed (L2 reads, bypass L1) ----
        {
            const int b   = tid & 15;
            const int e4b = tid >> 4;
            const float4* hp = (const float4*)(hsrc + b * H_DIM);
#pragma unroll
            for (int i = 0; i < 16; i++) {
                int e4 = e4b + 16 * i;
                float4 v = __ldcg(hp + e4);
                int e0 = e4 * 4;
                hT[(e0 + 0) * HT_STRIDE + b] = v.x;
                hT[(e0 + 1) * HT_STRIDE + b] = v.y;
                hT[(e0 + 2) * HT_STRIDE + b] = v.z;
                hT[(e0 + 3) * HT_STRIDE + b] = v.w;
            }
        }
        __syncthreads();

        // ---- partial GEMM ----
        unsigned long long acc[4][8];
#pragma unroll
        for (int l = 0; l < 4; l++)
#pragma unroll
            for (int bp = 0; bp < 8; bp++) acc[l][bp] = 0ull;

#pragma unroll 4
        for (int i = 0; i < 32; i++) {
            const int k = kt + 32 * i;
            const unsigned long long* hrow =
                (const unsigned long long*)(hT + k * HT_STRIDE);
            unsigned long long hv[8];
#pragma unroll
            for (int bp = 0; bp < 8; bp++) hv[bp] = hrow[bp];
            float w0 = wrow[0][32 * i], w1 = wrow[1][32 * i];
            float w2 = wrow[2][32 * i], w3 = wrow[3][32 * i];
            unsigned long long wd0 = dup2(w0), wd1 = dup2(w1);
            unsigned long long wd2 = dup2(w2), wd3 = dup2(w3);
#pragma unroll
            for (int bp = 0; bp < 8; bp++) {
                fma2(acc[0][bp], wd0, hv[bp]);
                fma2(acc[1][bp], wd1, hv[bp]);
                fma2(acc[2][bp], wd2, hv[bp]);
                fma2(acc[3][bp], wd3, hv[bp]);
            }
        }
        __syncthreads();   // hT reads done before pf (alias) writes

        {
            unsigned long long* pr =
                (unsigned long long*)(pf + kt * PF_STRIDE + (jt * 4) * 16);
#pragma unroll
            for (int l = 0; l < 4; l++)
#pragma unroll
                for (int bp = 0; bp < 8; bp++) pr[l * 8 + bp] = acc[l][bp];
        }
        __syncthreads();

        // ---- reduce over kt, add xW bias term ----
        {
            const int l = tid >> 3;
            const int b = (tid & 7) * 2;
            float s0 = 0.f, s1 = 0.f;
            const float* p = pf + l * 16 + b;
#pragma unroll 8
            for (int ktt = 0; ktt < 32; ktt++) {
                float2 v = *(const float2*)(p + ktt * PF_STRIDE);
                s0 += v.x; s1 += v.y;
            }
            const int j = (l >> 3) * H_DIM + hb + (l & 7);
            const float2 xv = *(const float2*)(xW + ((size_t)t * G4 + j) * 16 + b);
            sg[l * 16 + b]     = s0 + xv.x;
            sg[l * 16 + b + 1] = s1 + xv.y;
        }
        __syncthreads();

        // ---- activation + state update + publish h ----
        if (tid < 128) {
            float gi = sg[(0  + a_hil) * 16 + a_b];
            float gf = sg[(8  + a_hil) * 16 + a_b];
            float gg = sg[(16 + a_hil) * 16 + a_b];
            float go = sg[(24 + a_hil) * 16 + a_b];
            float cn = sigm(gf) * cloc + sigm(gi) * tanhf(gg);
            cloc = cn;
            hs[(size_t)t * B_SZ * H_DIM + a_b * H_DIM + hb + a_hil] =
                sigm(go) * tanhf(cn);
        }
        __syncthreads();

        // ---- distributed-flag grid barrier ----
        if (tid == 0) st_rel(&flags[blockIdx.x], (unsigned)(t + 1));
        if (tid < 128) {
            while (ld_acq(&flags[tid]) < (unsigned)(t + 1)) { }
        }
        __syncthreads();

        hsrc = hs + (size_t)t * B_SZ * H_DIM;
    }
}

// ---------------- bf16 hi/lo split kernels ----------------------------------
__global__ void __launch_bounds__(256)
split_a_k(const float* __restrict__ src, __nv_bfloat16* __restrict__ hi,
          __nv_bfloat16* __restrict__ lo, int n4)
{
    int i = blockIdx.x * blockDim.x + threadIdx.x;
    if (i >= n4) return;
    float4 v = ((const float4*)src)[i];
    float xs[4] = {v.x, v.y, v.z, v.w};
    __nv_bfloat16 h[4], l[4];
#pragma unroll
    for (int j = 0; j < 4; j++) {
        h[j] = __float2bfloat16_rn(xs[j]);
        l[j] = __float2bfloat16_rn(xs[j] - __bfloat162float(h[j]));
    }
    ((__nv_bfloat162*)hi)[2 * i]     = __halves2bfloat162(h[0], h[1]);
    ((__nv_bfloat162*)hi)[2 * i + 1] = __halves2bfloat162(h[2], h[3]);
    ((__nv_bfloat162*)lo)[2 * i]     = __halves2bfloat162(l[0], l[1]);
    ((__nv_bfloat162*)lo)[2 * i + 1] = __halves2bfloat162(l[2], l[3]);
}

__global__ void __launch_bounds__(256)
split_b_k(const float* __restrict__ src, __nv_bfloat16* __restrict__ hi,
          __nv_bfloat16* __restrict__ lo)
{
    int i = blockIdx.x * blockDim.x + threadIdx.x;
    if (i >= V_PAD * (H_DIM / 4)) return;
    int row = i >> 8;
    float4 v = make_float4(0.f, 0.f, 0.f, 0.f);
    if (row < V_SZ) v = ((const float4*)src)[i];
    float xs[4] = {v.x, v.y, v.z, v.w};
    __nv_bfloat16 h[4], l[4];
#pragma unroll
    for (int j = 0; j < 4; j++) {
        h[j] = __float2bfloat16_rn(xs[j]);
        l[j] = __float2bfloat16_rn(xs[j] - __bfloat162float(h[j]));
    }
    ((__nv_bfloat162*)hi)[2 * i]     = __halves2bfloat162(h[0], h[1]);
    ((__nv_bfloat162*)hi)[2 * i + 1] = __halves2bfloat162(h[2], h[3]);
    ((__nv_bfloat162*)lo)[2 * i]     = __halves2bfloat162(l[0], l[1]);
    ((__nv_bfloat162*)lo)[2 * i + 1] = __halves2bfloat162(l[2], l[3]);
}

// ---------------- mma.sync decoder GEMM (3-stage pipeline) ------------------
#define DROW 40

__global__ void __launch_bounds__(256, 1)
dec_gemm(const __nv_bfloat16* __restrict__ a_hi, const __nv_bfloat16* __restrict__ a_lo,
         const __nv_bfloat16* __restrict__ b_hi, const __nv_bfloat16* __restrict__ b_lo,
         const float* __restrict__ bias, float* __restrict__ out)
{
    __shared__ __align__(16) __nv_bfloat16 As[3][128 * DROW];
    __shared__ __align__(16) __nv_bfloat16 Bs[3][128 * DROW];

    const int tid  = threadIdx.x;
    const int lane = tid & 31;
    const int warp = tid >> 5;
    const int warpM = warp >> 2;
    const int warpN = warp & 3;
    const int bm = blockIdx.y * 128;
    const int bn = blockIdx.x * 128;

    const uint32_t sA[3] = { smem_u32(As[0]), smem_u32(As[1]), smem_u32(As[2]) };
    const uint32_t sB[3] = { smem_u32(Bs[0]), smem_u32(Bs[1]), smem_u32(Bs[2]) };

    float acc[4][4][4];
#pragma unroll
    for (int i = 0; i < 4; i++)
#pragma unroll
        for (int j = 0; j < 4; j++)
#pragma unroll
            for (int r = 0; r < 4; r++) acc[i][j][r] = 0.f;

    const int r0c = tid >> 2, c0c = tid & 3;
    const int r1c = (tid + 256) >> 2, c1c = tid & 3;

    auto issue = [&](int it, int buf) {
        const int p  = it >> 5;
        const int k0 = (it & 31) * 32;
        const __nv_bfloat16* Ap = (p < 2) ? a_hi : a_lo;
        const __nv_bfloat16* Bp = (p == 1) ? b_lo : b_hi;
        cp16(sA[buf] + (r0c * DROW + c0c * 8) * 2,
             Ap + (size_t)(bm + r0c) * H_DIM + k0 + c0c * 8);
        cp16(sA[buf] + (r1c * DROW + c1c * 8) * 2,
             Ap + (size_t)(bm + r1c) * H_DIM + k0 + c1c * 8);
        cp16(sB[buf] + (r0c * DROW + c0c * 8) * 2,
             Bp + (size_t)(bn + r0c) * H_DIM + k0 + c0c * 8);
        cp16(sB[buf] + (r1c * DROW + c1c * 8) * 2,
             Bp + (size_t)(bn + r1c) * H_DIM + k0 + c1c * 8);
    };

    issue(0, 0); CP_COMMIT();
    issue(1, 1); CP_COMMIT();

    for (int it = 0; it < 96; it++) {
        const int buf = it % 3;
        if (it + 1 < 96) CP_WAIT1(); else CP_WAIT0();
        __syncthreads();
        if (it + 2 < 96) { issue(it + 2, (it + 2) % 3); CP_COMMIT(); }

#pragma unroll
        for (int ks = 0; ks < 2; ks++) {
            uint32_t af[4][4];
#pragma unroll
            for (int mf = 0; mf < 4; mf++) {
                int row = warpM * 64 + mf * 16 + (lane & 15);
                int ch  = ks * 2 + (lane >> 4);
                ldsm_x4(af[mf], sA[buf] + (row * DROW + ch * 8) * 2);
            }
            uint32_t br[2][4];
#pragma unroll
            for (int g = 0; g < 2; g++) {
                int row = warpN * 32 + g * 16 + ((lane >> 4) << 3) + (lane & 7);
                int ch  = ks * 2 + ((lane >> 3) & 1);
                ldsm_x4(br[g], sB[buf] + (row * DROW + ch * 8) * 2);
            }
#pragma unroll
            for (int mf = 0; mf < 4; mf++)
#pragma unroll
                for (int g = 0; g < 2; g++) {
                    mma16816(acc[mf][g * 2],     af[mf], &br[g][0]);
                    mma16816(acc[mf][g * 2 + 1], af[mf], &br[g][2]);
                }
        }
    }

#pragma unroll
    for (int mf = 0; mf < 4; mf++) {
        int rowA = bm + warpM * 64 + mf * 16 + (lane >> 2);
        int rowB = rowA + 8;
#pragma unroll
        for (int nf = 0; nf < 4; nf++) {
            int col = bn + warpN * 32 + nf * 8 + (lane & 3) * 2;
            float b0 = (col     < V_SZ) ? bias[col]     : 0.f;
            float b1 = (col + 1 < V_SZ) ? bias[col + 1] : 0.f;
            if (col < V_SZ)     out[(size_t)rowA * V_SZ + col]     = acc[mf][nf][0] + b0;
            if (col + 1 < V_SZ) out[(size_t)rowA * V_SZ + col + 1] = acc[mf][nf][1] + b1;
            if (col < V_SZ)     out[(size_t)rowB * V_SZ + col]     = acc[mf][nf][2] + b0;
            if (col + 1 < V_SZ) out[(size_t)rowB * V_SZ + col + 1] = acc[mf][nf][3] + b1;
        }
    }
}

// ---------------- launcher --------------------------------------------------
extern "C" void kernel_launch(void* const* d_in, const int* in_sizes, int n_in,
                              void* d_out, int out_size)
{
    const int*   tokens = (const int*)  d_in[0];
    const float* h0     = (const float*)d_in[1];
    const float* c0     = (const float*)d_in[2];
    const float* emb    = (const float*)d_in[3];
    const float* Wih    = (const float*)d_in[4];
    const float* Whh    = (const float*)d_in[5];
    const float* bih    = (const float*)d_in[6];
    const float* bhh    = (const float*)d_in[7];
    const float* Whh2   = (const float*)d_in[8];
    const float* bhh2   = (const float*)d_in[9];
    const float* Whm    = (const float*)d_in[10];
    const float* bhm    = (const float*)d_in[11];
    const float* decW   = (const float*)d_in[12];
    const float* decb   = (const float*)d_in[13];
    const int*   kp     = (const int*)  d_in[14];
    float* out = (float*)d_out;

    void *p_xW, *p_hs, *p_outb, *p_hm, *p_fl, *p_ah, *p_al, *p_bh, *p_bl;
    cudaGetSymbolAddress(&p_xW,   g_xW);
    cudaGetSymbolAddress(&p_hs,   g_hs);
    cudaGetSymbolAddress(&p_outb, g_outbuf);
    cudaGetSymbolAddress(&p_hm,   g_hm);
    cudaGetSymbolAddress(&p_fl,   g_flags);
    cudaGetSymbolAddress(&p_ah,   g_a_hi);
    cudaGetSymbolAddress(&p_al,   g_a_lo);
    cudaGetSymbolAddress(&p_bh,   g_b_hi);
    cudaGetSymbolAddress(&p_bl,   g_b_lo);
    float* xW   = (float*)p_xW;
    float* hs   = (float*)p_hs;
    float* ob   = (float*)p_outb;
    float* hm   = (float*)p_hm;
    unsigned int* flags = (unsigned int*)p_fl;
    __nv_bfloat16* ah = (__nv_bfloat16*)p_ah;
    __nv_bfloat16* al = (__nv_bfloat16*)p_al;
    __nv_bfloat16* bh = (__nv_bfloat16*)p_bh;
    __nv_bfloat16* bl = (__nv_bfloat16*)p_bl;

    cudaFuncSetAttribute(lstm_scan, cudaFuncAttributeMaxDynamicSharedMemorySize,
                         LP_SMEM);

    const int M = S_LEN * B_SZ;   // 2048

    // 1) xW = gather(emb, tokens) @ Wih^T + bih + bhh  -> transposed [t][j][b]
    gemm_k<1><<<dim3(G4 / 128, M / 128), 256>>>(
        emb, Wih, xW, M, G4, E_DIM, bih, bhh, tokens, nullptr, nullptr);

    // split decW -> bf16 hi/lo (padded to V_PAD rows)
    split_b_k<<<(V_PAD * H_DIM / 4 + 255) / 256, 256>>>(decW, bh, bl);

    // 2) hm = h0 @ Whm^T + bhm
    gemm_k<0><<<dim3(H_DIM / 128, 1), 256>>>(
        h0, Whm, hm, B_SZ, H_DIM, H_DIM, bhm, nullptr, nullptr, nullptr, nullptr);

    // 3) reset barrier flags
    cudaMemsetAsync(flags, 0, 128 * sizeof(unsigned int), 0);

    // 4) persistent LSTM scan (one launch, 128 internal steps)
    lstm_scan<<<128, 256, LP_SMEM>>>(h0, c0, Whh, xW, hs, flags);

    // 5) outputs = (s<k) ? hs : hs @ Whh2^T + bhh2 + hm
    gemm_k<2><<<dim3(H_DIM / 128, M / 128), 256>>>(
        hs, Whh2, ob, M, H_DIM, H_DIM, bhh2, nullptr, nullptr, hm, kp);

    // split outputs -> bf16 hi/lo
    split_a_k<<<(M * H_DIM / 4 + 255) / 256, 256>>>(ob, ah, al, M * H_DIM / 4);

    // 6) decoded = outputs @ decW^T + decb  — mma.sync bf16-split GEMM
    dec_gemm<<<dim3(V_PAD / 128, M / 128), 256>>>(ah, al, bh, bl, decb, out);

    (void)in_sizes; (void)n_in; (void)out_size;
}

// round 8
// speedup vs baseline: 1.1590x; 1.1590x over previous
#include <cuda_runtime.h>
#include <cuda_bf16.h>
#include <cstdint>

// Problem dims (fixed by the dataset)
#define S_LEN 128
#define B_SZ  16
#define H_DIM 1024
#define E_DIM 1024
#define G4    4096
#define V_SZ  50257
#define V_PAD 50304          // 393 * 128

// ---------------- scratch (device globals; no allocation allowed) ----------
__device__ float g_xW [S_LEN * G4 * B_SZ];       // transposed: [t][j][b]
__device__ float g_hs [S_LEN * B_SZ * H_DIM];
__device__ float g_outbuf[S_LEN * B_SZ * H_DIM];
__device__ float g_hm [B_SZ * H_DIM];
__device__ unsigned int g_bar;
__device__ __align__(256) __nv_bfloat16 g_a_hi[S_LEN * B_SZ * H_DIM];
__device__ __align__(256) __nv_bfloat16 g_a_lo[S_LEN * B_SZ * H_DIM];
__device__ __align__(256) __nv_bfloat16 g_b_hi[(size_t)V_PAD * H_DIM];
__device__ __align__(256) __nv_bfloat16 g_b_lo[(size_t)V_PAD * H_DIM];

// ---------------- f32x2 helpers --------------------------------------------
__device__ __forceinline__ unsigned long long dup2(float x) {
    unsigned long long r; asm("mov.b64 %0, {%1, %1};" : "=l"(r) : "f"(x)); return r;
}
__device__ __forceinline__ unsigned long long pk2(float lo, float hi) {
    unsigned long long r; asm("mov.b64 %0, {%1, %2};" : "=l"(r) : "f"(lo), "f"(hi)); return r;
}
__device__ __forceinline__ void fma2(unsigned long long& d,
                                     unsigned long long a, unsigned long long b) {
    asm("fma.rn.f32x2 %0, %1, %2, %0;" : "+l"(d) : "l"(a), "l"(b));
}
__device__ __forceinline__ float2 up2(unsigned long long v) {
    float2 f; asm("mov.b64 {%0, %1}, %2;" : "=f"(f.x), "=f"(f.y) : "l"(v)); return f;
}
__device__ __forceinline__ float sigm(float x) { return 1.0f / (1.0f + expf(-x)); }

__device__ __forceinline__ uint32_t smem_u32(const void* p) {
    uint32_t a;
    asm("{ .reg .u64 t; cvta.to.shared.u64 t, %1; cvt.u32.u64 %0, t; }"
        : "=r"(a) : "l"(p));
    return a;
}
__device__ __forceinline__ unsigned int ld_acq(const unsigned int* p) {
    unsigned int v;
    asm volatile("ld.acquire.gpu.u32 %0, [%1];" : "=r"(v) : "l"(p) : "memory");
    return v;
}
__device__ __forceinline__ void red_rel_add(unsigned int* p, unsigned int v) {
    asm volatile("red.release.gpu.global.add.u32 [%0], %1;" :: "l"(p), "r"(v) : "memory");
}

// ---------------- mma.sync / ldmatrix / cp.async helpers (non-'a' PTX) ------
__device__ __forceinline__ void ldsm_x4(uint32_t* r, uint32_t addr) {
    asm volatile("ldmatrix.sync.aligned.m8n8.x4.shared.b16 {%0,%1,%2,%3}, [%4];"
                 : "=r"(r[0]), "=r"(r[1]), "=r"(r[2]), "=r"(r[3]) : "r"(addr));
}
__device__ __forceinline__ void mma16816(float* c, const uint32_t* a, const uint32_t* b) {
    asm volatile(
        "mma.sync.aligned.m16n8k16.row.col.f32.bf16.bf16.f32 "
        "{%0,%1,%2,%3}, {%4,%5,%6,%7}, {%8,%9}, {%0,%1,%2,%3};"
        : "+f"(c[0]), "+f"(c[1]), "+f"(c[2]), "+f"(c[3])
        : "r"(a[0]), "r"(a[1]), "r"(a[2]), "r"(a[3]), "r"(b[0]), "r"(b[1]));
}
__device__ __forceinline__ void cp16(uint32_t dst, const void* src) {
    asm volatile("cp.async.cg.shared.global [%0], [%1], 16;" :: "r"(dst), "l"(src));
}
#define CP_COMMIT() asm volatile("cp.async.commit_group;" ::: "memory")
#define CP_WAIT1()  asm volatile("cp.async.wait_group 1;" ::: "memory")
#define CP_WAIT0()  asm volatile("cp.async.wait_group 0;" ::: "memory")

// ---------------- generic tiled fp32 GEMM (steps 1,2,5) ---------------------
template <int MODE>
__global__ void __launch_bounds__(256)
gemm_k(const float* __restrict__ A, const float* __restrict__ Bm,
       float* __restrict__ C, int M, int N, int K,
       const float* __restrict__ bias0, const float* __restrict__ bias1,
       const int* __restrict__ gidx, const float* __restrict__ hmv,
       const int* __restrict__ kptr)
{
    constexpr int BM = 128, BN = 128, BK = 16;
    __shared__ float As[BK][BM + 4];
    __shared__ float Bs[BK][BN + 4];

    const int tid = threadIdx.x;
    const int bm = blockIdx.y * BM;
    const int bn = blockIdx.x * BN;
    const int tx = tid & 15;
    const int ty = tid >> 4;
    const int lr = tid >> 2;
    const int lk = (tid & 3) * 4;

    unsigned long long acc[8][4];
#pragma unroll
    for (int i = 0; i < 8; i++)
#pragma unroll
        for (int j = 0; j < 4; j++) acc[i][j] = 0ull;

    const float* arow0;
    const float* arow1;
    {
        int m0 = bm + lr, m1 = bm + lr + 64;
        if (MODE == 1) {
            arow0 = (m0 < M) ? A + (size_t)gidx[m0] * K : nullptr;
            arow1 = (m1 < M) ? A + (size_t)gidx[m1] * K : nullptr;
        } else {
            arow0 = (m0 < M) ? A + (size_t)m0 * K : nullptr;
            arow1 = (m1 < M) ? A + (size_t)m1 * K : nullptr;
        }
    }
    const int n0 = bn + lr, n1 = bn + lr + 64;
    const float* brow0 = (n0 < N) ? Bm + (size_t)n0 * K : nullptr;
    const float* brow1 = (n1 < N) ? Bm + (size_t)n1 * K : nullptr;

    const float4 fz = make_float4(0.f, 0.f, 0.f, 0.f);

    for (int k0 = 0; k0 < K; k0 += BK) {
        float4 a0 = arow0 ? *(const float4*)(arow0 + k0 + lk) : fz;
        float4 a1 = arow1 ? *(const float4*)(arow1 + k0 + lk) : fz;
        float4 b0 = brow0 ? *(const float4*)(brow0 + k0 + lk) : fz;
        float4 b1 = brow1 ? *(const float4*)(brow1 + k0 + lk) : fz;

        __syncthreads();
        As[lk + 0][lr] = a0.x;  As[lk + 1][lr] = a0.y;
        As[lk + 2][lr] = a0.z;  As[lk + 3][lr] = a0.w;
        As[lk + 0][lr + 64] = a1.x;  As[lk + 1][lr + 64] = a1.y;
        As[lk + 2][lr + 64] = a1.z;  As[lk + 3][lr + 64] = a1.w;
        Bs[lk + 0][lr] = b0.x;  Bs[lk + 1][lr] = b0.y;
        Bs[lk + 2][lr] = b0.z;  Bs[lk + 3][lr] = b0.w;
        Bs[lk + 0][lr + 64] = b1.x;  Bs[lk + 1][lr + 64] = b1.y;
        Bs[lk + 2][lr + 64] = b1.z;  Bs[lk + 3][lr + 64] = b1.w;
        __syncthreads();

#pragma unroll
        for (int kk = 0; kk < BK; kk++) {
            float4 av0 = *(const float4*)&As[kk][ty * 8];
            float4 av1 = *(const float4*)&As[kk][ty * 8 + 4];
            float4 bv0 = *(const float4*)&Bs[kk][tx * 8];
            float4 bv1 = *(const float4*)&Bs[kk][tx * 8 + 4];
            unsigned long long a2[8] = {dup2(av0.x), dup2(av0.y), dup2(av0.z), dup2(av0.w),
                                        dup2(av1.x), dup2(av1.y), dup2(av1.z), dup2(av1.w)};
            unsigned long long b2[4] = {pk2(bv0.x, bv0.y), pk2(bv0.z, bv0.w),
                                        pk2(bv1.x, bv1.y), pk2(bv1.z, bv1.w)};
#pragma unroll
            for (int i = 0; i < 8; i++)
#pragma unroll
                for (int j = 0; j < 4; j++) fma2(acc[i][j], a2[i], b2[j]);
        }
    }

    const int kval = (MODE == 2) ? *kptr : 0;

#pragma unroll
    for (int i = 0; i < 8; i++) {
        int m = bm + ty * 8 + i;
        if (m >= M) continue;
        size_t crow = (size_t)m * N;
        int srow = m >> 4;
        int b    = m & 15;
        bool cp = (MODE == 2) && (srow < kval);
#pragma unroll
        for (int j = 0; j < 4; j++) {
            float2 v = up2(acc[i][j]);
            int n = bn + tx * 8 + 2 * j;
            float vals[2] = {v.x, v.y};
#pragma unroll
            for (int u = 0; u < 2; u++) {
                int nn = n + u;
                if (nn >= N) continue;
                float r;
                if (MODE == 0)      r = vals[u] + bias0[nn];
                else if (MODE == 1) r = vals[u] + bias0[nn] + bias1[nn];
                else                r = cp ? A[(size_t)m * K + nn]
                                           : vals[u] + bias0[nn] + hmv[b * H_DIM + nn];
                if (MODE == 1)
                    C[((size_t)srow * G4 + nn) * 16 + b] = r;   // transposed xW
                else
                    C[crow + nn] = r;
            }
        }
    }
}

// ---------------- persistent LSTM scan (512 threads, 64-way K split) --------
// 128 blocks x 512 threads; block owns 8 hidden cols x 4 gates (32 gate cols).
// kt = tid&63 covers k = kt + 64*i (16 iters); cg = tid>>6 owns 4 gate cols.
// Whh slice in smem once. 3-phase reduction through pf (aliases hT).
// Grid barrier: single counter, release-add + acquire-poll by thread 0.
#define HT_STRIDE 18
#define PF_STRIDE 514
#define LP_W_FLOATS (32 * 1024)
#define LP_HT_FLOATS (H_DIM * HT_STRIDE)          // 18432 >= pf 32*514=16448
#define LP_SG 512
#define LP_SMEM ((LP_W_FLOATS + LP_HT_FLOATS + LP_SG) * 4)

__global__ void __launch_bounds__(512, 1)
lstm_scan(const float* __restrict__ h0,
          const float* __restrict__ c0,
          const float* __restrict__ Whh,
          const float* __restrict__ xW,       // [t][j][b]
          float* __restrict__ hs,
          unsigned int* __restrict__ bar)
{
    extern __shared__ float sh[];
    float* Wsm = sh;                              // [32][1024]
    float* hT  = sh + LP_W_FLOATS;                // [1024][18]
    float* pf  = hT;                              // aliases hT: [32][514]
    float* sg  = sh + LP_W_FLOATS + LP_HT_FLOATS; // [32][16]

    const int tid = threadIdx.x;
    const int hb  = blockIdx.x * 8;
    const int kt  = tid & 63;
    const int cg  = tid >> 6;                     // 0..7, owns cols cg*4..+3

    // ---- preload W slice into smem (once) ----
    for (int idx = tid; idx < 32 * 256; idx += 512) {
        int ll = idx >> 8;                        // 0..31
        int c4 = idx & 255;
        int j  = (ll >> 3) * H_DIM + hb + (ll & 7);
        ((float4*)(Wsm + ll * H_DIM))[c4] =
            ((const float4*)(Whh + (size_t)j * H_DIM))[c4];
    }

    // ---- cell state in registers (threads 0..127) ----
    float cloc = 0.f;
    const int a_hil = tid >> 4;
    const int a_b   = tid & 15;
    if (tid < 128) cloc = c0[a_b * H_DIM + hb + a_hil];

    const float* wrow[4];
#pragma unroll
    for (int l = 0; l < 4; l++) wrow[l] = Wsm + (cg * 4 + l) * H_DIM + kt;

    const unsigned long long ONE2 = dup2(1.0f);
    const float* hsrc = h0;

    for (int t = 0; t < S_LEN; t++) {
        // ---- stage h transposed (L2 reads, bypass L1) ----
        {
            const int b   = tid & 15;
            const int e4b = tid >> 4;            // 0..31
            const float4* hp = (const float4*)(hsrc + b * H_DIM);
#pragma unroll
            for (int i = 0; i < 8; i++) {
                int e4 = e4b + 32 * i;
                float4 v = __ldcg(hp + e4);
                int e0 = e4 * 4;
                hT[(e0 + 0) * HT_STRIDE + b] = v.x;
                hT[(e0 + 1) * HT_STRIDE + b] = v.y;
                hT[(e0 + 2) * HT_STRIDE + b] = v.z;
                hT[(e0 + 3) * HT_STRIDE + b] = v.w;
            }
        }
        __syncthreads();

        // ---- partial GEMM: k = kt + 64*i ----
        unsigned long long acc[4][8];
#pragma unroll
        for (int l = 0; l < 4; l++)
#pragma unroll
            for (int bp = 0; bp < 8; bp++) acc[l][bp] = 0ull;

#pragma unroll 4
        for (int i = 0; i < 16; i++) {
            const int k = kt + 64 * i;
            const unsigned long long* hrow =
                (const unsigned long long*)(hT + k * HT_STRIDE);
            unsigned long long hv[8];
#pragma unroll
            for (int bp = 0; bp < 8; bp++) hv[bp] = hrow[bp];
            float w0 = wrow[0][64 * i], w1 = wrow[1][64 * i];
            float w2 = wrow[2][64 * i], w3 = wrow[3][64 * i];
            unsigned long long wd0 = dup2(w0), wd1 = dup2(w1);
            unsigned long long wd2 = dup2(w2), wd3 = dup2(w3);
#pragma unroll
            for (int bp = 0; bp < 8; bp++) {
                fma2(acc[0][bp], wd0, hv[bp]);
                fma2(acc[1][bp], wd1, hv[bp]);
                fma2(acc[2][bp], wd2, hv[bp]);
                fma2(acc[3][bp], wd3, hv[bp]);
            }
        }
        __syncthreads();   // hT reads done before pf (alias) writes

        // ---- Phase A: upper-half threads (kt>=32) store partials ----
        if (kt >= 32) {
            unsigned long long* pr =
                (unsigned long long*)(pf + (kt - 32) * PF_STRIDE) + cg * 32;
#pragma unroll
            for (int l = 0; l < 4; l++)
#pragma unroll
                for (int bp = 0; bp < 8; bp++) pr[l * 8 + bp] = acc[l][bp];
        }
        __syncthreads();

        // ---- Phase B: lower-half threads fold in row kt, store back ----
        if (kt < 32) {
            unsigned long long* pr =
                (unsigned long long*)(pf + kt * PF_STRIDE) + cg * 32;
#pragma unroll
            for (int l = 0; l < 4; l++)
#pragma unroll
                for (int bp = 0; bp < 8; bp++)
                    fma2(acc[l][bp], ONE2, pr[l * 8 + bp]);
#pragma unroll
            for (int l = 0; l < 4; l++)
#pragma unroll
                for (int bp = 0; bp < 8; bp++) pr[l * 8 + bp] = acc[l][bp];
        }
        __syncthreads();

        // ---- Phase C: one thread per output element, reduce over 32 rows ----
        {
            const int l = tid >> 4;              // 0..31 (gate*8+hil)
            const int b = tid & 15;
            float s = 0.f;
            const float* p = pf + l * 16 + b;
#pragma unroll 8
            for (int r = 0; r < 32; r++) s += p[r * PF_STRIDE];
            const int j = (l >> 3) * H_DIM + hb + (l & 7);
            sg[l * 16 + b] = s + xW[((size_t)t * G4 + j) * 16 + b];
        }
        __syncthreads();

        // ---- activation + state update + publish h ----
        if (tid < 128) {
            float gi = sg[(0  + a_hil) * 16 + a_b];
            float gf = sg[(8  + a_hil) * 16 + a_b];
            float gg = sg[(16 + a_hil) * 16 + a_b];
            float go = sg[(24 + a_hil) * 16 + a_b];
            float cn = sigm(gf) * cloc + sigm(gi) * tanhf(gg);
            cloc = cn;
            hs[(size_t)t * B_SZ * H_DIM + a_b * H_DIM + hb + a_hil] =
                sigm(go) * tanhf(cn);
        }
        __syncthreads();

        // ---- grid barrier: release-add, acquire-poll (thread 0 only) ----
        if (tid == 0) {
            red_rel_add(bar, 1u);
            const unsigned int target = 128u * (unsigned)(t + 1);
            while (ld_acq(bar) < target) { }
        }
        __syncthreads();

        hsrc = hs + (size_t)t * B_SZ * H_DIM;
    }
}

// ---------------- bf16 hi/lo split kernels ----------------------------------
__global__ void __launch_bounds__(256)
split_a_k(const float* __restrict__ src, __nv_bfloat16* __restrict__ hi,
          __nv_bfloat16* __restrict__ lo, int n4)
{
    int i = blockIdx.x * blockDim.x + threadIdx.x;
    if (i >= n4) return;
    float4 v = ((const float4*)src)[i];
    float xs[4] = {v.x, v.y, v.z, v.w};
    __nv_bfloat16 h[4], l[4];
#pragma unroll
    for (int j = 0; j < 4; j++) {
        h[j] = __float2bfloat16_rn(xs[j]);
        l[j] = __float2bfloat16_rn(xs[j] - __bfloat162float(h[j]));
    }
    ((__nv_bfloat162*)hi)[2 * i]     = __halves2bfloat162(h[0], h[1]);
    ((__nv_bfloat162*)hi)[2 * i + 1] = __halves2bfloat162(h[2], h[3]);
    ((__nv_bfloat162*)lo)[2 * i]     = __halves2bfloat162(l[0], l[1]);
    ((__nv_bfloat162*)lo)[2 * i + 1] = __halves2bfloat162(l[2], l[3]);
}

__global__ void __launch_bounds__(256)
split_b_k(const float* __restrict__ src, __nv_bfloat16* __restrict__ hi,
          __nv_bfloat16* __restrict__ lo)
{
    int i = blockIdx.x * blockDim.x + threadIdx.x;
    if (i >= V_PAD * (H_DIM / 4)) return;
    int row = i >> 8;
    float4 v = make_float4(0.f, 0.f, 0.f, 0.f);
    if (row < V_SZ) v = ((const float4*)src)[i];
    float xs[4] = {v.x, v.y, v.z, v.w};
    __nv_bfloat16 h[4], l[4];
#pragma unroll
    for (int j = 0; j < 4; j++) {
        h[j] = __float2bfloat16_rn(xs[j]);
        l[j] = __float2bfloat16_rn(xs[j] - __bfloat162float(h[j]));
    }
    ((__nv_bfloat162*)hi)[2 * i]     = __halves2bfloat162(h[0], h[1]);
    ((__nv_bfloat162*)hi)[2 * i + 1] = __halves2bfloat162(h[2], h[3]);
    ((__nv_bfloat162*)lo)[2 * i]     = __halves2bfloat162(l[0], l[1]);
    ((__nv_bfloat162*)lo)[2 * i + 1] = __halves2bfloat162(l[2], l[3]);
}

// ---------------- mma.sync decoder GEMM (R6 2-stage, proven) ----------------
#define DROW 40

__global__ void __launch_bounds__(256, 1)
dec_gemm(const __nv_bfloat16* __restrict__ a_hi, const __nv_bfloat16* __restrict__ a_lo,
         const __nv_bfloat16* __restrict__ b_hi, const __nv_bfloat16* __restrict__ b_lo,
         const float* __restrict__ bias, float* __restrict__ out)
{
    __shared__ __align__(16) __nv_bfloat16 As[2][128 * DROW];
    __shared__ __align__(16) __nv_bfloat16 Bs[2][128 * DROW];

    const int tid  = threadIdx.x;
    const int lane = tid & 31;
    const int warp = tid >> 5;
    const int warpM = warp >> 2;
    const int warpN = warp & 3;
    const int bm = blockIdx.y * 128;
    const int bn = blockIdx.x * 128;

    const uint32_t sA[2] = { smem_u32(As[0]), smem_u32(As[1]) };
    const uint32_t sB[2] = { smem_u32(Bs[0]), smem_u32(Bs[1]) };

    float acc[4][4][4];
#pragma unroll
    for (int i = 0; i < 4; i++)
#pragma unroll
        for (int j = 0; j < 4; j++)
#pragma unroll
            for (int r = 0; r < 4; r++) acc[i][j][r] = 0.f;

    const int r0c = tid >> 2, c0c = tid & 3;
    const int r1c = (tid + 256) >> 2, c1c = tid & 3;

    auto issue = [&](int it, int buf) {
        const int p  = it >> 5;
        const int k0 = (it & 31) * 32;
        const __nv_bfloat16* Ap = (p < 2) ? a_hi : a_lo;
        const __nv_bfloat16* Bp = (p == 1) ? b_lo : b_hi;
        cp16(sA[buf] + (r0c * DROW + c0c * 8) * 2,
             Ap + (size_t)(bm + r0c) * H_DIM + k0 + c0c * 8);
        cp16(sA[buf] + (r1c * DROW + c1c * 8) * 2,
             Ap + (size_t)(bm + r1c) * H_DIM + k0 + c1c * 8);
        cp16(sB[buf] + (r0c * DROW + c0c * 8) * 2,
             Bp + (size_t)(bn + r0c) * H_DIM + k0 + c0c * 8);
        cp16(sB[buf] + (r1c * DROW + c1c * 8) * 2,
             Bp + (size_t)(bn + r1c) * H_DIM + k0 + c1c * 8);
    };

    issue(0, 0);
    CP_COMMIT();

    for (int it = 0; it < 96; it++) {
        const int buf = it & 1;
        if (it + 1 < 96) { issue(it + 1, buf ^ 1); CP_COMMIT(); CP_WAIT1(); }
        else             { CP_WAIT0(); }
        __syncthreads();

#pragma unroll
        for (int ks = 0; ks < 2; ks++) {
            uint32_t af[4][4];
#pragma unroll
            for (int mf = 0; mf < 4; mf++) {
                int row = warpM * 64 + mf * 16 + (lane & 15);
                int ch  = ks * 2 + (lane >> 4);
                ldsm_x4(af[mf], sA[buf] + (row * DROW + ch * 8) * 2);
            }
            uint32_t br[2][4];
#pragma unroll
            for (int g = 0; g < 2; g++) {
                int row = warpN * 32 + g * 16 + ((lane >> 4) << 3) + (lane & 7);
                int ch  = ks * 2 + ((lane >> 3) & 1);
                ldsm_x4(br[g], sB[buf] + (row * DROW + ch * 8) * 2);
            }
#pragma unroll
            for (int mf = 0; mf < 4; mf++)
#pragma unroll
                for (int g = 0; g < 2; g++) {
                    mma16816(acc[mf][g * 2],     af[mf], &br[g][0]);
                    mma16816(acc[mf][g * 2 + 1], af[mf], &br[g][2]);
                }
        }
        __syncthreads();
    }

#pragma unroll
    for (int mf = 0; mf < 4; mf++) {
        int rowA = bm + warpM * 64 + mf * 16 + (lane >> 2);
        int rowB = rowA + 8;
#pragma unroll
        for (int nf = 0; nf < 4; nf++) {
            int col = bn + warpN * 32 + nf * 8 + (lane & 3) * 2;
            float b0 = (col     < V_SZ) ? bias[col]     : 0.f;
            float b1 = (col + 1 < V_SZ) ? bias[col + 1] : 0.f;
            if (col < V_SZ)     out[(size_t)rowA * V_SZ + col]     = acc[mf][nf][0] + b0;
            if (col + 1 < V_SZ) out[(size_t)rowA * V_SZ + col + 1] = acc[mf][nf][1] + b1;
            if (col < V_SZ)     out[(size_t)rowB * V_SZ + col]     = acc[mf][nf][2] + b0;
            if (col + 1 < V_SZ) out[(size_t)rowB * V_SZ + col + 1] = acc[mf][nf][3] + b1;
        }
    }
}

// ---------------- launcher --------------------------------------------------
extern "C" void kernel_launch(void* const* d_in, const int* in_sizes, int n_in,
                              void* d_out, int out_size)
{
    const int*   tokens = (const int*)  d_in[0];
    const float* h0     = (const float*)d_in[1];
    const float* c0     = (const float*)d_in[2];
    const float* emb    = (const float*)d_in[3];
    const float* Wih    = (const float*)d_in[4];
    const float* Whh    = (const float*)d_in[5];
    const float* bih    = (const float*)d_in[6];
    const float* bhh    = (const float*)d_in[7];
    const float* Whh2   = (const float*)d_in[8];
    const float* bhh2   = (const float*)d_in[9];
    const float* Whm    = (const float*)d_in[10];
    const float* bhm    = (const float*)d_in[11];
    const float* decW   = (const float*)d_in[12];
    const float* decb   = (const float*)d_in[13];
    const int*   kp     = (const int*)  d_in[14];
    float* out = (float*)d_out;

    void *p_xW, *p_hs, *p_outb, *p_hm, *p_bar, *p_ah, *p_al, *p_bh, *p_bl;
    cudaGetSymbolAddress(&p_xW,   g_xW);
    cudaGetSymbolAddress(&p_hs,   g_hs);
    cudaGetSymbolAddress(&p_outb, g_outbuf);
    cudaGetSymbolAddress(&p_hm,   g_hm);
    cudaGetSymbolAddress(&p_bar,  g_bar);
    cudaGetSymbolAddress(&p_ah,   g_a_hi);
    cudaGetSymbolAddress(&p_al,   g_a_lo);
    cudaGetSymbolAddress(&p_bh,   g_b_hi);
    cudaGetSymbolAddress(&p_bl,   g_b_lo);
    float* xW   = (float*)p_xW;
    float* hs   = (float*)p_hs;
    float* ob   = (float*)p_outb;
    float* hm   = (float*)p_hm;
    unsigned int* bar = (unsigned int*)p_bar;
    __nv_bfloat16* ah = (__nv_bfloat16*)p_ah;
    __nv_bfloat16* al = (__nv_bfloat16*)p_al;
    __nv_bfloat16* bh = (__nv_bfloat16*)p_bh;
    __nv_bfloat16* bl = (__nv_bfloat16*)p_bl;

    cudaFuncSetAttribute(lstm_scan, cudaFuncAttributeMaxDynamicSharedMemorySize,
                         LP_SMEM);

    const int M = S_LEN * B_SZ;   // 2048

    // 1) xW = gather(emb, tokens) @ Wih^T + bih + bhh  -> transposed [t][j][b]
    gemm_k<1><<<dim3(G4 / 128, M / 128), 256>>>(
        emb, Wih, xW, M, G4, E_DIM, bih, bhh, tokens, nullptr, nullptr);

    // split decW -> bf16 hi/lo (padded to V_PAD rows)
    split_b_k<<<(V_PAD * H_DIM / 4 + 255) / 256, 256>>>(decW, bh, bl);

    // 2) hm = h0 @ Whm^T + bhm
    gemm_k<0><<<dim3(H_DIM / 128, 1), 256>>>(
        h0, Whm, hm, B_SZ, H_DIM, H_DIM, bhm, nullptr, nullptr, nullptr, nullptr);

    // 3) reset grid barrier
    cudaMemsetAsync(bar, 0, sizeof(unsigned int), 0);

    // 4) persistent LSTM scan (one launch, 128 internal steps)
    lstm_scan<<<128, 512, LP_SMEM>>>(h0, c0, Whh, xW, hs, bar);

    // 5) outputs = (s<k) ? hs : hs @ Whh2^T + bhh2 + hm
    gemm_k<2><<<dim3(H_DIM / 128, M / 128), 256>>>(
        hs, Whh2, ob, M, H_DIM, H_DIM, bhh2, nullptr, nullptr, hm, kp);

    // split outputs -> bf16 hi/lo
    split_a_k<<<(M * H_DIM / 4 + 255) / 256, 256>>>(ob, ah, al, M * H_DIM / 4);

    // 6) decoded = outputs @ decW^T + decb  — mma.sync bf16-split GEMM
    dec_gemm<<<dim3(V_PAD / 128, M / 128), 256>>>(ah, al, bh, bl, decb, out);

    (void)in_sizes; (void)n_in; (void)out_size;
}

// round 9
// speedup vs baseline: 1.4872x; 1.2832x over previous
#include <cuda_runtime.h>
#include <cuda_bf16.h>
#include <cuda_fp16.h>
#include <cstdint>

// Problem dims (fixed by the dataset)
#define S_LEN 128
#define B_SZ  16
#define H_DIM 1024
#define E_DIM 1024
#define G4    4096
#define V_SZ  50257
#define V_PAD 50304          // 393 * 128

// ---------------- scratch (device globals; no allocation allowed) ----------
__device__ float g_xW [S_LEN * G4 * B_SZ];       // transposed: [t][j][b]
__device__ float g_hs [S_LEN * B_SZ * H_DIM];
__device__ float g_outbuf[S_LEN * B_SZ * H_DIM];
__device__ float g_hm [B_SZ * H_DIM];
__device__ unsigned int g_bar;
__device__ __align__(256) __half g_a_hi[S_LEN * B_SZ * H_DIM];
__device__ __align__(256) __half g_a_lo[S_LEN * B_SZ * H_DIM];
__device__ __align__(256) __half g_b_h [(size_t)V_PAD * H_DIM];

// ---------------- f32x2 helpers --------------------------------------------
__device__ __forceinline__ unsigned long long dup2(float x) {
    unsigned long long r; asm("mov.b64 %0, {%1, %1};" : "=l"(r) : "f"(x)); return r;
}
__device__ __forceinline__ unsigned long long pk2(float lo, float hi) {
    unsigned long long r; asm("mov.b64 %0, {%1, %2};" : "=l"(r) : "f"(lo), "f"(hi)); return r;
}
__device__ __forceinline__ void fma2(unsigned long long& d,
                                     unsigned long long a, unsigned long long b) {
    asm("fma.rn.f32x2 %0, %1, %2, %0;" : "+l"(d) : "l"(a), "l"(b));
}
__device__ __forceinline__ float2 up2(unsigned long long v) {
    float2 f; asm("mov.b64 {%0, %1}, %2;" : "=f"(f.x), "=f"(f.y) : "l"(v)); return f;
}
__device__ __forceinline__ float sigm(float x) { return 1.0f / (1.0f + expf(-x)); }

__device__ __forceinline__ uint32_t smem_u32(const void* p) {
    uint32_t a;
    asm("{ .reg .u64 t; cvta.to.shared.u64 t, %1; cvt.u32.u64 %0, t; }"
        : "=r"(a) : "l"(p));
    return a;
}

// ---------------- mma.sync / ldmatrix / cp.async helpers (non-'a' PTX) ------
__device__ __forceinline__ void ldsm_x4(uint32_t* r, uint32_t addr) {
    asm volatile("ldmatrix.sync.aligned.m8n8.x4.shared.b16 {%0,%1,%2,%3}, [%4];"
                 : "=r"(r[0]), "=r"(r[1]), "=r"(r[2]), "=r"(r[3]) : "r"(addr));
}
__device__ __forceinline__ void mma16816(float* c, const uint32_t* a, const uint32_t* b) {
    asm volatile(
        "mma.sync.aligned.m16n8k16.row.col.f32.f16.f16.f32 "
        "{%0,%1,%2,%3}, {%4,%5,%6,%7}, {%8,%9}, {%0,%1,%2,%3};"
        : "+f"(c[0]), "+f"(c[1]), "+f"(c[2]), "+f"(c[3])
        : "r"(a[0]), "r"(a[1]), "r"(a[2]), "r"(a[3]), "r"(b[0]), "r"(b[1]));
}
__device__ __forceinline__ void cp16(uint32_t dst, const void* src) {
    asm volatile("cp.async.cg.shared.global [%0], [%1], 16;" :: "r"(dst), "l"(src));
}
#define CP_COMMIT() asm volatile("cp.async.commit_group;" ::: "memory")
#define CP_WAIT1()  asm volatile("cp.async.wait_group 1;" ::: "memory")
#define CP_WAIT0()  asm volatile("cp.async.wait_group 0;" ::: "memory")

// ---------------- generic tiled fp32 GEMM (steps 1,2,5) ---------------------
// MODE 0: C = acc + bias0[n]
// MODE 1: gather-A via gidx; writes TRANSPOSED xW layout [(m/16)*G4+n]*16+(m%16)
// MODE 2: trans/mask epilogue
template <int MODE>
__global__ void __launch_bounds__(256)
gemm_k(const float* __restrict__ A, const float* __restrict__ Bm,
       float* __restrict__ C, int M, int N, int K,
       const float* __restrict__ bias0, const float* __restrict__ bias1,
       const int* __restrict__ gidx, const float* __restrict__ hmv,
       const int* __restrict__ kptr)
{
    constexpr int BM = 128, BN = 128, BK = 16;
    __shared__ float As[BK][BM + 4];
    __shared__ float Bs[BK][BN + 4];

    const int tid = threadIdx.x;
    const int bm = blockIdx.y * BM;
    const int bn = blockIdx.x * BN;
    const int tx = tid & 15;
    const int ty = tid >> 4;
    const int lr = tid >> 2;
    const int lk = (tid & 3) * 4;

    unsigned long long acc[8][4];
#pragma unroll
    for (int i = 0; i < 8; i++)
#pragma unroll
        for (int j = 0; j < 4; j++) acc[i][j] = 0ull;

    const float* arow0;
    const float* arow1;
    {
        int m0 = bm + lr, m1 = bm + lr + 64;
        if (MODE == 1) {
            arow0 = (m0 < M) ? A + (size_t)gidx[m0] * K : nullptr;
            arow1 = (m1 < M) ? A + (size_t)gidx[m1] * K : nullptr;
        } else {
            arow0 = (m0 < M) ? A + (size_t)m0 * K : nullptr;
            arow1 = (m1 < M) ? A + (size_t)m1 * K : nullptr;
        }
    }
    const int n0 = bn + lr, n1 = bn + lr + 64;
    const float* brow0 = (n0 < N) ? Bm + (size_t)n0 * K : nullptr;
    const float* brow1 = (n1 < N) ? Bm + (size_t)n1 * K : nullptr;

    const float4 fz = make_float4(0.f, 0.f, 0.f, 0.f);

    for (int k0 = 0; k0 < K; k0 += BK) {
        float4 a0 = arow0 ? *(const float4*)(arow0 + k0 + lk) : fz;
        float4 a1 = arow1 ? *(const float4*)(arow1 + k0 + lk) : fz;
        float4 b0 = brow0 ? *(const float4*)(brow0 + k0 + lk) : fz;
        float4 b1 = brow1 ? *(const float4*)(brow1 + k0 + lk) : fz;

        __syncthreads();
        As[lk + 0][lr] = a0.x;  As[lk + 1][lr] = a0.y;
        As[lk + 2][lr] = a0.z;  As[lk + 3][lr] = a0.w;
        As[lk + 0][lr + 64] = a1.x;  As[lk + 1][lr + 64] = a1.y;
        As[lk + 2][lr + 64] = a1.z;  As[lk + 3][lr + 64] = a1.w;
        Bs[lk + 0][lr] = b0.x;  Bs[lk + 1][lr] = b0.y;
        Bs[lk + 2][lr] = b0.z;  Bs[lk + 3][lr] = b0.w;
        Bs[lk + 0][lr + 64] = b1.x;  Bs[lk + 1][lr + 64] = b1.y;
        Bs[lk + 2][lr + 64] = b1.z;  Bs[lk + 3][lr + 64] = b1.w;
        __syncthreads();

#pragma unroll
        for (int kk = 0; kk < BK; kk++) {
            float4 av0 = *(const float4*)&As[kk][ty * 8];
            float4 av1 = *(const float4*)&As[kk][ty * 8 + 4];
            float4 bv0 = *(const float4*)&Bs[kk][tx * 8];
            float4 bv1 = *(const float4*)&Bs[kk][tx * 8 + 4];
            unsigned long long a2[8] = {dup2(av0.x), dup2(av0.y), dup2(av0.z), dup2(av0.w),
                                        dup2(av1.x), dup2(av1.y), dup2(av1.z), dup2(av1.w)};
            unsigned long long b2[4] = {pk2(bv0.x, bv0.y), pk2(bv0.z, bv0.w),
                                        pk2(bv1.x, bv1.y), pk2(bv1.z, bv1.w)};
#pragma unroll
            for (int i = 0; i < 8; i++)
#pragma unroll
                for (int j = 0; j < 4; j++) fma2(acc[i][j], a2[i], b2[j]);
        }
    }

    const int kval = (MODE == 2) ? *kptr : 0;

#pragma unroll
    for (int i = 0; i < 8; i++) {
        int m = bm + ty * 8 + i;
        if (m >= M) continue;
        size_t crow = (size_t)m * N;
        int srow = m >> 4;
        int b    = m & 15;
        bool cp = (MODE == 2) && (srow < kval);
#pragma unroll
        for (int j = 0; j < 4; j++) {
            float2 v = up2(acc[i][j]);
            int n = bn + tx * 8 + 2 * j;
            float vals[2] = {v.x, v.y};
#pragma unroll
            for (int u = 0; u < 2; u++) {
                int nn = n + u;
                if (nn >= N) continue;
                float r;
                if (MODE == 0)      r = vals[u] + bias0[nn];
                else if (MODE == 1) r = vals[u] + bias0[nn] + bias1[nn];
                else                r = cp ? A[(size_t)m * K + nn]
                                           : vals[u] + bias0[nn] + hmv[b * H_DIM + nn];
                if (MODE == 1)
                    C[((size_t)srow * G4 + nn) * 16 + b] = r;   // transposed xW
                else
                    C[crow + nn] = r;
            }
        }
    }
}

// ---------------- persistent LSTM scan (R6 exact — measured best) ----------
#define HT_STRIDE 18
#define PF_STRIDE 514
#define LP_W_FLOATS (32 * 1024)
#define LP_HT_FLOATS (H_DIM * HT_STRIDE)          // 18432 >= pf 16448
#define LP_SG 512
#define LP_SMEM ((LP_W_FLOATS + LP_HT_FLOATS + LP_SG) * 4)

__global__ void __launch_bounds__(256, 1)
lstm_scan(const float* __restrict__ h0,
          const float* __restrict__ c0,
          const float* __restrict__ Whh,
          const float* __restrict__ xW,       // [t][j][b]
          float* __restrict__ hs,
          unsigned int* __restrict__ bar)
{
    extern __shared__ float sh[];
    float* Wsm = sh;                              // [32][1024]
    float* hT  = sh + LP_W_FLOATS;                // [1024][18]
    float* pf  = hT;                              // aliases hT: [32][514]
    float* sg  = sh + LP_W_FLOATS + LP_HT_FLOATS; // [32][16]

    const int tid = threadIdx.x;
    const int hb  = blockIdx.x * 8;
    const int kt  = tid & 31;
    const int jt  = tid >> 5;

    // ---- preload W slice into smem (once) ----
#pragma unroll 4
    for (int ll = 0; ll < 32; ll++) {
        int j = (ll >> 3) * H_DIM + hb + (ll & 7);
        ((float4*)(Wsm + ll * H_DIM))[tid] =
            ((const float4*)(Whh + (size_t)j * H_DIM))[tid];
    }

    // ---- cell state in registers (threads 0..127) ----
    float cloc = 0.f;
    const int a_hil = tid >> 4;
    const int a_b   = tid & 15;
    if (tid < 128) cloc = c0[a_b * H_DIM + hb + a_hil];

    const float* wrow[4];
#pragma unroll
    for (int l = 0; l < 4; l++) wrow[l] = Wsm + (jt * 4 + l) * H_DIM + kt;

    const float* hsrc = h0;

    for (int t = 0; t < S_LEN; t++) {
        // ---- stage h transposed (L2 reads, bypass L1) ----
        {
            const int b   = tid & 15;
            const int e4b = tid >> 4;
            const float4* hp = (const float4*)(hsrc + b * H_DIM);
#pragma unroll
            for (int i = 0; i < 16; i++) {
                int e4 = e4b + 16 * i;
                float4 v = __ldcg(hp + e4);
                int e0 = e4 * 4;
                hT[(e0 + 0) * HT_STRIDE + b] = v.x;
                hT[(e0 + 1) * HT_STRIDE + b] = v.y;
                hT[(e0 + 2) * HT_STRIDE + b] = v.z;
                hT[(e0 + 3) * HT_STRIDE + b] = v.w;
            }
        }
        __syncthreads();

        // ---- partial GEMM ----
        unsigned long long acc[4][8];
#pragma unroll
        for (int l = 0; l < 4; l++)
#pragma unroll
            for (int bp = 0; bp < 8; bp++) acc[l][bp] = 0ull;

#pragma unroll 4
        for (int i = 0; i < 32; i++) {
            const int k = kt + 32 * i;
            const unsigned long long* hrow =
                (const unsigned long long*)(hT + k * HT_STRIDE);
            unsigned long long hv[8];
#pragma unroll
            for (int bp = 0; bp < 8; bp++) hv[bp] = hrow[bp];
            float w0 = wrow[0][32 * i], w1 = wrow[1][32 * i];
            float w2 = wrow[2][32 * i], w3 = wrow[3][32 * i];
            unsigned long long wd0 = dup2(w0), wd1 = dup2(w1);
            unsigned long long wd2 = dup2(w2), wd3 = dup2(w3);
#pragma unroll
            for (int bp = 0; bp < 8; bp++) {
                fma2(acc[0][bp], wd0, hv[bp]);
                fma2(acc[1][bp], wd1, hv[bp]);
                fma2(acc[2][bp], wd2, hv[bp]);
                fma2(acc[3][bp], wd3, hv[bp]);
            }
        }
        __syncthreads();   // hT reads done before pf (alias) writes

        {
            unsigned long long* pr =
                (unsigned long long*)(pf + kt * PF_STRIDE + (jt * 4) * 16);
#pragma unroll
            for (int l = 0; l < 4; l++)
#pragma unroll
                for (int bp = 0; bp < 8; bp++) pr[l * 8 + bp] = acc[l][bp];
        }
        __syncthreads();

        // ---- reduce over kt, add xW bias term ----
        {
            const int l = tid >> 3;
            const int b = (tid & 7) * 2;
            float s0 = 0.f, s1 = 0.f;
            const float* p = pf + l * 16 + b;
#pragma unroll 8
            for (int ktt = 0; ktt < 32; ktt++) {
                float2 v = *(const float2*)(p + ktt * PF_STRIDE);
                s0 += v.x; s1 += v.y;
            }
            const int j = (l >> 3) * H_DIM + hb + (l & 7);
            const float2 xv = *(const float2*)(xW + ((size_t)t * G4 + j) * 16 + b);
            sg[l * 16 + b]     = s0 + xv.x;
            sg[l * 16 + b + 1] = s1 + xv.y;
        }
        __syncthreads();

        // ---- activation + state update + publish h ----
        if (tid < 128) {
            float gi = sg[(0  + a_hil) * 16 + a_b];
            float gf = sg[(8  + a_hil) * 16 + a_b];
            float gg = sg[(16 + a_hil) * 16 + a_b];
            float go = sg[(24 + a_hil) * 16 + a_b];
            float cn = sigm(gf) * cloc + sigm(gi) * tanhf(gg);
            cloc = cn;
            hs[(size_t)t * B_SZ * H_DIM + a_b * H_DIM + hb + a_hil] =
                sigm(go) * tanhf(cn);
        }
        __threadfence();
        __syncthreads();

        // ---- grid barrier ----
        if (tid == 0) {
            atomicAdd(bar, 1u);
            const unsigned int target = 128u * (unsigned)(t + 1);
            while (*((volatile unsigned int*)bar) < target) { }
        }
        __syncthreads();

        hsrc = hs + (size_t)t * B_SZ * H_DIM;
    }
}

// ---------------- fp16 split kernels ----------------------------------------
__global__ void __launch_bounds__(256)
split_a_k(const float* __restrict__ src, __half* __restrict__ hi,
          __half* __restrict__ lo, int n4)
{
    int i = blockIdx.x * blockDim.x + threadIdx.x;
    if (i >= n4) return;
    float4 v = ((const float4*)src)[i];
    float xs[4] = {v.x, v.y, v.z, v.w};
    __half h[4], l[4];
#pragma unroll
    for (int j = 0; j < 4; j++) {
        h[j] = __float2half_rn(xs[j]);
        l[j] = __float2half_rn(xs[j] - __half2float(h[j]));
    }
    ((__half2*)hi)[2 * i]     = __halves2half2(h[0], h[1]);
    ((__half2*)hi)[2 * i + 1] = __halves2half2(h[2], h[3]);
    ((__half2*)lo)[2 * i]     = __halves2half2(l[0], l[1]);
    ((__half2*)lo)[2 * i + 1] = __halves2half2(l[2], l[3]);
}

__global__ void __launch_bounds__(256)
split_b_k(const float* __restrict__ src, __half* __restrict__ out)
{
    int i = blockIdx.x * blockDim.x + threadIdx.x;   // over V_PAD*1024/4
    if (i >= V_PAD * (H_DIM / 4)) return;
    int row = i >> 8;
    float4 v = make_float4(0.f, 0.f, 0.f, 0.f);
    if (row < V_SZ) v = ((const float4*)src)[i];
    __half h[4] = { __float2half_rn(v.x), __float2half_rn(v.y),
                    __float2half_rn(v.z), __float2half_rn(v.w) };
    ((__half2*)out)[2 * i]     = __halves2half2(h[0], h[1]);
    ((__half2*)out)[2 * i + 1] = __halves2half2(h[2], h[3]);
}

// ---------------- mma.sync decoder GEMM (fp16, 2-pass) ----------------------
// C[2048, V] = (Ahi + Alo) * Bh^T + bias, all fp16 operands, fp32 accum.
// Error vs fp32 ref: dominated by A*Blo ~ 2^-12 relative (norm) ≈ 1.5e-4.
// CTA 128x128, BK=32, 8 warps (2M x 4N), cp.async 2-stage, 64 K-iterations.
#define DROW 40

__global__ void __launch_bounds__(256, 1)
dec_gemm(const __half* __restrict__ a_hi, const __half* __restrict__ a_lo,
         const __half* __restrict__ b_h,
         const float* __restrict__ bias, float* __restrict__ out)
{
    __shared__ __align__(16) __half As[2][128 * DROW];
    __shared__ __align__(16) __half Bs[2][128 * DROW];

    const int tid  = threadIdx.x;
    const int lane = tid & 31;
    const int warp = tid >> 5;
    const int warpM = warp >> 2;
    const int warpN = warp & 3;
    const int bm = blockIdx.y * 128;
    const int bn = blockIdx.x * 128;

    const uint32_t sA[2] = { smem_u32(As[0]), smem_u32(As[1]) };
    const uint32_t sB[2] = { smem_u32(Bs[0]), smem_u32(Bs[1]) };

    float acc[4][4][4];
#pragma unroll
    for (int i = 0; i < 4; i++)
#pragma unroll
        for (int j = 0; j < 4; j++)
#pragma unroll
            for (int r = 0; r < 4; r++) acc[i][j][r] = 0.f;

    const int r0c = tid >> 2, c0c = tid & 3;
    const int r1c = (tid + 256) >> 2, c1c = tid & 3;

    auto issue = [&](int it, int buf) {
        const int p  = it >> 5;                   // 0: Ahi, 1: Alo
        const int k0 = (it & 31) * 32;
        const __half* Ap = p ? a_lo : a_hi;
        cp16(sA[buf] + (r0c * DROW + c0c * 8) * 2,
             Ap + (size_t)(bm + r0c) * H_DIM + k0 + c0c * 8);
        cp16(sA[buf] + (r1c * DROW + c1c * 8) * 2,
             Ap + (size_t)(bm + r1c) * H_DIM + k0 + c1c * 8);
        cp16(sB[buf] + (r0c * DROW + c0c * 8) * 2,
             b_h + (size_t)(bn + r0c) * H_DIM + k0 + c0c * 8);
        cp16(sB[buf] + (r1c * DROW + c1c * 8) * 2,
             b_h + (size_t)(bn + r1c) * H_DIM + k0 + c1c * 8);
    };

    issue(0, 0);
    CP_COMMIT();

    for (int it = 0; it < 64; it++) {
        const int buf = it & 1;
        if (it + 1 < 64) { issue(it + 1, buf ^ 1); CP_COMMIT(); CP_WAIT1(); }
        else             { CP_WAIT0(); }
        __syncthreads();

#pragma unroll
        for (int ks = 0; ks < 2; ks++) {
            uint32_t af[4][4];
#pragma unroll
            for (int mf = 0; mf < 4; mf++) {
                int row = warpM * 64 + mf * 16 + (lane & 15);
                int ch  = ks * 2 + (lane >> 4);
                ldsm_x4(af[mf], sA[buf] + (row * DROW + ch * 8) * 2);
            }
            uint32_t br[2][4];
#pragma unroll
            for (int g = 0; g < 2; g++) {
                int row = warpN * 32 + g * 16 + ((lane >> 4) << 3) + (lane & 7);
                int ch  = ks * 2 + ((lane >> 3) & 1);
                ldsm_x4(br[g], sB[buf] + (row * DROW + ch * 8) * 2);
            }
#pragma unroll
            for (int mf = 0; mf < 4; mf++)
#pragma unroll
                for (int g = 0; g < 2; g++) {
                    mma16816(acc[mf][g * 2],     af[mf], &br[g][0]);
                    mma16816(acc[mf][g * 2 + 1], af[mf], &br[g][2]);
                }
        }
        __syncthreads();
    }

#pragma unroll
    for (int mf = 0; mf < 4; mf++) {
        int rowA = bm + warpM * 64 + mf * 16 + (lane >> 2);
        int rowB = rowA + 8;
#pragma unroll
        for (int nf = 0; nf < 4; nf++) {
            int col = bn + warpN * 32 + nf * 8 + (lane & 3) * 2;
            float b0 = (col     < V_SZ) ? bias[col]     : 0.f;
            float b1 = (col + 1 < V_SZ) ? bias[col + 1] : 0.f;
            if (col < V_SZ)     out[(size_t)rowA * V_SZ + col]     = acc[mf][nf][0] + b0;
            if (col + 1 < V_SZ) out[(size_t)rowA * V_SZ + col + 1] = acc[mf][nf][1] + b1;
            if (col < V_SZ)     out[(size_t)rowB * V_SZ + col]     = acc[mf][nf][2] + b0;
            if (col + 1 < V_SZ) out[(size_t)rowB * V_SZ + col + 1] = acc[mf][nf][3] + b1;
        }
    }
}

// ---------------- launcher --------------------------------------------------
extern "C" void kernel_launch(void* const* d_in, const int* in_sizes, int n_in,
                              void* d_out, int out_size)
{
    const int*   tokens = (const int*)  d_in[0];
    const float* h0     = (const float*)d_in[1];
    const float* c0     = (const float*)d_in[2];
    const float* emb    = (const float*)d_in[3];
    const float* Wih    = (const float*)d_in[4];
    const float* Whh    = (const float*)d_in[5];
    const float* bih    = (const float*)d_in[6];
    const float* bhh    = (const float*)d_in[7];
    const float* Whh2   = (const float*)d_in[8];
    const float* bhh2   = (const float*)d_in[9];
    const float* Whm    = (const float*)d_in[10];
    const float* bhm    = (const float*)d_in[11];
    const float* decW   = (const float*)d_in[12];
    const float* decb   = (const float*)d_in[13];
    const int*   kp     = (const int*)  d_in[14];
    float* out = (float*)d_out;

    void *p_xW, *p_hs, *p_outb, *p_hm, *p_bar, *p_ah, *p_al, *p_bh;
    cudaGetSymbolAddress(&p_xW,   g_xW);
    cudaGetSymbolAddress(&p_hs,   g_hs);
    cudaGetSymbolAddress(&p_outb, g_outbuf);
    cudaGetSymbolAddress(&p_hm,   g_hm);
    cudaGetSymbolAddress(&p_bar,  g_bar);
    cudaGetSymbolAddress(&p_ah,   g_a_hi);
    cudaGetSymbolAddress(&p_al,   g_a_lo);
    cudaGetSymbolAddress(&p_bh,   g_b_h);
    float* xW   = (float*)p_xW;
    float* hs   = (float*)p_hs;
    float* ob   = (float*)p_outb;
    float* hm   = (float*)p_hm;
    unsigned int* bar = (unsigned int*)p_bar;
    __half* ah = (__half*)p_ah;
    __half* al = (__half*)p_al;
    __half* bh = (__half*)p_bh;

    cudaFuncSetAttribute(lstm_scan, cudaFuncAttributeMaxDynamicSharedMemorySize,
                         LP_SMEM);

    const int M = S_LEN * B_SZ;   // 2048

    // 1) xW = gather(emb, tokens) @ Wih^T + bih + bhh  -> transposed [t][j][b]
    gemm_k<1><<<dim3(G4 / 128, M / 128), 256>>>(
        emb, Wih, xW, M, G4, E_DIM, bih, bhh, tokens, nullptr, nullptr);

    // convert decW -> fp16 (padded to V_PAD rows)
    split_b_k<<<(V_PAD * H_DIM / 4 + 255) / 256, 256>>>(decW, bh);

    // 2) hm = h0 @ Whm^T + bhm
    gemm_k<0><<<dim3(H_DIM / 128, 1), 256>>>(
        h0, Whm, hm, B_SZ, H_DIM, H_DIM, bhm, nullptr, nullptr, nullptr, nullptr);

    // 3) reset grid barrier
    cudaMemsetAsync(bar, 0, sizeof(unsigned int), 0);

    // 4) persistent LSTM scan (one launch, 128 internal steps)
    lstm_scan<<<128, 256, LP_SMEM>>>(h0, c0, Whh, xW, hs, bar);

    // 5) outputs = (s<k) ? hs : hs @ Whh2^T + bhh2 + hm
    gemm_k<2><<<dim3(H_DIM / 128, M / 128), 256>>>(
        hs, Whh2, ob, M, H_DIM, H_DIM, bhh2, nullptr, nullptr, hm, kp);

    // split outputs -> fp16 hi/lo
    split_a_k<<<(M * H_DIM / 4 + 255) / 256, 256>>>(ob, ah, al, M * H_DIM / 4);

    // 6) decoded = outputs @ decW^T + decb  — mma.sync fp16 2-pass GEMM
    dec_gemm<<<dim3(V_PAD / 128, M / 128), 256>>>(ah, al, bh, decb, out);

    (void)in_sizes; (void)n_in; (void)out_size;
}

// round 10
// speedup vs baseline: 1.9977x; 1.3433x over previous
#include <cuda_runtime.h>
#include <cuda_bf16.h>
#include <cuda_fp16.h>
#include <cstdint>

// Problem dims (fixed by the dataset)
#define S_LEN 128
#define B_SZ  16
#define H_DIM 1024
#define E_DIM 1024
#define G4    4096
#define V_SZ  50257
#define V_PAD 50304          // 393 * 128

// ---------------- scratch (device globals; no allocation allowed) ----------
__device__ float g_xW [S_LEN * G4 * B_SZ];       // transposed: [t][j][b]
__device__ float g_hs [S_LEN * B_SZ * H_DIM];
__device__ float g_outbuf[S_LEN * B_SZ * H_DIM];
__device__ float g_hm [B_SZ * H_DIM];
__device__ unsigned int g_bar;
__device__ __align__(256) __half g_a_h[S_LEN * B_SZ * H_DIM];
__device__ __align__(256) __half g_b_h[(size_t)V_PAD * H_DIM];

// ---------------- f32x2 helpers --------------------------------------------
__device__ __forceinline__ unsigned long long dup2(float x) {
    unsigned long long r; asm("mov.b64 %0, {%1, %1};" : "=l"(r) : "f"(x)); return r;
}
__device__ __forceinline__ unsigned long long pk2(float lo, float hi) {
    unsigned long long r; asm("mov.b64 %0, {%1, %2};" : "=l"(r) : "f"(lo), "f"(hi)); return r;
}
__device__ __forceinline__ void fma2(unsigned long long& d,
                                     unsigned long long a, unsigned long long b) {
    asm("fma.rn.f32x2 %0, %1, %2, %0;" : "+l"(d) : "l"(a), "l"(b));
}
__device__ __forceinline__ float2 up2(unsigned long long v) {
    float2 f; asm("mov.b64 {%0, %1}, %2;" : "=f"(f.x), "=f"(f.y) : "l"(v)); return f;
}
__device__ __forceinline__ float sigm(float x) { return 1.0f / (1.0f + expf(-x)); }

__device__ __forceinline__ uint32_t smem_u32(const void* p) {
    uint32_t a;
    asm("{ .reg .u64 t; cvta.to.shared.u64 t, %1; cvt.u32.u64 %0, t; }"
        : "=r"(a) : "l"(p));
    return a;
}

// ---------------- mma.sync / ldmatrix / cp.async helpers (non-'a' PTX) ------
__device__ __forceinline__ void ldsm_x4(uint32_t* r, uint32_t addr) {
    asm volatile("ldmatrix.sync.aligned.m8n8.x4.shared.b16 {%0,%1,%2,%3}, [%4];"
                 : "=r"(r[0]), "=r"(r[1]), "=r"(r[2]), "=r"(r[3]) : "r"(addr));
}
__device__ __forceinline__ void mma16816(float* c, const uint32_t* a, const uint32_t* b) {
    asm volatile(
        "mma.sync.aligned.m16n8k16.row.col.f32.f16.f16.f32 "
        "{%0,%1,%2,%3}, {%4,%5,%6,%7}, {%8,%9}, {%0,%1,%2,%3};"
        : "+f"(c[0]), "+f"(c[1]), "+f"(c[2]), "+f"(c[3])
        : "r"(a[0]), "r"(a[1]), "r"(a[2]), "r"(a[3]), "r"(b[0]), "r"(b[1]));
}
__device__ __forceinline__ void cp16(uint32_t dst, const void* src) {
    asm volatile("cp.async.cg.shared.global [%0], [%1], 16;" :: "r"(dst), "l"(src));
}
#define CP_COMMIT() asm volatile("cp.async.commit_group;" ::: "memory")
#define CP_WAIT1()  asm volatile("cp.async.wait_group 1;" ::: "memory")
#define CP_WAIT0()  asm volatile("cp.async.wait_group 0;" ::: "memory")

// ---------------- generic tiled fp32 GEMM (steps 1,2,5) ---------------------
// MODE 0: C = acc + bias0[n]
// MODE 1: gather-A via gidx; writes TRANSPOSED xW layout [(m/16)*G4+n]*16+(m%16)
// MODE 2: trans/mask epilogue
template <int MODE>
__global__ void __launch_bounds__(256)
gemm_k(const float* __restrict__ A, const float* __restrict__ Bm,
       float* __restrict__ C, int M, int N, int K,
       const float* __restrict__ bias0, const float* __restrict__ bias1,
       const int* __restrict__ gidx, const float* __restrict__ hmv,
       const int* __restrict__ kptr)
{
    constexpr int BM = 128, BN = 128, BK = 16;
    __shared__ float As[BK][BM + 4];
    __shared__ float Bs[BK][BN + 4];

    const int tid = threadIdx.x;
    const int bm = blockIdx.y * BM;
    const int bn = blockIdx.x * BN;
    const int tx = tid & 15;
    const int ty = tid >> 4;
    const int lr = tid >> 2;
    const int lk = (tid & 3) * 4;

    unsigned long long acc[8][4];
#pragma unroll
    for (int i = 0; i < 8; i++)
#pragma unroll
        for (int j = 0; j < 4; j++) acc[i][j] = 0ull;

    const float* arow0;
    const float* arow1;
    {
        int m0 = bm + lr, m1 = bm + lr + 64;
        if (MODE == 1) {
            arow0 = (m0 < M) ? A + (size_t)gidx[m0] * K : nullptr;
            arow1 = (m1 < M) ? A + (size_t)gidx[m1] * K : nullptr;
        } else {
            arow0 = (m0 < M) ? A + (size_t)m0 * K : nullptr;
            arow1 = (m1 < M) ? A + (size_t)m1 * K : nullptr;
        }
    }
    const int n0 = bn + lr, n1 = bn + lr + 64;
    const float* brow0 = (n0 < N) ? Bm + (size_t)n0 * K : nullptr;
    const float* brow1 = (n1 < N) ? Bm + (size_t)n1 * K : nullptr;

    const float4 fz = make_float4(0.f, 0.f, 0.f, 0.f);

    for (int k0 = 0; k0 < K; k0 += BK) {
        float4 a0 = arow0 ? *(const float4*)(arow0 + k0 + lk) : fz;
        float4 a1 = arow1 ? *(const float4*)(arow1 + k0 + lk) : fz;
        float4 b0 = brow0 ? *(const float4*)(brow0 + k0 + lk) : fz;
        float4 b1 = brow1 ? *(const float4*)(brow1 + k0 + lk) : fz;

        __syncthreads();
        As[lk + 0][lr] = a0.x;  As[lk + 1][lr] = a0.y;
        As[lk + 2][lr] = a0.z;  As[lk + 3][lr] = a0.w;
        As[lk + 0][lr + 64] = a1.x;  As[lk + 1][lr + 64] = a1.y;
        As[lk + 2][lr + 64] = a1.z;  As[lk + 3][lr + 64] = a1.w;
        Bs[lk + 0][lr] = b0.x;  Bs[lk + 1][lr] = b0.y;
        Bs[lk + 2][lr] = b0.z;  Bs[lk + 3][lr] = b0.w;
        Bs[lk + 0][lr + 64] = b1.x;  Bs[lk + 1][lr + 64] = b1.y;
        Bs[lk + 2][lr + 64] = b1.z;  Bs[lk + 3][lr + 64] = b1.w;
        __syncthreads();

#pragma unroll
        for (int kk = 0; kk < BK; kk++) {
            float4 av0 = *(const float4*)&As[kk][ty * 8];
            float4 av1 = *(const float4*)&As[kk][ty * 8 + 4];
            float4 bv0 = *(const float4*)&Bs[kk][tx * 8];
            float4 bv1 = *(const float4*)&Bs[kk][tx * 8 + 4];
            unsigned long long a2[8] = {dup2(av0.x), dup2(av0.y), dup2(av0.z), dup2(av0.w),
                                        dup2(av1.x), dup2(av1.y), dup2(av1.z), dup2(av1.w)};
            unsigned long long b2[4] = {pk2(bv0.x, bv0.y), pk2(bv0.z, bv0.w),
                                        pk2(bv1.x, bv1.y), pk2(bv1.z, bv1.w)};
#pragma unroll
            for (int i = 0; i < 8; i++)
#pragma unroll
                for (int j = 0; j < 4; j++) fma2(acc[i][j], a2[i], b2[j]);
        }
    }

    const int kval = (MODE == 2) ? *kptr : 0;

#pragma unroll
    for (int i = 0; i < 8; i++) {
        int m = bm + ty * 8 + i;
        if (m >= M) continue;
        size_t crow = (size_t)m * N;
        int srow = m >> 4;
        int b    = m & 15;
        bool cp = (MODE == 2) && (srow < kval);
#pragma unroll
        for (int j = 0; j < 4; j++) {
            float2 v = up2(acc[i][j]);
            int n = bn + tx * 8 + 2 * j;
            float vals[2] = {v.x, v.y};
#pragma unroll
            for (int u = 0; u < 2; u++) {
                int nn = n + u;
                if (nn >= N) continue;
                float r;
                if (MODE == 0)      r = vals[u] + bias0[nn];
                else if (MODE == 1) r = vals[u] + bias0[nn] + bias1[nn];
                else                r = cp ? A[(size_t)m * K + nn]
                                           : vals[u] + bias0[nn] + hmv[b * H_DIM + nn];
                if (MODE == 1)
                    C[((size_t)srow * G4 + nn) * 16 + b] = r;   // transposed xW
                else
                    C[crow + nn] = r;
            }
        }
    }
}

// ---------------- persistent LSTM scan (R6 exact — measured best) ----------
#define HT_STRIDE 18
#define PF_STRIDE 514
#define LP_W_FLOATS (32 * 1024)
#define LP_HT_FLOATS (H_DIM * HT_STRIDE)          // 18432 >= pf 16448
#define LP_SG 512
#define LP_SMEM ((LP_W_FLOATS + LP_HT_FLOATS + LP_SG) * 4)

__global__ void __launch_bounds__(256, 1)
lstm_scan(const float* __restrict__ h0,
          const float* __restrict__ c0,
          const float* __restrict__ Whh,
          const float* __restrict__ xW,       // [t][j][b]
          float* __restrict__ hs,
          unsigned int* __restrict__ bar)
{
    extern __shared__ float sh[];
    float* Wsm = sh;                              // [32][1024]
    float* hT  = sh + LP_W_FLOATS;                // [1024][18]
    float* pf  = hT;                              // aliases hT: [32][514]
    float* sg  = sh + LP_W_FLOATS + LP_HT_FLOATS; // [32][16]

    const int tid = threadIdx.x;
    const int hb  = blockIdx.x * 8;
    const int kt  = tid & 31;
    const int jt  = tid >> 5;

    // ---- preload W slice into smem (once) ----
#pragma unroll 4
    for (int ll = 0; ll < 32; ll++) {
        int j = (ll >> 3) * H_DIM + hb + (ll & 7);
        ((float4*)(Wsm + ll * H_DIM))[tid] =
            ((const float4*)(Whh + (size_t)j * H_DIM))[tid];
    }

    // ---- cell state in registers (threads 0..127) ----
    float cloc = 0.f;
    const int a_hil = tid >> 4;
    const int a_b   = tid & 15;
    if (tid < 128) cloc = c0[a_b * H_DIM + hb + a_hil];

    const float* wrow[4];
#pragma unroll
    for (int l = 0; l < 4; l++) wrow[l] = Wsm + (jt * 4 + l) * H_DIM + kt;

    const float* hsrc = h0;

    for (int t = 0; t < S_LEN; t++) {
        // ---- stage h transposed (L2 reads, bypass L1) ----
        {
            const int b   = tid & 15;
            const int e4b = tid >> 4;
            const float4* hp = (const float4*)(hsrc + b * H_DIM);
#pragma unroll
            for (int i = 0; i < 16; i++) {
                int e4 = e4b + 16 * i;
                float4 v = __ldcg(hp + e4);
                int e0 = e4 * 4;
                hT[(e0 + 0) * HT_STRIDE + b] = v.x;
                hT[(e0 + 1) * HT_STRIDE + b] = v.y;
                hT[(e0 + 2) * HT_STRIDE + b] = v.z;
                hT[(e0 + 3) * HT_STRIDE + b] = v.w;
            }
        }
        __syncthreads();

        // ---- partial GEMM ----
        unsigned long long acc[4][8];
#pragma unroll
        for (int l = 0; l < 4; l++)
#pragma unroll
            for (int bp = 0; bp < 8; bp++) acc[l][bp] = 0ull;

#pragma unroll 4
        for (int i = 0; i < 32; i++) {
            const int k = kt + 32 * i;
            const unsigned long long* hrow =
                (const unsigned long long*)(hT + k * HT_STRIDE);
            unsigned long long hv[8];
#pragma unroll
            for (int bp = 0; bp < 8; bp++) hv[bp] = hrow[bp];
            float w0 = wrow[0][32 * i], w1 = wrow[1][32 * i];
            float w2 = wrow[2][32 * i], w3 = wrow[3][32 * i];
            unsigned long long wd0 = dup2(w0), wd1 = dup2(w1);
            unsigned long long wd2 = dup2(w2), wd3 = dup2(w3);
#pragma unroll
            for (int bp = 0; bp < 8; bp++) {
                fma2(acc[0][bp], wd0, hv[bp]);
                fma2(acc[1][bp], wd1, hv[bp]);
                fma2(acc[2][bp], wd2, hv[bp]);
                fma2(acc[3][bp], wd3, hv[bp]);
            }
        }
        __syncthreads();   // hT reads done before pf (alias) writes

        {
            unsigned long long* pr =
                (unsigned long long*)(pf + kt * PF_STRIDE + (jt * 4) * 16);
#pragma unroll
            for (int l = 0; l < 4; l++)
#pragma unroll
                for (int bp = 0; bp < 8; bp++) pr[l * 8 + bp] = acc[l][bp];
        }
        __syncthreads();

        // ---- reduce over kt, add xW bias term ----
        {
            const int l = tid >> 3;
            const int b = (tid & 7) * 2;
            float s0 = 0.f, s1 = 0.f;
            const float* p = pf + l * 16 + b;
#pragma unroll 8
            for (int ktt = 0; ktt < 32; ktt++) {
                float2 v = *(const float2*)(p + ktt * PF_STRIDE);
                s0 += v.x; s1 += v.y;
            }
            const int j = (l >> 3) * H_DIM + hb + (l & 7);
            const float2 xv = *(const float2*)(xW + ((size_t)t * G4 + j) * 16 + b);
            sg[l * 16 + b]     = s0 + xv.x;
            sg[l * 16 + b + 1] = s1 + xv.y;
        }
        __syncthreads();

        // ---- activation + state update + publish h ----
        if (tid < 128) {
            float gi = sg[(0  + a_hil) * 16 + a_b];
            float gf = sg[(8  + a_hil) * 16 + a_b];
            float gg = sg[(16 + a_hil) * 16 + a_b];
            float go = sg[(24 + a_hil) * 16 + a_b];
            float cn = sigm(gf) * cloc + sigm(gi) * tanhf(gg);
            cloc = cn;
            hs[(size_t)t * B_SZ * H_DIM + a_b * H_DIM + hb + a_hil] =
                sigm(go) * tanhf(cn);
        }
        __threadfence();
        __syncthreads();

        // ---- grid barrier ----
        if (tid == 0) {
            atomicAdd(bar, 1u);
            const unsigned int target = 128u * (unsigned)(t + 1);
            while (*((volatile unsigned int*)bar) < target) { }
        }
        __syncthreads();

        hsrc = hs + (size_t)t * B_SZ * H_DIM;
    }
}

// ---------------- fp16 convert kernels ---------------------------------------
__global__ void __launch_bounds__(256)
conv_a_k(const float* __restrict__ src, __half* __restrict__ dst, int n4)
{
    int i = blockIdx.x * blockDim.x + threadIdx.x;
    if (i >= n4) return;
    float4 v = ((const float4*)src)[i];
    __half h[4] = { __float2half_rn(v.x), __float2half_rn(v.y),
                    __float2half_rn(v.z), __float2half_rn(v.w) };
    ((__half2*)dst)[2 * i]     = __halves2half2(h[0], h[1]);
    ((__half2*)dst)[2 * i + 1] = __halves2half2(h[2], h[3]);
}

__global__ void __launch_bounds__(256)
conv_b_k(const float* __restrict__ src, __half* __restrict__ out)
{
    int i = blockIdx.x * blockDim.x + threadIdx.x;   // over V_PAD*1024/4
    if (i >= V_PAD * (H_DIM / 4)) return;
    int row = i >> 8;
    float4 v = make_float4(0.f, 0.f, 0.f, 0.f);
    if (row < V_SZ) v = ((const float4*)src)[i];
    __half h[4] = { __float2half_rn(v.x), __float2half_rn(v.y),
                    __float2half_rn(v.z), __float2half_rn(v.w) };
    ((__half2*)out)[2 * i]     = __halves2half2(h[0], h[1]);
    ((__half2*)out)[2 * i + 1] = __halves2half2(h[2], h[3]);
}

// ---------------- mma.sync decoder GEMM (fp16, single pass) -----------------
// C[2048, V] = Ah * Bh^T + bias (fp16 operands, fp32 accum).
// Error model (calibrated R5/R9): ~1.7x RMS of rounding terms; A-err and B-err
// independent -> predicted rel_err ~ sqrt(2) * 2.08e-4 ~ 2.9e-4 << 1e-3.
// CTA 128x128, BK=32, 8 warps (2M x 4N), cp.async 2-stage, 32 K-iterations.
#define DROW 40

__global__ void __launch_bounds__(256, 1)
dec_gemm(const __half* __restrict__ a_h, const __half* __restrict__ b_h,
         const float* __restrict__ bias, float* __restrict__ out)
{
    __shared__ __align__(16) __half As[2][128 * DROW];
    __shared__ __align__(16) __half Bs[2][128 * DROW];

    const int tid  = threadIdx.x;
    const int lane = tid & 31;
    const int warp = tid >> 5;
    const int warpM = warp >> 2;
    const int warpN = warp & 3;
    const int bm = blockIdx.y * 128;
    const int bn = blockIdx.x * 128;

    const uint32_t sA[2] = { smem_u32(As[0]), smem_u32(As[1]) };
    const uint32_t sB[2] = { smem_u32(Bs[0]), smem_u32(Bs[1]) };

    float acc[4][4][4];
#pragma unroll
    for (int i = 0; i < 4; i++)
#pragma unroll
        for (int j = 0; j < 4; j++)
#pragma unroll
            for (int r = 0; r < 4; r++) acc[i][j][r] = 0.f;

    const int r0c = tid >> 2, c0c = tid & 3;
    const int r1c = (tid + 256) >> 2, c1c = tid & 3;

    auto issue = [&](int it, int buf) {
        const int k0 = it * 32;
        cp16(sA[buf] + (r0c * DROW + c0c * 8) * 2,
             a_h + (size_t)(bm + r0c) * H_DIM + k0 + c0c * 8);
        cp16(sA[buf] + (r1c * DROW + c1c * 8) * 2,
             a_h + (size_t)(bm + r1c) * H_DIM + k0 + c1c * 8);
        cp16(sB[buf] + (r0c * DROW + c0c * 8) * 2,
             b_h + (size_t)(bn + r0c) * H_DIM + k0 + c0c * 8);
        cp16(sB[buf] + (r1c * DROW + c1c * 8) * 2,
             b_h + (size_t)(bn + r1c) * H_DIM + k0 + c1c * 8);
    };

    issue(0, 0);
    CP_COMMIT();

    for (int it = 0; it < 32; it++) {
        const int buf = it & 1;
        if (it + 1 < 32) { issue(it + 1, buf ^ 1); CP_COMMIT(); CP_WAIT1(); }
        else             { CP_WAIT0(); }
        __syncthreads();

#pragma unroll
        for (int ks = 0; ks < 2; ks++) {
            uint32_t af[4][4];
#pragma unroll
            for (int mf = 0; mf < 4; mf++) {
                int row = warpM * 64 + mf * 16 + (lane & 15);
                int ch  = ks * 2 + (lane >> 4);
                ldsm_x4(af[mf], sA[buf] + (row * DROW + ch * 8) * 2);
            }
            uint32_t br[2][4];
#pragma unroll
            for (int g = 0; g < 2; g++) {
                int row = warpN * 32 + g * 16 + ((lane >> 4) << 3) + (lane & 7);
                int ch  = ks * 2 + ((lane >> 3) & 1);
                ldsm_x4(br[g], sB[buf] + (row * DROW + ch * 8) * 2);
            }
#pragma unroll
            for (int mf = 0; mf < 4; mf++)
#pragma unroll
                for (int g = 0; g < 2; g++) {
                    mma16816(acc[mf][g * 2],     af[mf], &br[g][0]);
                    mma16816(acc[mf][g * 2 + 1], af[mf], &br[g][2]);
                }
        }
        __syncthreads();
    }

#pragma unroll
    for (int mf = 0; mf < 4; mf++) {
        int rowA = bm + warpM * 64 + mf * 16 + (lane >> 2);
        int rowB = rowA + 8;
#pragma unroll
        for (int nf = 0; nf < 4; nf++) {
            int col = bn + warpN * 32 + nf * 8 + (lane & 3) * 2;
            float b0 = (col     < V_SZ) ? bias[col]     : 0.f;
            float b1 = (col + 1 < V_SZ) ? bias[col + 1] : 0.f;
            if (col < V_SZ)     out[(size_t)rowA * V_SZ + col]     = acc[mf][nf][0] + b0;
            if (col + 1 < V_SZ) out[(size_t)rowA * V_SZ + col + 1] = acc[mf][nf][1] + b1;
            if (col < V_SZ)     out[(size_t)rowB * V_SZ + col]     = acc[mf][nf][2] + b0;
            if (col + 1 < V_SZ) out[(size_t)rowB * V_SZ + col + 1] = acc[mf][nf][3] + b1;
        }
    }
}

// ---------------- launcher --------------------------------------------------
extern "C" void kernel_launch(void* const* d_in, const int* in_sizes, int n_in,
                              void* d_out, int out_size)
{
    const int*   tokens = (const int*)  d_in[0];
    const float* h0     = (const float*)d_in[1];
    const float* c0     = (const float*)d_in[2];
    const float* emb    = (const float*)d_in[3];
    const float* Wih    = (const float*)d_in[4];
    const float* Whh    = (const float*)d_in[5];
    const float* bih    = (const float*)d_in[6];
    const float* bhh    = (const float*)d_in[7];
    const float* Whh2   = (const float*)d_in[8];
    const float* bhh2   = (const float*)d_in[9];
    const float* Whm    = (const float*)d_in[10];
    const float* bhm    = (const float*)d_in[11];
    const float* decW   = (const float*)d_in[12];
    const float* decb   = (const float*)d_in[13];
    const int*   kp     = (const int*)  d_in[14];
    float* out = (float*)d_out;

    void *p_xW, *p_hs, *p_outb, *p_hm, *p_bar, *p_ah, *p_bh;
    cudaGetSymbolAddress(&p_xW,   g_xW);
    cudaGetSymbolAddress(&p_hs,   g_hs);
    cudaGetSymbolAddress(&p_outb, g_outbuf);
    cudaGetSymbolAddress(&p_hm,   g_hm);
    cudaGetSymbolAddress(&p_bar,  g_bar);
    cudaGetSymbolAddress(&p_ah,   g_a_h);
    cudaGetSymbolAddress(&p_bh,   g_b_h);
    float* xW   = (float*)p_xW;
    float* hs   = (float*)p_hs;
    float* ob   = (float*)p_outb;
    float* hm   = (float*)p_hm;
    unsigned int* bar = (unsigned int*)p_bar;
    __half* ah = (__half*)p_ah;
    __half* bh = (__half*)p_bh;

    cudaFuncSetAttribute(lstm_scan, cudaFuncAttributeMaxDynamicSharedMemorySize,
                         LP_SMEM);

    const int M = S_LEN * B_SZ;   // 2048

    // 1) xW = gather(emb, tokens) @ Wih^T + bih + bhh  -> transposed [t][j][b]
    gemm_k<1><<<dim3(G4 / 128, M / 128), 256>>>(
        emb, Wih, xW, M, G4, E_DIM, bih, bhh, tokens, nullptr, nullptr);

    // convert decW -> fp16 (padded to V_PAD rows)
    conv_b_k<<<(V_PAD * H_DIM / 4 + 255) / 256, 256>>>(decW, bh);

    // 2) hm = h0 @ Whm^T + bhm
    gemm_k<0><<<dim3(H_DIM / 128, 1), 256>>>(
        h0, Whm, hm, B_SZ, H_DIM, H_DIM, bhm, nullptr, nullptr, nullptr, nullptr);

    // 3) reset grid barrier
    cudaMemsetAsync(bar, 0, sizeof(unsigned int), 0);

    // 4) persistent LSTM scan (one launch, 128 internal steps)
    lstm_scan<<<128, 256, LP_SMEM>>>(h0, c0, Whh, xW, hs, bar);

    // 5) outputs = (s<k) ? hs : hs @ Whh2^T + bhh2 + hm
    gemm_k<2><<<dim3(H_DIM / 128, M / 128), 256>>>(
        hs, Whh2, ob, M, H_DIM, H_DIM, bhh2, nullptr, nullptr, hm, kp);

    // convert outputs -> fp16
    conv_a_k<<<(M * H_DIM / 4 + 255) / 256, 256>>>(ob, ah, M * H_DIM / 4);

    // 6) decoded = outputs @ decW^T + decb  — mma.sync fp16 single-pass GEMM
    dec_gemm<<<dim3(V_PAD / 128, M / 128), 256>>>(ah, bh, decb, out);

    (void)in_sizes; (void)n_in; (void)out_size;
}

// round 11
// speedup vs baseline: 2.1170x; 1.0597x over previous
#include <cuda_runtime.h>
#include <cuda_bf16.h>
#include <cuda_fp16.h>
#include <cstdint>

// Problem dims (fixed by the dataset)
#define S_LEN 128
#define B_SZ  16
#define H_DIM 1024
#define E_DIM 1024
#define G4    4096
#define V_SZ  50257
#define V_PAD 50304          // 393 * 128

// ---------------- scratch (device globals; no allocation allowed) ----------
__device__ float g_xW [S_LEN * B_SZ * G4];       // plain row-major [m][4H]
__device__ float g_hs [S_LEN * B_SZ * H_DIM];
__device__ float g_outbuf[S_LEN * B_SZ * H_DIM];
__device__ float g_hm [B_SZ * H_DIM];
__device__ unsigned int g_bar;
__device__ __align__(256) __half g_a_h[S_LEN * B_SZ * H_DIM];
__device__ __align__(256) __half g_b_h[(size_t)V_PAD * H_DIM];
__device__ __align__(256) __half g_emb_h[(size_t)V_SZ * E_DIM];
__device__ __align__(256) __half g_wih_hi[G4 * E_DIM];
__device__ __align__(256) __half g_wih_lo[G4 * E_DIM];

// ---------------- f32x2 helpers --------------------------------------------
__device__ __forceinline__ unsigned long long dup2(float x) {
    unsigned long long r; asm("mov.b64 %0, {%1, %1};" : "=l"(r) : "f"(x)); return r;
}
__device__ __forceinline__ unsigned long long pk2(float lo, float hi) {
    unsigned long long r; asm("mov.b64 %0, {%1, %2};" : "=l"(r) : "f"(lo), "f"(hi)); return r;
}
__device__ __forceinline__ void fma2(unsigned long long& d,
                                     unsigned long long a, unsigned long long b) {
    asm("fma.rn.f32x2 %0, %1, %2, %0;" : "+l"(d) : "l"(a), "l"(b));
}
__device__ __forceinline__ float2 up2(unsigned long long v) {
    float2 f; asm("mov.b64 {%0, %1}, %2;" : "=f"(f.x), "=f"(f.y) : "l"(v)); return f;
}
__device__ __forceinline__ float sigm(float x) { return 1.0f / (1.0f + expf(-x)); }

__device__ __forceinline__ uint32_t smem_u32(const void* p) {
    uint32_t a;
    asm("{ .reg .u64 t; cvta.to.shared.u64 t, %1; cvt.u32.u64 %0, t; }"
        : "=r"(a) : "l"(p));
    return a;
}

// ---------------- mma.sync / ldmatrix / cp.async helpers (non-'a' PTX) ------
__device__ __forceinline__ void ldsm_x4(uint32_t* r, uint32_t addr) {
    asm volatile("ldmatrix.sync.aligned.m8n8.x4.shared.b16 {%0,%1,%2,%3}, [%4];"
                 : "=r"(r[0]), "=r"(r[1]), "=r"(r[2]), "=r"(r[3]) : "r"(addr));
}
__device__ __forceinline__ void mma16816(float* c, const uint32_t* a, const uint32_t* b) {
    asm volatile(
        "mma.sync.aligned.m16n8k16.row.col.f32.f16.f16.f32 "
        "{%0,%1,%2,%3}, {%4,%5,%6,%7}, {%8,%9}, {%0,%1,%2,%3};"
        : "+f"(c[0]), "+f"(c[1]), "+f"(c[2]), "+f"(c[3])
        : "r"(a[0]), "r"(a[1]), "r"(a[2]), "r"(a[3]), "r"(b[0]), "r"(b[1]));
}
__device__ __forceinline__ void cp16(uint32_t dst, const void* src) {
    asm volatile("cp.async.cg.shared.global [%0], [%1], 16;" :: "r"(dst), "l"(src));
}
#define CP_COMMIT() asm volatile("cp.async.commit_group;" ::: "memory")
#define CP_WAIT1()  asm volatile("cp.async.wait_group 1;" ::: "memory")
#define CP_WAIT0()  asm volatile("cp.async.wait_group 0;" ::: "memory")

// ---------------- generic tiled fp32 GEMM (steps 2,5) -----------------------
// MODE 0: C = acc + bias0[n]
// MODE 2: trans/mask epilogue
template <int MODE>
__global__ void __launch_bounds__(256)
gemm_k(const float* __restrict__ A, const float* __restrict__ Bm,
       float* __restrict__ C, int M, int N, int K,
       const float* __restrict__ bias0,
       const float* __restrict__ hmv, const int* __restrict__ kptr)
{
    constexpr int BM = 128, BN = 128, BK = 16;
    __shared__ float As[BK][BM + 4];
    __shared__ float Bs[BK][BN + 4];

    const int tid = threadIdx.x;
    const int bm = blockIdx.y * BM;
    const int bn = blockIdx.x * BN;
    const int tx = tid & 15;
    const int ty = tid >> 4;
    const int lr = tid >> 2;
    const int lk = (tid & 3) * 4;

    unsigned long long acc[8][4];
#pragma unroll
    for (int i = 0; i < 8; i++)
#pragma unroll
        for (int j = 0; j < 4; j++) acc[i][j] = 0ull;

    const int m0 = bm + lr, m1 = bm + lr + 64;
    const float* arow0 = (m0 < M) ? A + (size_t)m0 * K : nullptr;
    const float* arow1 = (m1 < M) ? A + (size_t)m1 * K : nullptr;
    const int n0 = bn + lr, n1 = bn + lr + 64;
    const float* brow0 = (n0 < N) ? Bm + (size_t)n0 * K : nullptr;
    const float* brow1 = (n1 < N) ? Bm + (size_t)n1 * K : nullptr;

    const float4 fz = make_float4(0.f, 0.f, 0.f, 0.f);

    for (int k0 = 0; k0 < K; k0 += BK) {
        float4 a0 = arow0 ? *(const float4*)(arow0 + k0 + lk) : fz;
        float4 a1 = arow1 ? *(const float4*)(arow1 + k0 + lk) : fz;
        float4 b0 = brow0 ? *(const float4*)(brow0 + k0 + lk) : fz;
        float4 b1 = brow1 ? *(const float4*)(brow1 + k0 + lk) : fz;

        __syncthreads();
        As[lk + 0][lr] = a0.x;  As[lk + 1][lr] = a0.y;
        As[lk + 2][lr] = a0.z;  As[lk + 3][lr] = a0.w;
        As[lk + 0][lr + 64] = a1.x;  As[lk + 1][lr + 64] = a1.y;
        As[lk + 2][lr + 64] = a1.z;  As[lk + 3][lr + 64] = a1.w;
        Bs[lk + 0][lr] = b0.x;  Bs[lk + 1][lr] = b0.y;
        Bs[lk + 2][lr] = b0.z;  Bs[lk + 3][lr] = b0.w;
        Bs[lk + 0][lr + 64] = b1.x;  Bs[lk + 1][lr + 64] = b1.y;
        Bs[lk + 2][lr + 64] = b1.z;  Bs[lk + 3][lr + 64] = b1.w;
        __syncthreads();

#pragma unroll
        for (int kk = 0; kk < BK; kk++) {
            float4 av0 = *(const float4*)&As[kk][ty * 8];
            float4 av1 = *(const float4*)&As[kk][ty * 8 + 4];
            float4 bv0 = *(const float4*)&Bs[kk][tx * 8];
            float4 bv1 = *(const float4*)&Bs[kk][tx * 8 + 4];
            unsigned long long a2[8] = {dup2(av0.x), dup2(av0.y), dup2(av0.z), dup2(av0.w),
                                        dup2(av1.x), dup2(av1.y), dup2(av1.z), dup2(av1.w)};
            unsigned long long b2[4] = {pk2(bv0.x, bv0.y), pk2(bv0.z, bv0.w),
                                        pk2(bv1.x, bv1.y), pk2(bv1.z, bv1.w)};
#pragma unroll
            for (int i = 0; i < 8; i++)
#pragma unroll
                for (int j = 0; j < 4; j++) fma2(acc[i][j], a2[i], b2[j]);
        }
    }

    const int kval = (MODE == 2) ? *kptr : 0;

#pragma unroll
    for (int i = 0; i < 8; i++) {
        int m = bm + ty * 8 + i;
        if (m >= M) continue;
        size_t crow = (size_t)m * N;
        int srow = m >> 4;
        int b    = m & 15;
        bool cp = (MODE == 2) && (srow < kval);
#pragma unroll
        for (int j = 0; j < 4; j++) {
            float2 v = up2(acc[i][j]);
            int n = bn + tx * 8 + 2 * j;
            float vals[2] = {v.x, v.y};
#pragma unroll
            for (int u = 0; u < 2; u++) {
                int nn = n + u;
                if (nn >= N) continue;
                float r;
                if (MODE == 0) r = vals[u] + bias0[nn];
                else           r = cp ? A[(size_t)m * K + nn]
                                      : vals[u] + bias0[nn] + hmv[b * H_DIM + nn];
                C[crow + nn] = r;
            }
        }
    }
}

// ---------------- persistent LSTM scan (R6 + hv/w software pipeline) --------
#define HT_STRIDE 18
#define PF_STRIDE 514
#define LP_W_FLOATS (32 * 1024)
#define LP_HT_FLOATS (H_DIM * HT_STRIDE)          // 18432 >= pf 16448
#define LP_SG 512
#define LP_SMEM ((LP_W_FLOATS + LP_HT_FLOATS + LP_SG) * 4)

__global__ void __launch_bounds__(256, 1)
lstm_scan(const float* __restrict__ h0,
          const float* __restrict__ c0,
          const float* __restrict__ Whh,
          const float* __restrict__ xW,       // [m][4H] row-major
          float* __restrict__ hs,
          unsigned int* __restrict__ bar)
{
    extern __shared__ float sh[];
    float* Wsm = sh;                              // [32][1024]
    float* hT  = sh + LP_W_FLOATS;                // [1024][18]
    float* pf  = hT;                              // aliases hT: [32][514]
    float* sg  = sh + LP_W_FLOATS + LP_HT_FLOATS; // [32][16]

    const int tid = threadIdx.x;
    const int hb  = blockIdx.x * 8;
    const int kt  = tid & 31;
    const int jt  = tid >> 5;

    // ---- preload W slice into smem (once) ----
#pragma unroll 4
    for (int ll = 0; ll < 32; ll++) {
        int j = (ll >> 3) * H_DIM + hb + (ll & 7);
        ((float4*)(Wsm + ll * H_DIM))[tid] =
            ((const float4*)(Whh + (size_t)j * H_DIM))[tid];
    }

    // ---- cell state in registers (threads 0..127) ----
    float cloc = 0.f;
    const int a_hil = tid >> 4;
    const int a_b   = tid & 15;
    if (tid < 128) cloc = c0[a_b * H_DIM + hb + a_hil];

    const float* wrow[4];
#pragma unroll
    for (int l = 0; l < 4; l++) wrow[l] = Wsm + (jt * 4 + l) * H_DIM + kt;

    const float* hsrc = h0;

    for (int t = 0; t < S_LEN; t++) {
        // ---- stage h transposed (L2 reads, bypass L1) ----
        {
            const int b   = tid & 15;
            const int e4b = tid >> 4;
            const float4* hp = (const float4*)(hsrc + b * H_DIM);
#pragma unroll
            for (int i = 0; i < 16; i++) {
                int e4 = e4b + 16 * i;
                float4 v = __ldcg(hp + e4);
                int e0 = e4 * 4;
                hT[(e0 + 0) * HT_STRIDE + b] = v.x;
                hT[(e0 + 1) * HT_STRIDE + b] = v.y;
                hT[(e0 + 2) * HT_STRIDE + b] = v.z;
                hT[(e0 + 3) * HT_STRIDE + b] = v.w;
            }
        }
        __syncthreads();

        // ---- partial GEMM, software-pipelined (double-buffered hv/w) ----
        unsigned long long acc[4][8];
#pragma unroll
        for (int l = 0; l < 4; l++)
#pragma unroll
            for (int bp = 0; bp < 8; bp++) acc[l][bp] = 0ull;

        unsigned long long hv[2][8];
        float wv[2][4];
        {
            const unsigned long long* hrow =
                (const unsigned long long*)(hT + kt * HT_STRIDE);
#pragma unroll
            for (int bp = 0; bp < 8; bp++) hv[0][bp] = hrow[bp];
#pragma unroll
            for (int l = 0; l < 4; l++) wv[0][l] = wrow[l][0];
        }

#pragma unroll 2
        for (int i = 0; i < 32; i++) {
            const int cur = i & 1, nxt = cur ^ 1;
            if (i < 31) {
                const int k2 = kt + 32 * (i + 1);
                const unsigned long long* hrow2 =
                    (const unsigned long long*)(hT + k2 * HT_STRIDE);
#pragma unroll
                for (int bp = 0; bp < 8; bp++) hv[nxt][bp] = hrow2[bp];
#pragma unroll
                for (int l = 0; l < 4; l++) wv[nxt][l] = wrow[l][32 * (i + 1)];
            }
            unsigned long long wd0 = dup2(wv[cur][0]), wd1 = dup2(wv[cur][1]);
            unsigned long long wd2 = dup2(wv[cur][2]), wd3 = dup2(wv[cur][3]);
#pragma unroll
            for (int bp = 0; bp < 8; bp++) {
                fma2(acc[0][bp], wd0, hv[cur][bp]);
                fma2(acc[1][bp], wd1, hv[cur][bp]);
                fma2(acc[2][bp], wd2, hv[cur][bp]);
                fma2(acc[3][bp], wd3, hv[cur][bp]);
            }
        }
        __syncthreads();   // hT reads done before pf (alias) writes

        {
            unsigned long long* pr =
                (unsigned long long*)(pf + kt * PF_STRIDE + (jt * 4) * 16);
#pragma unroll
            for (int l = 0; l < 4; l++)
#pragma unroll
                for (int bp = 0; bp < 8; bp++) pr[l * 8 + bp] = acc[l][bp];
        }
        __syncthreads();

        // ---- reduce over kt, add xW bias term ----
        {
            const int l = tid >> 3;
            const int b = (tid & 7) * 2;
            float s0 = 0.f, s1 = 0.f;
            const float* p = pf + l * 16 + b;
#pragma unroll 8
            for (int ktt = 0; ktt < 32; ktt++) {
                float2 v = *(const float2*)(p + ktt * PF_STRIDE);
                s0 += v.x; s1 += v.y;
            }
            const int j = (l >> 3) * H_DIM + hb + (l & 7);
            const size_t mrow = (size_t)t * 16;
            sg[l * 16 + b]     = s0 + __ldg(xW + (mrow + b) * G4 + j);
            sg[l * 16 + b + 1] = s1 + __ldg(xW + (mrow + b + 1) * G4 + j);
        }
        __syncthreads();

        // ---- activation + state update + publish h ----
        if (tid < 128) {
            float gi = sg[(0  + a_hil) * 16 + a_b];
            float gf = sg[(8  + a_hil) * 16 + a_b];
            float gg = sg[(16 + a_hil) * 16 + a_b];
            float go = sg[(24 + a_hil) * 16 + a_b];
            float cn = sigm(gf) * cloc + sigm(gi) * tanhf(gg);
            cloc = cn;
            hs[(size_t)t * B_SZ * H_DIM + a_b * H_DIM + hb + a_hil] =
                sigm(go) * tanhf(cn);
        }
        __threadfence();
        __syncthreads();

        // ---- grid barrier ----
        if (tid == 0) {
            atomicAdd(bar, 1u);
            const unsigned int target = 128u * (unsigned)(t + 1);
            while (*((volatile unsigned int*)bar) < target) { }
        }
        __syncthreads();

        hsrc = hs + (size_t)t * B_SZ * H_DIM;
    }
}

// ---------------- fp16 convert / split kernels -------------------------------
__global__ void __launch_bounds__(256)
conv_a_k(const float* __restrict__ src, __half* __restrict__ dst, int n4)
{
    int i = blockIdx.x * blockDim.x + threadIdx.x;
    if (i >= n4) return;
    float4 v = ((const float4*)src)[i];
    __half h[4] = { __float2half_rn(v.x), __float2half_rn(v.y),
                    __float2half_rn(v.z), __float2half_rn(v.w) };
    ((__half2*)dst)[2 * i]     = __halves2half2(h[0], h[1]);
    ((__half2*)dst)[2 * i + 1] = __halves2half2(h[2], h[3]);
}

__global__ void __launch_bounds__(256)
conv_b_k(const float* __restrict__ src, __half* __restrict__ out)
{
    int i = blockIdx.x * blockDim.x + threadIdx.x;   // over V_PAD*1024/4
    if (i >= V_PAD * (H_DIM / 4)) return;
    int row = i >> 8;
    float4 v = make_float4(0.f, 0.f, 0.f, 0.f);
    if (row < V_SZ) v = ((const float4*)src)[i];
    __half h[4] = { __float2half_rn(v.x), __float2half_rn(v.y),
                    __float2half_rn(v.z), __float2half_rn(v.w) };
    ((__half2*)out)[2 * i]     = __halves2half2(h[0], h[1]);
    ((__half2*)out)[2 * i + 1] = __halves2half2(h[2], h[3]);
}

__global__ void __launch_bounds__(256)
split_w_k(const float* __restrict__ src, __half* __restrict__ hi,
          __half* __restrict__ lo, int n4)
{
    int i = blockIdx.x * blockDim.x + threadIdx.x;
    if (i >= n4) return;
    float4 v = ((const float4*)src)[i];
    float xs[4] = {v.x, v.y, v.z, v.w};
    __half h[4], l[4];
#pragma unroll
    for (int j = 0; j < 4; j++) {
        h[j] = __float2half_rn(xs[j]);
        l[j] = __float2half_rn(xs[j] - __half2float(h[j]));
    }
    ((__half2*)hi)[2 * i]     = __halves2half2(h[0], h[1]);
    ((__half2*)hi)[2 * i + 1] = __halves2half2(h[2], h[3]);
    ((__half2*)lo)[2 * i]     = __halves2half2(l[0], l[1]);
    ((__half2*)lo)[2 * i + 1] = __halves2half2(l[2], l[3]);
}

// ---------------- xW GEMM: gathered fp16 mma, 2-pass -------------------------
// xW[2048, 4096] = emb_h[tokens] @ (Wih_hi + Wih_lo)^T + bih + bhh
// Error: emb-rounding only (~2.8e-4 on xW), attenuated through LSTM recurrence.
#define DROW 40

__global__ void __launch_bounds__(256, 1)
xw_gemm(const __half* __restrict__ emb_h, const int* __restrict__ tokens,
        const __half* __restrict__ w_hi, const __half* __restrict__ w_lo,
        const float* __restrict__ bih, const float* __restrict__ bhh,
        float* __restrict__ out)
{
    __shared__ __align__(16) __half As[2][128 * DROW];
    __shared__ __align__(16) __half Bs[2][128 * DROW];

    const int tid  = threadIdx.x;
    const int lane = tid & 31;
    const int warp = tid >> 5;
    const int warpM = warp >> 2;
    const int warpN = warp & 3;
    const int bm = blockIdx.y * 128;
    const int bn = blockIdx.x * 128;

    const uint32_t sA[2] = { smem_u32(As[0]), smem_u32(As[1]) };
    const uint32_t sB[2] = { smem_u32(Bs[0]), smem_u32(Bs[1]) };

    float acc[4][4][4];
#pragma unroll
    for (int i = 0; i < 4; i++)
#pragma unroll
        for (int j = 0; j < 4; j++)
#pragma unroll
            for (int r = 0; r < 4; r++) acc[i][j][r] = 0.f;

    const int r0c = tid >> 2, c0c = tid & 3;
    const int r1c = r0c + 64;
    // gather row pointers (fixed across iterations)
    const __half* a0p = emb_h + (size_t)tokens[bm + r0c] * E_DIM;
    const __half* a1p = emb_h + (size_t)tokens[bm + r1c] * E_DIM;

    auto issue = [&](int it, int buf) {
        const int p  = it >> 5;                  // 0: w_hi, 1: w_lo
        const int k0 = (it & 31) * 32;
        const __half* Bp = p ? w_lo : w_hi;
        cp16(sA[buf] + (r0c * DROW + c0c * 8) * 2, a0p + k0 + c0c * 8);
        cp16(sA[buf] + (r1c * DROW + c0c * 8) * 2, a1p + k0 + c0c * 8);
        cp16(sB[buf] + (r0c * DROW + c0c * 8) * 2,
             Bp + (size_t)(bn + r0c) * E_DIM + k0 + c0c * 8);
        cp16(sB[buf] + (r1c * DROW + c0c * 8) * 2,
             Bp + (size_t)(bn + r1c) * E_DIM + k0 + c0c * 8);
    };

    issue(0, 0);
    CP_COMMIT();

    for (int it = 0; it < 64; it++) {
        const int buf = it & 1;
        if (it + 1 < 64) { issue(it + 1, buf ^ 1); CP_COMMIT(); CP_WAIT1(); }
        else             { CP_WAIT0(); }
        __syncthreads();

#pragma unroll
        for (int ks = 0; ks < 2; ks++) {
            uint32_t af[4][4];
#pragma unroll
            for (int mf = 0; mf < 4; mf++) {
                int row = warpM * 64 + mf * 16 + (lane & 15);
                int ch  = ks * 2 + (lane >> 4);
                ldsm_x4(af[mf], sA[buf] + (row * DROW + ch * 8) * 2);
            }
            uint32_t br[2][4];
#pragma unroll
            for (int g = 0; g < 2; g++) {
                int row = warpN * 32 + g * 16 + ((lane >> 4) << 3) + (lane & 7);
                int ch  = ks * 2 + ((lane >> 3) & 1);
                ldsm_x4(br[g], sB[buf] + (row * DROW + ch * 8) * 2);
            }
#pragma unroll
            for (int mf = 0; mf < 4; mf++)
#pragma unroll
                for (int g = 0; g < 2; g++) {
                    mma16816(acc[mf][g * 2],     af[mf], &br[g][0]);
                    mma16816(acc[mf][g * 2 + 1], af[mf], &br[g][2]);
                }
        }
        __syncthreads();
    }

#pragma unroll
    for (int mf = 0; mf < 4; mf++) {
        int rowA = bm + warpM * 64 + mf * 16 + (lane >> 2);
        int rowB = rowA + 8;
#pragma unroll
        for (int nf = 0; nf < 4; nf++) {
            int col = bn + warpN * 32 + nf * 8 + (lane & 3) * 2;
            float b0 = bih[col]     + bhh[col];
            float b1 = bih[col + 1] + bhh[col + 1];
            out[(size_t)rowA * G4 + col]     = acc[mf][nf][0] + b0;
            out[(size_t)rowA * G4 + col + 1] = acc[mf][nf][1] + b1;
            out[(size_t)rowB * G4 + col]     = acc[mf][nf][2] + b0;
            out[(size_t)rowB * G4 + col + 1] = acc[mf][nf][3] + b1;
        }
    }
}

// ---------------- mma.sync decoder GEMM (fp16, single pass — R10 exact) -----
__global__ void __launch_bounds__(256, 1)
dec_gemm(const __half* __restrict__ a_h, const __half* __restrict__ b_h,
         const float* __restrict__ bias, float* __restrict__ out)
{
    __shared__ __align__(16) __half As[2][128 * DROW];
    __shared__ __align__(16) __half Bs[2][128 * DROW];

    const int tid  = threadIdx.x;
    const int lane = tid & 31;
    const int warp = tid >> 5;
    const int warpM = warp >> 2;
    const int warpN = warp & 3;
    const int bm = blockIdx.y * 128;
    const int bn = blockIdx.x * 128;

    const uint32_t sA[2] = { smem_u32(As[0]), smem_u32(As[1]) };
    const uint32_t sB[2] = { smem_u32(Bs[0]), smem_u32(Bs[1]) };

    float acc[4][4][4];
#pragma unroll
    for (int i = 0; i < 4; i++)
#pragma unroll
        for (int j = 0; j < 4; j++)
#pragma unroll
            for (int r = 0; r < 4; r++) acc[i][j][r] = 0.f;

    const int r0c = tid >> 2, c0c = tid & 3;
    const int r1c = (tid + 256) >> 2, c1c = tid & 3;

    auto issue = [&](int it, int buf) {
        const int k0 = it * 32;
        cp16(sA[buf] + (r0c * DROW + c0c * 8) * 2,
             a_h + (size_t)(bm + r0c) * H_DIM + k0 + c0c * 8);
        cp16(sA[buf] + (r1c * DROW + c1c * 8) * 2,
             a_h + (size_t)(bm + r1c) * H_DIM + k0 + c1c * 8);
        cp16(sB[buf] + (r0c * DROW + c0c * 8) * 2,
             b_h + (size_t)(bn + r0c) * H_DIM + k0 + c0c * 8);
        cp16(sB[buf] + (r1c * DROW + c1c * 8) * 2,
             b_h + (size_t)(bn + r1c) * H_DIM + k0 + c1c * 8);
    };

    issue(0, 0);
    CP_COMMIT();

    for (int it = 0; it < 32; it++) {
        const int buf = it & 1;
        if (it + 1 < 32) { issue(it + 1, buf ^ 1); CP_COMMIT(); CP_WAIT1(); }
        else             { CP_WAIT0(); }
        __syncthreads();

#pragma unroll
        for (int ks = 0; ks < 2; ks++) {
            uint32_t af[4][4];
#pragma unroll
            for (int mf = 0; mf < 4; mf++) {
                int row = warpM * 64 + mf * 16 + (lane & 15);
                int ch  = ks * 2 + (lane >> 4);
                ldsm_x4(af[mf], sA[buf] + (row * DROW + ch * 8) * 2);
            }
            uint32_t br[2][4];
#pragma unroll
            for (int g = 0; g < 2; g++) {
                int row = warpN * 32 + g * 16 + ((lane >> 4) << 3) + (lane & 7);
                int ch  = ks * 2 + ((lane >> 3) & 1);
                ldsm_x4(br[g], sB[buf] + (row * DROW + ch * 8) * 2);
            }
#pragma unroll
            for (int mf = 0; mf < 4; mf++)
#pragma unroll
                for (int g = 0; g < 2; g++) {
                    mma16816(acc[mf][g * 2],     af[mf], &br[g][0]);
                    mma16816(acc[mf][g * 2 + 1], af[mf], &br[g][2]);
                }
        }
        __syncthreads();
    }

#pragma unroll
    for (int mf = 0; mf < 4; mf++) {
        int rowA = bm + warpM * 64 + mf * 16 + (lane >> 2);
        int rowB = rowA + 8;
#pragma unroll
        for (int nf = 0; nf < 4; nf++) {
            int col = bn + warpN * 32 + nf * 8 + (lane & 3) * 2;
            float b0 = (col     < V_SZ) ? bias[col]     : 0.f;
            float b1 = (col + 1 < V_SZ) ? bias[col + 1] : 0.f;
            if (col < V_SZ)     out[(size_t)rowA * V_SZ + col]     = acc[mf][nf][0] + b0;
            if (col + 1 < V_SZ) out[(size_t)rowA * V_SZ + col + 1] = acc[mf][nf][1] + b1;
            if (col < V_SZ)     out[(size_t)rowB * V_SZ + col]     = acc[mf][nf][2] + b0;
            if (col + 1 < V_SZ) out[(size_t)rowB * V_SZ + col + 1] = acc[mf][nf][3] + b1;
        }
    }
}

// ---------------- launcher --------------------------------------------------
extern "C" void kernel_launch(void* const* d_in, const int* in_sizes, int n_in,
                              void* d_out, int out_size)
{
    const int*   tokens = (const int*)  d_in[0];
    const float* h0     = (const float*)d_in[1];
    const float* c0     = (const float*)d_in[2];
    const float* emb    = (const float*)d_in[3];
    const float* Wih    = (const float*)d_in[4];
    const float* Whh    = (const float*)d_in[5];
    const float* bih    = (const float*)d_in[6];
    const float* bhh    = (const float*)d_in[7];
    const float* Whh2   = (const float*)d_in[8];
    const float* bhh2   = (const float*)d_in[9];
    const float* Whm    = (const float*)d_in[10];
    const float* bhm    = (const float*)d_in[11];
    const float* decW   = (const float*)d_in[12];
    const float* decb   = (const float*)d_in[13];
    const int*   kp     = (const int*)  d_in[14];
    float* out = (float*)d_out;

    void *p_xW, *p_hs, *p_outb, *p_hm, *p_bar, *p_ah, *p_bh, *p_eh, *p_wh, *p_wl;
    cudaGetSymbolAddress(&p_xW,   g_xW);
    cudaGetSymbolAddress(&p_hs,   g_hs);
    cudaGetSymbolAddress(&p_outb, g_outbuf);
    cudaGetSymbolAddress(&p_hm,   g_hm);
    cudaGetSymbolAddress(&p_bar,  g_bar);
    cudaGetSymbolAddress(&p_ah,   g_a_h);
    cudaGetSymbolAddress(&p_bh,   g_b_h);
    cudaGetSymbolAddress(&p_eh,   g_emb_h);
    cudaGetSymbolAddress(&p_wh,   g_wih_hi);
    cudaGetSymbolAddress(&p_wl,   g_wih_lo);
    float* xW   = (float*)p_xW;
    float* hs   = (float*)p_hs;
    float* ob   = (float*)p_outb;
    float* hm   = (float*)p_hm;
    unsigned int* bar = (unsigned int*)p_bar;
    __half* ah = (__half*)p_ah;
    __half* bh = (__half*)p_bh;
    __half* eh = (__half*)p_eh;
    __half* wh = (__half*)p_wh;
    __half* wl = (__half*)p_wl;

    cudaFuncSetAttribute(lstm_scan, cudaFuncAttributeMaxDynamicSharedMemorySize,
                         LP_SMEM);

    const int M = S_LEN * B_SZ;   // 2048

    // 0) conversions: emb -> fp16; Wih -> fp16 hi/lo; decW -> fp16
    conv_a_k<<<((int)((size_t)V_SZ * E_DIM / 4) + 255) / 256, 256>>>(
        emb, eh, (int)((size_t)V_SZ * E_DIM / 4));
    split_w_k<<<(G4 * E_DIM / 4 + 255) / 256, 256>>>(Wih, wh, wl, G4 * E_DIM / 4);
    conv_b_k<<<(V_PAD * H_DIM / 4 + 255) / 256, 256>>>(decW, bh);

    // 1) xW = gather(emb_h, tokens) @ (Wih_hi+Wih_lo)^T + bih + bhh  (mma)
    xw_gemm<<<dim3(G4 / 128, M / 128), 256>>>(eh, tokens, wh, wl, bih, bhh, xW);

    // 2) hm = h0 @ Whm^T + bhm
    gemm_k<0><<<dim3(H_DIM / 128, 1), 256>>>(
        h0, Whm, hm, B_SZ, H_DIM, H_DIM, bhm, nullptr, nullptr);

    // 3) reset grid barrier
    cudaMemsetAsync(bar, 0, sizeof(unsigned int), 0);

    // 4) persistent LSTM scan (one launch, 128 internal steps)
    lstm_scan<<<128, 256, LP_SMEM>>>(h0, c0, Whh, xW, hs, bar);

    // 5) outputs = (s<k) ? hs : hs @ Whh2^T + bhh2 + hm
    gemm_k<2><<<dim3(H_DIM / 128, M / 128), 256>>>(
        hs, Whh2, ob, M, H_DIM, H_DIM, bhh2, hm, kp);

    // convert outputs -> fp16
    conv_a_k<<<(M * H_DIM / 4 + 255) / 256, 256>>>(ob, ah, M * H_DIM / 4);

    // 6) decoded = outputs @ decW^T + decb  — mma.sync fp16 single-pass GEMM
    dec_gemm<<<dim3(V_PAD / 128, M / 128), 256>>>(ah, bh, decb, out);

    (void)in_sizes; (void)n_in; (void)out_size;
}

// round 12
// speedup vs baseline: 2.4476x; 1.1562x over previous
#include <cuda_runtime.h>
#include <cuda_bf16.h>
#include <cuda_fp16.h>
#include <cstdint>

// Problem dims (fixed by the dataset)
#define S_LEN 128
#define B_SZ  16
#define H_DIM 1024
#define E_DIM 1024
#define G4    4096
#define V_SZ  50257
#define V_PAD 50304          // 393 * 128

// ---------------- scratch (device globals; no allocation allowed) ----------
__device__ float g_xW [S_LEN * B_SZ * G4];       // plain row-major [m][4H]
__device__ float g_hs [S_LEN * B_SZ * H_DIM];
__device__ float g_outbuf[S_LEN * B_SZ * H_DIM];
__device__ float g_hm [B_SZ * H_DIM];
__device__ unsigned int g_bar;
__device__ __align__(256) __half g_a_h[S_LEN * B_SZ * H_DIM];  // reused: gathered emb, then outputs
__device__ __align__(256) __half g_b_h[(size_t)V_PAD * H_DIM];
__device__ __align__(256) __half g_wih_hi[G4 * E_DIM];
__device__ __align__(256) __half g_wih_lo[G4 * E_DIM];

// ---------------- f32x2 helpers --------------------------------------------
__device__ __forceinline__ unsigned long long dup2(float x) {
    unsigned long long r; asm("mov.b64 %0, {%1, %1};" : "=l"(r) : "f"(x)); return r;
}
__device__ __forceinline__ unsigned long long pk2(float lo, float hi) {
    unsigned long long r; asm("mov.b64 %0, {%1, %2};" : "=l"(r) : "f"(lo), "f"(hi)); return r;
}
__device__ __forceinline__ void fma2(unsigned long long& d,
                                     unsigned long long a, unsigned long long b) {
    asm("fma.rn.f32x2 %0, %1, %2, %0;" : "+l"(d) : "l"(a), "l"(b));
}
__device__ __forceinline__ float2 up2(unsigned long long v) {
    float2 f; asm("mov.b64 {%0, %1}, %2;" : "=f"(f.x), "=f"(f.y) : "l"(v)); return f;
}
__device__ __forceinline__ float sigm(float x) { return 1.0f / (1.0f + expf(-x)); }

__device__ __forceinline__ uint32_t smem_u32(const void* p) {
    uint32_t a;
    asm("{ .reg .u64 t; cvta.to.shared.u64 t, %1; cvt.u32.u64 %0, t; }"
        : "=r"(a) : "l"(p));
    return a;
}

// ---------------- mma.sync / ldmatrix / cp.async helpers (non-'a' PTX) ------
__device__ __forceinline__ void ldsm_x4(uint32_t* r, uint32_t addr) {
    asm volatile("ldmatrix.sync.aligned.m8n8.x4.shared.b16 {%0,%1,%2,%3}, [%4];"
                 : "=r"(r[0]), "=r"(r[1]), "=r"(r[2]), "=r"(r[3]) : "r"(addr));
}
__device__ __forceinline__ void mma16816(float* c, const uint32_t* a, const uint32_t* b) {
    asm volatile(
        "mma.sync.aligned.m16n8k16.row.col.f32.f16.f16.f32 "
        "{%0,%1,%2,%3}, {%4,%5,%6,%7}, {%8,%9}, {%0,%1,%2,%3};"
        : "+f"(c[0]), "+f"(c[1]), "+f"(c[2]), "+f"(c[3])
        : "r"(a[0]), "r"(a[1]), "r"(a[2]), "r"(a[3]), "r"(b[0]), "r"(b[1]));
}
__device__ __forceinline__ void cp16(uint32_t dst, const void* src) {
    asm volatile("cp.async.cg.shared.global [%0], [%1], 16;" :: "r"(dst), "l"(src));
}
#define CP_COMMIT() asm volatile("cp.async.commit_group;" ::: "memory")
#define CP_WAIT1()  asm volatile("cp.async.wait_group 1;" ::: "memory")
#define CP_WAIT0()  asm volatile("cp.async.wait_group 0;" ::: "memory")

// ---------------- generic tiled fp32 GEMM (steps 2,5) -----------------------
// MODE 0: C = acc + bias0[n]
// MODE 2: trans/mask epilogue
template <int MODE>
__global__ void __launch_bounds__(256)
gemm_k(const float* __restrict__ A, const float* __restrict__ Bm,
       float* __restrict__ C, int M, int N, int K,
       const float* __restrict__ bias0,
       const float* __restrict__ hmv, const int* __restrict__ kptr)
{
    constexpr int BM = 128, BN = 128, BK = 16;
    __shared__ float As[BK][BM + 4];
    __shared__ float Bs[BK][BN + 4];

    const int tid = threadIdx.x;
    const int bm = blockIdx.y * BM;
    const int bn = blockIdx.x * BN;
    const int tx = tid & 15;
    const int ty = tid >> 4;
    const int lr = tid >> 2;
    const int lk = (tid & 3) * 4;

    unsigned long long acc[8][4];
#pragma unroll
    for (int i = 0; i < 8; i++)
#pragma unroll
        for (int j = 0; j < 4; j++) acc[i][j] = 0ull;

    const int m0 = bm + lr, m1 = bm + lr + 64;
    const float* arow0 = (m0 < M) ? A + (size_t)m0 * K : nullptr;
    const float* arow1 = (m1 < M) ? A + (size_t)m1 * K : nullptr;
    const int n0 = bn + lr, n1 = bn + lr + 64;
    const float* brow0 = (n0 < N) ? Bm + (size_t)n0 * K : nullptr;
    const float* brow1 = (n1 < N) ? Bm + (size_t)n1 * K : nullptr;

    const float4 fz = make_float4(0.f, 0.f, 0.f, 0.f);

    for (int k0 = 0; k0 < K; k0 += BK) {
        float4 a0 = arow0 ? *(const float4*)(arow0 + k0 + lk) : fz;
        float4 a1 = arow1 ? *(const float4*)(arow1 + k0 + lk) : fz;
        float4 b0 = brow0 ? *(const float4*)(brow0 + k0 + lk) : fz;
        float4 b1 = brow1 ? *(const float4*)(brow1 + k0 + lk) : fz;

        __syncthreads();
        As[lk + 0][lr] = a0.x;  As[lk + 1][lr] = a0.y;
        As[lk + 2][lr] = a0.z;  As[lk + 3][lr] = a0.w;
        As[lk + 0][lr + 64] = a1.x;  As[lk + 1][lr + 64] = a1.y;
        As[lk + 2][lr + 64] = a1.z;  As[lk + 3][lr + 64] = a1.w;
        Bs[lk + 0][lr] = b0.x;  Bs[lk + 1][lr] = b0.y;
        Bs[lk + 2][lr] = b0.z;  Bs[lk + 3][lr] = b0.w;
        Bs[lk + 0][lr + 64] = b1.x;  Bs[lk + 1][lr + 64] = b1.y;
        Bs[lk + 2][lr + 64] = b1.z;  Bs[lk + 3][lr + 64] = b1.w;
        __syncthreads();

#pragma unroll
        for (int kk = 0; kk < BK; kk++) {
            float4 av0 = *(const float4*)&As[kk][ty * 8];
            float4 av1 = *(const float4*)&As[kk][ty * 8 + 4];
            float4 bv0 = *(const float4*)&Bs[kk][tx * 8];
            float4 bv1 = *(const float4*)&Bs[kk][tx * 8 + 4];
            unsigned long long a2[8] = {dup2(av0.x), dup2(av0.y), dup2(av0.z), dup2(av0.w),
                                        dup2(av1.x), dup2(av1.y), dup2(av1.z), dup2(av1.w)};
            unsigned long long b2[4] = {pk2(bv0.x, bv0.y), pk2(bv0.z, bv0.w),
                                        pk2(bv1.x, bv1.y), pk2(bv1.z, bv1.w)};
#pragma unroll
            for (int i = 0; i < 8; i++)
#pragma unroll
                for (int j = 0; j < 4; j++) fma2(acc[i][j], a2[i], b2[j]);
        }
    }

    const int kval = (MODE == 2) ? *kptr : 0;

#pragma unroll
    for (int i = 0; i < 8; i++) {
        int m = bm + ty * 8 + i;
        if (m >= M) continue;
        size_t crow = (size_t)m * N;
        int srow = m >> 4;
        int b    = m & 15;
        bool cp = (MODE == 2) && (srow < kval);
#pragma unroll
        for (int j = 0; j < 4; j++) {
            float2 v = up2(acc[i][j]);
            int n = bn + tx * 8 + 2 * j;
            float vals[2] = {v.x, v.y};
#pragma unroll
            for (int u = 0; u < 2; u++) {
                int nn = n + u;
                if (nn >= N) continue;
                float r;
                if (MODE == 0) r = vals[u] + bias0[nn];
                else           r = cp ? A[(size_t)m * K + nn]
                                      : vals[u] + bias0[nn] + hmv[b * H_DIM + nn];
                C[crow + nn] = r;
            }
        }
    }
}

// ---------------- persistent LSTM scan (R11 version, unchanged) -------------
#define HT_STRIDE 18
#define PF_STRIDE 514
#define LP_W_FLOATS (32 * 1024)
#define LP_HT_FLOATS (H_DIM * HT_STRIDE)          // 18432 >= pf 16448
#define LP_SG 512
#define LP_SMEM ((LP_W_FLOATS + LP_HT_FLOATS + LP_SG) * 4)

__global__ void __launch_bounds__(256, 1)
lstm_scan(const float* __restrict__ h0,
          const float* __restrict__ c0,
          const float* __restrict__ Whh,
          const float* __restrict__ xW,       // [m][4H] row-major
          float* __restrict__ hs,
          unsigned int* __restrict__ bar)
{
    extern __shared__ float sh[];
    float* Wsm = sh;                              // [32][1024]
    float* hT  = sh + LP_W_FLOATS;                // [1024][18]
    float* pf  = hT;                              // aliases hT: [32][514]
    float* sg  = sh + LP_W_FLOATS + LP_HT_FLOATS; // [32][16]

    const int tid = threadIdx.x;
    const int hb  = blockIdx.x * 8;
    const int kt  = tid & 31;
    const int jt  = tid >> 5;

    // ---- preload W slice into smem (once) ----
#pragma unroll 4
    for (int ll = 0; ll < 32; ll++) {
        int j = (ll >> 3) * H_DIM + hb + (ll & 7);
        ((float4*)(Wsm + ll * H_DIM))[tid] =
            ((const float4*)(Whh + (size_t)j * H_DIM))[tid];
    }

    // ---- cell state in registers (threads 0..127) ----
    float cloc = 0.f;
    const int a_hil = tid >> 4;
    const int a_b   = tid & 15;
    if (tid < 128) cloc = c0[a_b * H_DIM + hb + a_hil];

    const float* wrow[4];
#pragma unroll
    for (int l = 0; l < 4; l++) wrow[l] = Wsm + (jt * 4 + l) * H_DIM + kt;

    const float* hsrc = h0;

    for (int t = 0; t < S_LEN; t++) {
        // ---- stage h transposed (L2 reads, bypass L1) ----
        {
            const int b   = tid & 15;
            const int e4b = tid >> 4;
            const float4* hp = (const float4*)(hsrc + b * H_DIM);
#pragma unroll
            for (int i = 0; i < 16; i++) {
                int e4 = e4b + 16 * i;
                float4 v = __ldcg(hp + e4);
                int e0 = e4 * 4;
                hT[(e0 + 0) * HT_STRIDE + b] = v.x;
                hT[(e0 + 1) * HT_STRIDE + b] = v.y;
                hT[(e0 + 2) * HT_STRIDE + b] = v.z;
                hT[(e0 + 3) * HT_STRIDE + b] = v.w;
            }
        }
        __syncthreads();

        // ---- partial GEMM, software-pipelined (double-buffered hv/w) ----
        unsigned long long acc[4][8];
#pragma unroll
        for (int l = 0; l < 4; l++)
#pragma unroll
            for (int bp = 0; bp < 8; bp++) acc[l][bp] = 0ull;

        unsigned long long hv[2][8];
        float wv[2][4];
        {
            const unsigned long long* hrow =
                (const unsigned long long*)(hT + kt * HT_STRIDE);
#pragma unroll
            for (int bp = 0; bp < 8; bp++) hv[0][bp] = hrow[bp];
#pragma unroll
            for (int l = 0; l < 4; l++) wv[0][l] = wrow[l][0];
        }

#pragma unroll 2
        for (int i = 0; i < 32; i++) {
            const int cur = i & 1, nxt = cur ^ 1;
            if (i < 31) {
                const int k2 = kt + 32 * (i + 1);
                const unsigned long long* hrow2 =
                    (const unsigned long long*)(hT + k2 * HT_STRIDE);
#pragma unroll
                for (int bp = 0; bp < 8; bp++) hv[nxt][bp] = hrow2[bp];
#pragma unroll
                for (int l = 0; l < 4; l++) wv[nxt][l] = wrow[l][32 * (i + 1)];
            }
            unsigned long long wd0 = dup2(wv[cur][0]), wd1 = dup2(wv[cur][1]);
            unsigned long long wd2 = dup2(wv[cur][2]), wd3 = dup2(wv[cur][3]);
#pragma unroll
            for (int bp = 0; bp < 8; bp++) {
                fma2(acc[0][bp], wd0, hv[cur][bp]);
                fma2(acc[1][bp], wd1, hv[cur][bp]);
                fma2(acc[2][bp], wd2, hv[cur][bp]);
                fma2(acc[3][bp], wd3, hv[cur][bp]);
            }
        }
        __syncthreads();   // hT reads done before pf (alias) writes

        {
            unsigned long long* pr =
                (unsigned long long*)(pf + kt * PF_STRIDE + (jt * 4) * 16);
#pragma unroll
            for (int l = 0; l < 4; l++)
#pragma unroll
                for (int bp = 0; bp < 8; bp++) pr[l * 8 + bp] = acc[l][bp];
        }
        __syncthreads();

        // ---- reduce over kt, add xW bias term ----
        {
            const int l = tid >> 3;
            const int b = (tid & 7) * 2;
            float s0 = 0.f, s1 = 0.f;
            const float* p = pf + l * 16 + b;
#pragma unroll 8
            for (int ktt = 0; ktt < 32; ktt++) {
                float2 v = *(const float2*)(p + ktt * PF_STRIDE);
                s0 += v.x; s1 += v.y;
            }
            const int j = (l >> 3) * H_DIM + hb + (l & 7);
            const size_t mrow = (size_t)t * 16;
            sg[l * 16 + b]     = s0 + __ldg(xW + (mrow + b) * G4 + j);
            sg[l * 16 + b + 1] = s1 + __ldg(xW + (mrow + b + 1) * G4 + j);
        }
        __syncthreads();

        // ---- activation + state update + publish h ----
        if (tid < 128) {
            float gi = sg[(0  + a_hil) * 16 + a_b];
            float gf = sg[(8  + a_hil) * 16 + a_b];
            float gg = sg[(16 + a_hil) * 16 + a_b];
            float go = sg[(24 + a_hil) * 16 + a_b];
            float cn = sigm(gf) * cloc + sigm(gi) * tanhf(gg);
            cloc = cn;
            hs[(size_t)t * B_SZ * H_DIM + a_b * H_DIM + hb + a_hil] =
                sigm(go) * tanhf(cn);
        }
        __threadfence();
        __syncthreads();

        // ---- grid barrier ----
        if (tid == 0) {
            atomicAdd(bar, 1u);
            const unsigned int target = 128u * (unsigned)(t + 1);
            while (*((volatile unsigned int*)bar) < target) { }
        }
        __syncthreads();

        hsrc = hs + (size_t)t * B_SZ * H_DIM;
    }
}

// ---------------- fp16 convert / split kernels -------------------------------
__global__ void __launch_bounds__(256)
conv_a_k(const float* __restrict__ src, __half* __restrict__ dst, int n4)
{
    int i = blockIdx.x * blockDim.x + threadIdx.x;
    if (i >= n4) return;
    float4 v = ((const float4*)src)[i];
    __half h[4] = { __float2half_rn(v.x), __float2half_rn(v.y),
                    __float2half_rn(v.z), __float2half_rn(v.w) };
    ((__half2*)dst)[2 * i]     = __halves2half2(h[0], h[1]);
    ((__half2*)dst)[2 * i + 1] = __halves2half2(h[2], h[3]);
}

// gather rows of emb via tokens and convert to fp16 (one block per row)
__global__ void __launch_bounds__(256)
conv_gather_k(const float* __restrict__ emb, const int* __restrict__ tokens,
              __half* __restrict__ dst)
{
    const int m = blockIdx.x;
    const float4* src = (const float4*)(emb + (size_t)tokens[m] * E_DIM);
    float4 v = src[threadIdx.x];                 // 256 thr x 4 = 1024 elems
    __half2 h0 = __halves2half2(__float2half_rn(v.x), __float2half_rn(v.y));
    __half2 h1 = __halves2half2(__float2half_rn(v.z), __float2half_rn(v.w));
    __half2* d = (__half2*)(dst + (size_t)m * E_DIM);
    d[threadIdx.x * 2]     = h0;
    d[threadIdx.x * 2 + 1] = h1;
}

__global__ void __launch_bounds__(256)
conv_b_k(const float* __restrict__ src, __half* __restrict__ out)
{
    int i = blockIdx.x * blockDim.x + threadIdx.x;   // over V_PAD*1024/4
    if (i >= V_PAD * (H_DIM / 4)) return;
    int row = i >> 8;
    float4 v = make_float4(0.f, 0.f, 0.f, 0.f);
    if (row < V_SZ) v = ((const float4*)src)[i];
    __half h[4] = { __float2half_rn(v.x), __float2half_rn(v.y),
                    __float2half_rn(v.z), __float2half_rn(v.w) };
    ((__half2*)out)[2 * i]     = __halves2half2(h[0], h[1]);
    ((__half2*)out)[2 * i + 1] = __halves2half2(h[2], h[3]);
}

__global__ void __launch_bounds__(256)
split_w_k(const float* __restrict__ src, __half* __restrict__ hi,
          __half* __restrict__ lo, int n4)
{
    int i = blockIdx.x * blockDim.x + threadIdx.x;
    if (i >= n4) return;
    float4 v = ((const float4*)src)[i];
    float xs[4] = {v.x, v.y, v.z, v.w};
    __half h[4], l[4];
#pragma unroll
    for (int j = 0; j < 4; j++) {
        h[j] = __float2half_rn(xs[j]);
        l[j] = __float2half_rn(xs[j] - __half2float(h[j]));
    }
    ((__half2*)hi)[2 * i]     = __halves2half2(h[0], h[1]);
    ((__half2*)hi)[2 * i + 1] = __halves2half2(h[2], h[3]);
    ((__half2*)lo)[2 * i]     = __halves2half2(l[0], l[1]);
    ((__half2*)lo)[2 * i + 1] = __halves2half2(l[2], l[3]);
}

// ---------------- xW GEMM: fp16 mma, 2-pass (A pre-gathered) -----------------
// xW[2048, 4096] = a_h @ (Wih_hi + Wih_lo)^T + bih + bhh
#define DROW 40

__global__ void __launch_bounds__(256, 2)
xw_gemm(const __half* __restrict__ a_h,
        const __half* __restrict__ w_hi, const __half* __restrict__ w_lo,
        const float* __restrict__ bih, const float* __restrict__ bhh,
        float* __restrict__ out)
{
    __shared__ __align__(16) __half As[2][128 * DROW];
    __shared__ __align__(16) __half Bs[2][128 * DROW];

    const int tid  = threadIdx.x;
    const int lane = tid & 31;
    const int warp = tid >> 5;
    const int warpM = warp >> 2;
    const int warpN = warp & 3;
    const int bm = blockIdx.y * 128;
    const int bn = blockIdx.x * 128;

    const uint32_t sA[2] = { smem_u32(As[0]), smem_u32(As[1]) };
    const uint32_t sB[2] = { smem_u32(Bs[0]), smem_u32(Bs[1]) };

    float acc[4][4][4];
#pragma unroll
    for (int i = 0; i < 4; i++)
#pragma unroll
        for (int j = 0; j < 4; j++)
#pragma unroll
            for (int r = 0; r < 4; r++) acc[i][j][r] = 0.f;

    const int r0c = tid >> 2, c0c = tid & 3;
    const int r1c = r0c + 64;

    auto issue = [&](int it, int buf) {
        const int p  = it >> 5;                  // 0: w_hi, 1: w_lo
        const int k0 = (it & 31) * 32;
        const __half* Bp = p ? w_lo : w_hi;
        cp16(sA[buf] + (r0c * DROW + c0c * 8) * 2,
             a_h + (size_t)(bm + r0c) * E_DIM + k0 + c0c * 8);
        cp16(sA[buf] + (r1c * DROW + c0c * 8) * 2,
             a_h + (size_t)(bm + r1c) * E_DIM + k0 + c0c * 8);
        cp16(sB[buf] + (r0c * DROW + c0c * 8) * 2,
             Bp + (size_t)(bn + r0c) * E_DIM + k0 + c0c * 8);
        cp16(sB[buf] + (r1c * DROW + c0c * 8) * 2,
             Bp + (size_t)(bn + r1c) * E_DIM + k0 + c0c * 8);
    };

    issue(0, 0);
    CP_COMMIT();

    for (int it = 0; it < 64; it++) {
        const int buf = it & 1;
        if (it + 1 < 64) { issue(it + 1, buf ^ 1); CP_COMMIT(); CP_WAIT1(); }
        else             { CP_WAIT0(); }
        __syncthreads();

#pragma unroll
        for (int ks = 0; ks < 2; ks++) {
            uint32_t af[4][4];
#pragma unroll
            for (int mf = 0; mf < 4; mf++) {
                int row = warpM * 64 + mf * 16 + (lane & 15);
                int ch  = ks * 2 + (lane >> 4);
                ldsm_x4(af[mf], sA[buf] + (row * DROW + ch * 8) * 2);
            }
            uint32_t br[2][4];
#pragma unroll
            for (int g = 0; g < 2; g++) {
                int row = warpN * 32 + g * 16 + ((lane >> 4) << 3) + (lane & 7);
                int ch  = ks * 2 + ((lane >> 3) & 1);
                ldsm_x4(br[g], sB[buf] + (row * DROW + ch * 8) * 2);
            }
#pragma unroll
            for (int mf = 0; mf < 4; mf++)
#pragma unroll
                for (int g = 0; g < 2; g++) {
                    mma16816(acc[mf][g * 2],     af[mf], &br[g][0]);
                    mma16816(acc[mf][g * 2 + 1], af[mf], &br[g][2]);
                }
        }
        __syncthreads();
    }

#pragma unroll
    for (int mf = 0; mf < 4; mf++) {
        int rowA = bm + warpM * 64 + mf * 16 + (lane >> 2);
        int rowB = rowA + 8;
#pragma unroll
        for (int nf = 0; nf < 4; nf++) {
            int col = bn + warpN * 32 + nf * 8 + (lane & 3) * 2;
            float b0 = bih[col]     + bhh[col];
            float b1 = bih[col + 1] + bhh[col + 1];
            out[(size_t)rowA * G4 + col]     = acc[mf][nf][0] + b0;
            out[(size_t)rowA * G4 + col + 1] = acc[mf][nf][1] + b1;
            out[(size_t)rowB * G4 + col]     = acc[mf][nf][2] + b0;
            out[(size_t)rowB * G4 + col + 1] = acc[mf][nf][3] + b1;
        }
    }
}

// ---------------- mma.sync decoder GEMM (fp16, single pass, 2 CTAs/SM) ------
__global__ void __launch_bounds__(256, 2)
dec_gemm(const __half* __restrict__ a_h, const __half* __restrict__ b_h,
         const float* __restrict__ bias, float* __restrict__ out)
{
    __shared__ __align__(16) __half As[2][128 * DROW];
    __shared__ __align__(16) __half Bs[2][128 * DROW];

    const int tid  = threadIdx.x;
    const int lane = tid & 31;
    const int warp = tid >> 5;
    const int warpM = warp >> 2;
    const int warpN = warp & 3;
    const int bm = blockIdx.y * 128;
    const int bn = blockIdx.x * 128;

    const uint32_t sA[2] = { smem_u32(As[0]), smem_u32(As[1]) };
    const uint32_t sB[2] = { smem_u32(Bs[0]), smem_u32(Bs[1]) };

    float acc[4][4][4];
#pragma unroll
    for (int i = 0; i < 4; i++)
#pragma unroll
        for (int j = 0; j < 4; j++)
#pragma unroll
            for (int r = 0; r < 4; r++) acc[i][j][r] = 0.f;

    const int r0c = tid >> 2, c0c = tid & 3;
    const int r1c = (tid + 256) >> 2, c1c = tid & 3;

    auto issue = [&](int it, int buf) {
        const int k0 = it * 32;
        cp16(sA[buf] + (r0c * DROW + c0c * 8) * 2,
             a_h + (size_t)(bm + r0c) * H_DIM + k0 + c0c * 8);
        cp16(sA[buf] + (r1c * DROW + c1c * 8) * 2,
             a_h + (size_t)(bm + r1c) * H_DIM + k0 + c1c * 8);
        cp16(sB[buf] + (r0c * DROW + c0c * 8) * 2,
             b_h + (size_t)(bn + r0c) * H_DIM + k0 + c0c * 8);
        cp16(sB[buf] + (r1c * DROW + c1c * 8) * 2,
             b_h + (size_t)(bn + r1c) * H_DIM + k0 + c1c * 8);
    };

    issue(0, 0);
    CP_COMMIT();

    for (int it = 0; it < 32; it++) {
        const int buf = it & 1;
        if (it + 1 < 32) { issue(it + 1, buf ^ 1); CP_COMMIT(); CP_WAIT1(); }
        else             { CP_WAIT0(); }
        __syncthreads();

#pragma unroll
        for (int ks = 0; ks < 2; ks++) {
            uint32_t af[4][4];
#pragma unroll
            for (int mf = 0; mf < 4; mf++) {
                int row = warpM * 64 + mf * 16 + (lane & 15);
                int ch  = ks * 2 + (lane >> 4);
                ldsm_x4(af[mf], sA[buf] + (row * DROW + ch * 8) * 2);
            }
            uint32_t br[2][4];
#pragma unroll
            for (int g = 0; g < 2; g++) {
                int row = warpN * 32 + g * 16 + ((lane >> 4) << 3) + (lane & 7);
                int ch  = ks * 2 + ((lane >> 3) & 1);
                ldsm_x4(br[g], sB[buf] + (row * DROW + ch * 8) * 2);
            }
#pragma unroll
            for (int mf = 0; mf < 4; mf++)
#pragma unroll
                for (int g = 0; g < 2; g++) {
                    mma16816(acc[mf][g * 2],     af[mf], &br[g][0]);
                    mma16816(acc[mf][g * 2 + 1], af[mf], &br[g][2]);
                }
        }
        __syncthreads();
    }

#pragma unroll
    for (int mf = 0; mf < 4; mf++) {
        int rowA = bm + warpM * 64 + mf * 16 + (lane >> 2);
        int rowB = rowA + 8;
#pragma unroll
        for (int nf = 0; nf < 4; nf++) {
            int col = bn + warpN * 32 + nf * 8 + (lane & 3) * 2;
            float b0 = (col     < V_SZ) ? bias[col]     : 0.f;
            float b1 = (col + 1 < V_SZ) ? bias[col + 1] : 0.f;
            if (col < V_SZ)     out[(size_t)rowA * V_SZ + col]     = acc[mf][nf][0] + b0;
            if (col + 1 < V_SZ) out[(size_t)rowA * V_SZ + col + 1] = acc[mf][nf][1] + b1;
            if (col < V_SZ)     out[(size_t)rowB * V_SZ + col]     = acc[mf][nf][2] + b0;
            if (col + 1 < V_SZ) out[(size_t)rowB * V_SZ + col + 1] = acc[mf][nf][3] + b1;
        }
    }
}

// ---------------- launcher --------------------------------------------------
extern "C" void kernel_launch(void* const* d_in, const int* in_sizes, int n_in,
                              void* d_out, int out_size)
{
    const int*   tokens = (const int*)  d_in[0];
    const float* h0     = (const float*)d_in[1];
    const float* c0     = (const float*)d_in[2];
    const float* emb    = (const float*)d_in[3];
    const float* Wih    = (const float*)d_in[4];
    const float* Whh    = (const float*)d_in[5];
    const float* bih    = (const float*)d_in[6];
    const float* bhh    = (const float*)d_in[7];
    const float* Whh2   = (const float*)d_in[8];
    const float* bhh2   = (const float*)d_in[9];
    const float* Whm    = (const float*)d_in[10];
    const float* bhm    = (const float*)d_in[11];
    const float* decW   = (const float*)d_in[12];
    const float* decb   = (const float*)d_in[13];
    const int*   kp     = (const int*)  d_in[14];
    float* out = (float*)d_out;

    void *p_xW, *p_hs, *p_outb, *p_hm, *p_bar, *p_ah, *p_bh, *p_wh, *p_wl;
    cudaGetSymbolAddress(&p_xW,   g_xW);
    cudaGetSymbolAddress(&p_hs,   g_hs);
    cudaGetSymbolAddress(&p_outb, g_outbuf);
    cudaGetSymbolAddress(&p_hm,   g_hm);
    cudaGetSymbolAddress(&p_bar,  g_bar);
    cudaGetSymbolAddress(&p_ah,   g_a_h);
    cudaGetSymbolAddress(&p_bh,   g_b_h);
    cudaGetSymbolAddress(&p_wh,   g_wih_hi);
    cudaGetSymbolAddress(&p_wl,   g_wih_lo);
    float* xW   = (float*)p_xW;
    float* hs   = (float*)p_hs;
    float* ob   = (float*)p_outb;
    float* hm   = (float*)p_hm;
    unsigned int* bar = (unsigned int*)p_bar;
    __half* ah = (__half*)p_ah;
    __half* bh = (__half*)p_bh;
    __half* wh = (__half*)p_wh;
    __half* wl = (__half*)p_wl;

    cudaFuncSetAttribute(lstm_scan, cudaFuncAttributeMaxDynamicSharedMemorySize,
                         LP_SMEM);

    const int M = S_LEN * B_SZ;   // 2048

    // 0) conversions: gather emb rows -> fp16 (into g_a_h, reused later);
    //    Wih -> fp16 hi/lo; decW -> fp16
    conv_gather_k<<<M, 256>>>(emb, tokens, ah);
    split_w_k<<<(G4 * E_DIM / 4 + 255) / 256, 256>>>(Wih, wh, wl, G4 * E_DIM / 4);
    conv_b_k<<<(V_PAD * H_DIM / 4 + 255) / 256, 256>>>(decW, bh);

    // 1) xW = a_h @ (Wih_hi+Wih_lo)^T + bih + bhh  (mma, 2-pass)
    xw_gemm<<<dim3(G4 / 128, M / 128), 256>>>(ah, wh, wl, bih, bhh, xW);

    // 2) hm = h0 @ Whm^T + bhm
    gemm_k<0><<<dim3(H_DIM / 128, 1), 256>>>(
        h0, Whm, hm, B_SZ, H_DIM, H_DIM, bhm, nullptr, nullptr);

    // 3) reset grid barrier
    cudaMemsetAsync(bar, 0, sizeof(unsigned int), 0);

    // 4) persistent LSTM scan (one launch, 128 internal steps)
    lstm_scan<<<128, 256, LP_SMEM>>>(h0, c0, Whh, xW, hs, bar);

    // 5) outputs = (s<k) ? hs : hs @ Whh2^T + bhh2 + hm
    gemm_k<2><<<dim3(H_DIM / 128, M / 128), 256>>>(
        hs, Whh2, ob, M, H_DIM, H_DIM, bhh2, hm, kp);

    // convert outputs -> fp16 (overwrites gathered emb in g_a_h — already consumed)
    conv_a_k<<<(M * H_DIM / 4 + 255) / 256, 256>>>(ob, ah, M * H_DIM / 4);

    // 6) decoded = outputs @ decW^T + decb  — mma.sync fp16 single-pass GEMM
    dec_gemm<<<dim3(V_PAD / 128, M / 128), 256>>>(ah, bh, decb, out);

    (void)in_sizes; (void)n_in; (void)out_size;
}

// round 13
// speedup vs baseline: 2.8309x; 1.1566x over previous
#include <cuda_runtime.h>
#include <cuda_bf16.h>
#include <cuda_fp16.h>
#include <cstdint>

// Problem dims (fixed by the dataset)
#define S_LEN 128
#define B_SZ  16
#define H_DIM 1024
#define E_DIM 1024
#define G4    4096
#define V_SZ  50257
#define V_PAD 50304          // 393 * 128

// ---------------- scratch (device globals; no allocation allowed) ----------
__device__ float g_xW [S_LEN * B_SZ * G4];       // plain row-major [m][4H]
__device__ float g_hs [S_LEN * B_SZ * H_DIM];
__device__ float g_outbuf[S_LEN * B_SZ * H_DIM];
__device__ float g_hm [B_SZ * H_DIM];
__device__ unsigned int g_bar;
__device__ __align__(256) __half g_a_h[S_LEN * B_SZ * H_DIM];  // gathered emb, then outputs
__device__ __align__(256) __half g_b_h[(size_t)V_PAD * H_DIM];
__device__ __align__(256) __half g_wih_hi[G4 * E_DIM];
__device__ __align__(256) __half g_wih_lo[G4 * E_DIM];
__device__ __align__(256) __half g_whh_hi[G4 * H_DIM];
__device__ __align__(256) __half g_whh_lo[G4 * H_DIM];

// ---------------- f32x2 helpers --------------------------------------------
__device__ __forceinline__ unsigned long long dup2(float x) {
    unsigned long long r; asm("mov.b64 %0, {%1, %1};" : "=l"(r) : "f"(x)); return r;
}
__device__ __forceinline__ unsigned long long pk2(float lo, float hi) {
    unsigned long long r; asm("mov.b64 %0, {%1, %2};" : "=l"(r) : "f"(lo), "f"(hi)); return r;
}
__device__ __forceinline__ void fma2(unsigned long long& d,
                                     unsigned long long a, unsigned long long b) {
    asm("fma.rn.f32x2 %0, %1, %2, %0;" : "+l"(d) : "l"(a), "l"(b));
}
__device__ __forceinline__ float2 up2(unsigned long long v) {
    float2 f; asm("mov.b64 {%0, %1}, %2;" : "=f"(f.x), "=f"(f.y) : "l"(v)); return f;
}
__device__ __forceinline__ float sigm(float x) { return 1.0f / (1.0f + expf(-x)); }

__device__ __forceinline__ uint32_t smem_u32(const void* p) {
    uint32_t a;
    asm("{ .reg .u64 t; cvta.to.shared.u64 t, %1; cvt.u32.u64 %0, t; }"
        : "=r"(a) : "l"(p));
    return a;
}
__device__ __forceinline__ unsigned int ld_acq(const unsigned int* p) {
    unsigned int v;
    asm volatile("ld.acquire.gpu.u32 %0, [%1];" : "=r"(v) : "l"(p) : "memory");
    return v;
}
__device__ __forceinline__ void red_rel_add(unsigned int* p, unsigned int v) {
    asm volatile("red.release.gpu.global.add.u32 [%0], %1;" :: "l"(p), "r"(v) : "memory");
}

// ---------------- mma.sync / ldmatrix / cp.async helpers (non-'a' PTX) ------
__device__ __forceinline__ void ldsm_x4(uint32_t* r, uint32_t addr) {
    asm volatile("ldmatrix.sync.aligned.m8n8.x4.shared.b16 {%0,%1,%2,%3}, [%4];"
                 : "=r"(r[0]), "=r"(r[1]), "=r"(r[2]), "=r"(r[3]) : "r"(addr));
}
__device__ __forceinline__ void mma16816(float* c, const uint32_t* a, const uint32_t* b) {
    asm volatile(
        "mma.sync.aligned.m16n8k16.row.col.f32.f16.f16.f32 "
        "{%0,%1,%2,%3}, {%4,%5,%6,%7}, {%8,%9}, {%0,%1,%2,%3};"
        : "+f"(c[0]), "+f"(c[1]), "+f"(c[2]), "+f"(c[3])
        : "r"(a[0]), "r"(a[1]), "r"(a[2]), "r"(a[3]), "r"(b[0]), "r"(b[1]));
}
__device__ __forceinline__ void cp16(uint32_t dst, const void* src) {
    asm volatile("cp.async.cg.shared.global [%0], [%1], 16;" :: "r"(dst), "l"(src));
}
#define CP_COMMIT() asm volatile("cp.async.commit_group;" ::: "memory")
#define CP_WAIT1()  asm volatile("cp.async.wait_group 1;" ::: "memory")
#define CP_WAIT0()  asm volatile("cp.async.wait_group 0;" ::: "memory")

// ---------------- generic tiled fp32 GEMM (steps 2,5) -----------------------
template <int MODE>
__global__ void __launch_bounds__(256)
gemm_k(const float* __restrict__ A, const float* __restrict__ Bm,
       float* __restrict__ C, int M, int N, int K,
       const float* __restrict__ bias0,
       const float* __restrict__ hmv, const int* __restrict__ kptr)
{
    constexpr int BM = 128, BN = 128, BK = 16;
    __shared__ float As[BK][BM + 4];
    __shared__ float Bs[BK][BN + 4];

    const int tid = threadIdx.x;
    const int bm = blockIdx.y * BM;
    const int bn = blockIdx.x * BN;
    const int tx = tid & 15;
    const int ty = tid >> 4;
    const int lr = tid >> 2;
    const int lk = (tid & 3) * 4;

    unsigned long long acc[8][4];
#pragma unroll
    for (int i = 0; i < 8; i++)
#pragma unroll
        for (int j = 0; j < 4; j++) acc[i][j] = 0ull;

    const int m0 = bm + lr, m1 = bm + lr + 64;
    const float* arow0 = (m0 < M) ? A + (size_t)m0 * K : nullptr;
    const float* arow1 = (m1 < M) ? A + (size_t)m1 * K : nullptr;
    const int n0 = bn + lr, n1 = bn + lr + 64;
    const float* brow0 = (n0 < N) ? Bm + (size_t)n0 * K : nullptr;
    const float* brow1 = (n1 < N) ? Bm + (size_t)n1 * K : nullptr;

    const float4 fz = make_float4(0.f, 0.f, 0.f, 0.f);

    for (int k0 = 0; k0 < K; k0 += BK) {
        float4 a0 = arow0 ? *(const float4*)(arow0 + k0 + lk) : fz;
        float4 a1 = arow1 ? *(const float4*)(arow1 + k0 + lk) : fz;
        float4 b0 = brow0 ? *(const float4*)(brow0 + k0 + lk) : fz;
        float4 b1 = brow1 ? *(const float4*)(brow1 + k0 + lk) : fz;

        __syncthreads();
        As[lk + 0][lr] = a0.x;  As[lk + 1][lr] = a0.y;
        As[lk + 2][lr] = a0.z;  As[lk + 3][lr] = a0.w;
        As[lk + 0][lr + 64] = a1.x;  As[lk + 1][lr + 64] = a1.y;
        As[lk + 2][lr + 64] = a1.z;  As[lk + 3][lr + 64] = a1.w;
        Bs[lk + 0][lr] = b0.x;  Bs[lk + 1][lr] = b0.y;
        Bs[lk + 2][lr] = b0.z;  Bs[lk + 3][lr] = b0.w;
        Bs[lk + 0][lr + 64] = b1.x;  Bs[lk + 1][lr + 64] = b1.y;
        Bs[lk + 2][lr + 64] = b1.z;  Bs[lk + 3][lr + 64] = b1.w;
        __syncthreads();

#pragma unroll
        for (int kk = 0; kk < BK; kk++) {
            float4 av0 = *(const float4*)&As[kk][ty * 8];
            float4 av1 = *(const float4*)&As[kk][ty * 8 + 4];
            float4 bv0 = *(const float4*)&Bs[kk][tx * 8];
            float4 bv1 = *(const float4*)&Bs[kk][tx * 8 + 4];
            unsigned long long a2[8] = {dup2(av0.x), dup2(av0.y), dup2(av0.z), dup2(av0.w),
                                        dup2(av1.x), dup2(av1.y), dup2(av1.z), dup2(av1.w)};
            unsigned long long b2[4] = {pk2(bv0.x, bv0.y), pk2(bv0.z, bv0.w),
                                        pk2(bv1.x, bv1.y), pk2(bv1.z, bv1.w)};
#pragma unroll
            for (int i = 0; i < 8; i++)
#pragma unroll
                for (int j = 0; j < 4; j++) fma2(acc[i][j], a2[i], b2[j]);
        }
    }

    const int kval = (MODE == 2) ? *kptr : 0;

#pragma unroll
    for (int i = 0; i < 8; i++) {
        int m = bm + ty * 8 + i;
        if (m >= M) continue;
        size_t crow = (size_t)m * N;
        int srow = m >> 4;
        int b    = m & 15;
        bool cp = (MODE == 2) && (srow < kval);
#pragma unroll
        for (int j = 0; j < 4; j++) {
            float2 v = up2(acc[i][j]);
            int n = bn + tx * 8 + 2 * j;
            float vals[2] = {v.x, v.y};
#pragma unroll
            for (int u = 0; u < 2; u++) {
                int nn = n + u;
                if (nn >= N) continue;
                float r;
                if (MODE == 0) r = vals[u] + bias0[nn];
                else           r = cp ? A[(size_t)m * K + nn]
                                      : vals[u] + bias0[nn] + hmv[b * H_DIM + nn];
                C[crow + nn] = r;
            }
        }
    }
}

// ---------------- persistent LSTM scan — TENSOR CORE version ----------------
// 128 blocks x 256 threads. Block owns 8 hidden cols x 4 gates = 32 gate cols.
// Whh slice pre-split to fp16 hi/lo in gmem, staged to smem once (rows padded
// to 1032 halves => odd 16B-chunk stride => ldmatrix conflict-free).
// Per step: h -> fp16 hi/lo A-tile; warp w computes K slice [w*128,(w+1)*128)
// with 3-pass split mma (Ahi*Whi + Alo*Whi + Ahi*Wlo; dropped term ~2^-22);
// partials (8 x 16x32 fp32) reduced + fused activation; release/acquire barrier.
#define SC_ROW 1032
#define SC_W_HALFS (32 * SC_ROW)              // 33024
#define SC_A_HALFS (16 * SC_ROW)              // 16512
#define SC_PF_STRIDE 34
#define SC_PF_FLOATS (8 * 16 * SC_PF_STRIDE)  // 4352
#define SC_SMEM ((2 * SC_W_HALFS + 2 * SC_A_HALFS) * 2 + SC_PF_FLOATS * 4)  // 215552

__global__ void __launch_bounds__(256, 1)
lstm_scan_mma(const float* __restrict__ h0,
              const float* __restrict__ c0,
              const __half* __restrict__ whh_hi,
              const __half* __restrict__ whh_lo,
              const float* __restrict__ xW,   // [m][4H] row-major
              float* __restrict__ hs,
              unsigned int* __restrict__ bar)
{
    extern __shared__ __half shh[];
    __half* sWhi = shh;
    __half* sWlo = shh + SC_W_HALFS;
    __half* sAhi = shh + 2 * SC_W_HALFS;
    __half* sAlo = shh + 2 * SC_W_HALFS + SC_A_HALFS;
    float*  pf   = (float*)(shh + 2 * SC_W_HALFS + 2 * SC_A_HALFS);

    const int tid  = threadIdx.x;
    const int lane = tid & 31;
    const int w    = tid >> 5;
    const int hb   = blockIdx.x * 8;

    // ---- preload W hi/lo slices (once): 32 rows x 1024 halves each ----
#pragma unroll
    for (int it = 0; it < 16; it++) {
        int idx = tid + it * 256;            // 0..4095 chunks of 8 halves
        int ll = idx >> 7, c8 = idx & 127;
        int j  = (ll >> 3) * H_DIM + hb + (ll & 7);
        *(uint4*)(sWhi + ll * SC_ROW + c8 * 8) =
            *(const uint4*)(whh_hi + (size_t)j * H_DIM + c8 * 8);
        *(uint4*)(sWlo + ll * SC_ROW + c8 * 8) =
            *(const uint4*)(whh_lo + (size_t)j * H_DIM + c8 * 8);
    }

    // ---- cell state in registers (threads 0..127) ----
    const int a_b = tid & 15, a_hil = (tid >> 4) & 7;
    float cloc = 0.f;
    if (tid < 128) cloc = c0[a_b * H_DIM + hb + a_hil];

    // staging map: m = tid&15 (2-way STS conflicts), seg = tid>>4
    const int st_m = tid & 15, st_seg = tid >> 4;
    const int kc = w * 16;                   // warp's K base in 8-half chunks

    const float* hsrc = h0;

    for (int t = 0; t < S_LEN; t++) {
        // ---- prefetch xW gate biases for this thread's output ----
        float xv0 = 0.f, xv1 = 0.f, xv2 = 0.f, xv3 = 0.f;
        if (tid < 128) {
            const float* xp = xW + ((size_t)t * 16 + a_b) * G4 + hb + a_hil;
            xv0 = __ldg(xp);        xv1 = __ldg(xp + 1024);
            xv2 = __ldg(xp + 2048); xv3 = __ldg(xp + 3072);
        }

        // ---- stage h -> fp16 hi/lo A-tile ----
        {
            const float4* hp = (const float4*)(hsrc + st_m * H_DIM + st_seg * 64);
            __half2* dhi = (__half2*)(sAhi + st_m * SC_ROW + st_seg * 64);
            __half2* dlo = (__half2*)(sAlo + st_m * SC_ROW + st_seg * 64);
#pragma unroll
            for (int i = 0; i < 16; i++) {
                float4 v = __ldcg(hp + i);
                __half h0_ = __float2half_rn(v.x);
                __half h1_ = __float2half_rn(v.y);
                __half h2_ = __float2half_rn(v.z);
                __half h3_ = __float2half_rn(v.w);
                __half l0_ = __float2half_rn(v.x - __half2float(h0_));
                __half l1_ = __float2half_rn(v.y - __half2float(h1_));
                __half l2_ = __float2half_rn(v.z - __half2float(h2_));
                __half l3_ = __float2half_rn(v.w - __half2float(h3_));
                dhi[i * 2]     = __halves2half2(h0_, h1_);
                dhi[i * 2 + 1] = __halves2half2(h2_, h3_);
                dlo[i * 2]     = __halves2half2(l0_, l1_);
                dlo[i * 2 + 1] = __halves2half2(l2_, l3_);
            }
        }
        __syncthreads();

        // ---- mma: M=16, N=32, K=128 per warp, 3-pass split ----
        float acc[4][4];
#pragma unroll
        for (int nf = 0; nf < 4; nf++)
#pragma unroll
            for (int r = 0; r < 4; r++) acc[nf][r] = 0.f;

#pragma unroll
        for (int pass = 0; pass < 3; pass++) {
            const __half* Asrc = (pass == 1) ? sAlo : sAhi;
            const __half* Wsrc = (pass == 2) ? sWlo : sWhi;
#pragma unroll
            for (int ks = 0; ks < 8; ks++) {
                uint32_t af[4];
                ldsm_x4(af, smem_u32(Asrc + (lane & 15) * SC_ROW
                                     + (kc + ks * 2 + (lane >> 4)) * 8));
                uint32_t br[2][4];
#pragma unroll
                for (int g = 0; g < 2; g++) {
                    int row = g * 16 + ((lane >> 4) << 3) + (lane & 7);
                    ldsm_x4(br[g], smem_u32(Wsrc + row * SC_ROW
                                            + (kc + ks * 2 + ((lane >> 3) & 1)) * 8));
                }
#pragma unroll
                for (int g = 0; g < 2; g++) {
                    mma16816(acc[g * 2],     af, &br[g][0]);
                    mma16816(acc[g * 2 + 1], af, &br[g][2]);
                }
            }
        }

        // ---- store partials: pf[w][m][n], stride 34 ----
        {
            float* pw = pf + w * 16 * SC_PF_STRIDE;
            int r0 = lane >> 2;
            int cb = (lane & 3) * 2;
#pragma unroll
            for (int nf = 0; nf < 4; nf++) {
                int c = nf * 8 + cb;
                *(float2*)(pw + r0 * SC_PF_STRIDE + c) =
                    make_float2(acc[nf][0], acc[nf][1]);
                *(float2*)(pw + (r0 + 8) * SC_PF_STRIDE + c) =
                    make_float2(acc[nf][2], acc[nf][3]);
            }
        }
        __syncthreads();

        // ---- reduce over 8 warps + fused activation (threads 0..127) ----
        if (tid < 128) {
            float gI = xv0, gF = xv1, gG = xv2, gO = xv3;
            const float* pw = pf + a_b * SC_PF_STRIDE + a_hil;
#pragma unroll
            for (int ww = 0; ww < 8; ww++) {
                const float* p = pw + ww * 16 * SC_PF_STRIDE;
                gI += p[0]; gF += p[8]; gG += p[16]; gO += p[24];
            }
            float cn = sigm(gF) * cloc + sigm(gI) * tanhf(gG);
            cloc = cn;
            hs[(size_t)t * B_SZ * H_DIM + a_b * H_DIM + hb + a_hil] =
                sigm(gO) * tanhf(cn);
        }
        __syncthreads();

        // ---- grid barrier: release-add + acquire-poll ----
        if (tid == 0) {
            red_rel_add(bar, 1u);
            const unsigned int target = 128u * (unsigned)(t + 1);
            while (ld_acq(bar) < target) { }
        }
        __syncthreads();

        hsrc = hs + (size_t)t * B_SZ * H_DIM;
    }
}

// ---------------- fp16 convert / split kernels -------------------------------
__global__ void __launch_bounds__(256)
conv_a_k(const float* __restrict__ src, __half* __restrict__ dst, int n4)
{
    int i = blockIdx.x * blockDim.x + threadIdx.x;
    if (i >= n4) return;
    float4 v = ((const float4*)src)[i];
    __half h[4] = { __float2half_rn(v.x), __float2half_rn(v.y),
                    __float2half_rn(v.z), __float2half_rn(v.w) };
    ((__half2*)dst)[2 * i]     = __halves2half2(h[0], h[1]);
    ((__half2*)dst)[2 * i + 1] = __halves2half2(h[2], h[3]);
}

// gather rows of emb via tokens and convert to fp16 (one block per row)
__global__ void __launch_bounds__(256)
conv_gather_k(const float* __restrict__ emb, const int* __restrict__ tokens,
              __half* __restrict__ dst)
{
    const int m = blockIdx.x;
    const float4* src = (const float4*)(emb + (size_t)tokens[m] * E_DIM);
    float4 v = src[threadIdx.x];
    __half2 h0 = __halves2half2(__float2half_rn(v.x), __float2half_rn(v.y));
    __half2 h1 = __halves2half2(__float2half_rn(v.z), __float2half_rn(v.w));
    __half2* d = (__half2*)(dst + (size_t)m * E_DIM);
    d[threadIdx.x * 2]     = h0;
    d[threadIdx.x * 2 + 1] = h1;
}

__global__ void __launch_bounds__(256)
conv_b_k(const float* __restrict__ src, __half* __restrict__ out)
{
    int i = blockIdx.x * blockDim.x + threadIdx.x;
    if (i >= V_PAD * (H_DIM / 4)) return;
    int row = i >> 8;
    float4 v = make_float4(0.f, 0.f, 0.f, 0.f);
    if (row < V_SZ) v = ((const float4*)src)[i];
    __half h[4] = { __float2half_rn(v.x), __float2half_rn(v.y),
                    __float2half_rn(v.z), __float2half_rn(v.w) };
    ((__half2*)out)[2 * i]     = __halves2half2(h[0], h[1]);
    ((__half2*)out)[2 * i + 1] = __halves2half2(h[2], h[3]);
}

__global__ void __launch_bounds__(256)
split_w_k(const float* __restrict__ src, __half* __restrict__ hi,
          __half* __restrict__ lo, int n4)
{
    int i = blockIdx.x * blockDim.x + threadIdx.x;
    if (i >= n4) return;
    float4 v = ((const float4*)src)[i];
    float xs[4] = {v.x, v.y, v.z, v.w};
    __half h[4], l[4];
#pragma unroll
    for (int j = 0; j < 4; j++) {
        h[j] = __float2half_rn(xs[j]);
        l[j] = __float2half_rn(xs[j] - __half2float(h[j]));
    }
    ((__half2*)hi)[2 * i]     = __halves2half2(h[0], h[1]);
    ((__half2*)hi)[2 * i + 1] = __halves2half2(h[2], h[3]);
    ((__half2*)lo)[2 * i]     = __halves2half2(l[0], l[1]);
    ((__half2*)lo)[2 * i + 1] = __halves2half2(l[2], l[3]);
}

// ---------------- xW GEMM: fp16 mma, 2-pass (A pre-gathered) -----------------
#define DROW 40

__global__ void __launch_bounds__(256, 2)
xw_gemm(const __half* __restrict__ a_h,
        const __half* __restrict__ w_hi, const __half* __restrict__ w_lo,
        const float* __restrict__ bih, const float* __restrict__ bhh,
        float* __restrict__ out)
{
    __shared__ __align__(16) __half As[2][128 * DROW];
    __shared__ __align__(16) __half Bs[2][128 * DROW];

    const int tid  = threadIdx.x;
    const int lane = tid & 31;
    const int warp = tid >> 5;
    const int warpM = warp >> 2;
    const int warpN = warp & 3;
    const int bm = blockIdx.y * 128;
    const int bn = blockIdx.x * 128;

    const uint32_t sA[2] = { smem_u32(As[0]), smem_u32(As[1]) };
    const uint32_t sB[2] = { smem_u32(Bs[0]), smem_u32(Bs[1]) };

    float acc[4][4][4];
#pragma unroll
    for (int i = 0; i < 4; i++)
#pragma unroll
        for (int j = 0; j < 4; j++)
#pragma unroll
            for (int r = 0; r < 4; r++) acc[i][j][r] = 0.f;

    const int r0c = tid >> 2, c0c = tid & 3;
    const int r1c = r0c + 64;

    auto issue = [&](int it, int buf) {
        const int p  = it >> 5;
        const int k0 = (it & 31) * 32;
        const __half* Bp = p ? w_lo : w_hi;
        cp16(sA[buf] + (r0c * DROW + c0c * 8) * 2,
             a_h + (size_t)(bm + r0c) * E_DIM + k0 + c0c * 8);
        cp16(sA[buf] + (r1c * DROW + c0c * 8) * 2,
             a_h + (size_t)(bm + r1c) * E_DIM + k0 + c0c * 8);
        cp16(sB[buf] + (r0c * DROW + c0c * 8) * 2,
             Bp + (size_t)(bn + r0c) * E_DIM + k0 + c0c * 8);
        cp16(sB[buf] + (r1c * DROW + c0c * 8) * 2,
             Bp + (size_t)(bn + r1c) * E_DIM + k0 + c0c * 8);
    };

    issue(0, 0);
    CP_COMMIT();

    for (int it = 0; it < 64; it++) {
        const int buf = it & 1;
        if (it + 1 < 64) { issue(it + 1, buf ^ 1); CP_COMMIT(); CP_WAIT1(); }
        else             { CP_WAIT0(); }
        __syncthreads();

#pragma unroll
        for (int ks = 0; ks < 2; ks++) {
            uint32_t af[4][4];
#pragma unroll
            for (int mf = 0; mf < 4; mf++) {
                int row = warpM * 64 + mf * 16 + (lane & 15);
                int ch  = ks * 2 + (lane >> 4);
                ldsm_x4(af[mf], sA[buf] + (row * DROW + ch * 8) * 2);
            }
            uint32_t br[2][4];
#pragma unroll
            for (int g = 0; g < 2; g++) {
                int row = warpN * 32 + g * 16 + ((lane >> 4) << 3) + (lane & 7);
                int ch  = ks * 2 + ((lane >> 3) & 1);
                ldsm_x4(br[g], sB[buf] + (row * DROW + ch * 8) * 2);
            }
#pragma unroll
            for (int mf = 0; mf < 4; mf++)
#pragma unroll
                for (int g = 0; g < 2; g++) {
                    mma16816(acc[mf][g * 2],     af[mf], &br[g][0]);
                    mma16816(acc[mf][g * 2 + 1], af[mf], &br[g][2]);
                }
        }
        __syncthreads();
    }

#pragma unroll
    for (int mf = 0; mf < 4; mf++) {
        int rowA = bm + warpM * 64 + mf * 16 + (lane >> 2);
        int rowB = rowA + 8;
#pragma unroll
        for (int nf = 0; nf < 4; nf++) {
            int col = bn + warpN * 32 + nf * 8 + (lane & 3) * 2;
            float b0 = bih[col]     + bhh[col];
            float b1 = bih[col + 1] + bhh[col + 1];
            out[(size_t)rowA * G4 + col]     = acc[mf][nf][0] + b0;
            out[(size_t)rowA * G4 + col + 1] = acc[mf][nf][1] + b1;
            out[(size_t)rowB * G4 + col]     = acc[mf][nf][2] + b0;
            out[(size_t)rowB * G4 + col + 1] = acc[mf][nf][3] + b1;
        }
    }
}

// ---------------- mma.sync decoder GEMM (fp16, single pass, 2 CTAs/SM) ------
__global__ void __launch_bounds__(256, 2)
dec_gemm(const __half* __restrict__ a_h, const __half* __restrict__ b_h,
         const float* __restrict__ bias, float* __restrict__ out)
{
    __shared__ __align__(16) __half As[2][128 * DROW];
    __shared__ __align__(16) __half Bs[2][128 * DROW];

    const int tid  = threadIdx.x;
    const int lane = tid & 31;
    const int warp = tid >> 5;
    const int warpM = warp >> 2;
    const int warpN = warp & 3;
    const int bm = blockIdx.y * 128;
    const int bn = blockIdx.x * 128;

    const uint32_t sA[2] = { smem_u32(As[0]), smem_u32(As[1]) };
    const uint32_t sB[2] = { smem_u32(Bs[0]), smem_u32(Bs[1]) };

    float acc[4][4][4];
#pragma unroll
    for (int i = 0; i < 4; i++)
#pragma unroll
        for (int j = 0; j < 4; j++)
#pragma unroll
            for (int r = 0; r < 4; r++) acc[i][j][r] = 0.f;

    const int r0c = tid >> 2, c0c = tid & 3;
    const int r1c = (tid + 256) >> 2, c1c = tid & 3;

    auto issue = [&](int it, int buf) {
        const int k0 = it * 32;
        cp16(sA[buf] + (r0c * DROW + c0c * 8) * 2,
             a_h + (size_t)(bm + r0c) * H_DIM + k0 + c0c * 8);
        cp16(sA[buf] + (r1c * DROW + c1c * 8) * 2,
             a_h + (size_t)(bm + r1c) * H_DIM + k0 + c1c * 8);
        cp16(sB[buf] + (r0c * DROW + c0c * 8) * 2,
             b_h + (size_t)(bn + r0c) * H_DIM + k0 + c0c * 8);
        cp16(sB[buf] + (r1c * DROW + c1c * 8) * 2,
             b_h + (size_t)(bn + r1c) * H_DIM + k0 + c1c * 8);
    };

    issue(0, 0);
    CP_COMMIT();

    for (int it = 0; it < 32; it++) {
        const int buf = it & 1;
        if (it + 1 < 32) { issue(it + 1, buf ^ 1); CP_COMMIT(); CP_WAIT1(); }
        else             { CP_WAIT0(); }
        __syncthreads();

#pragma unroll
        for (int ks = 0; ks < 2; ks++) {
            uint32_t af[4][4];
#pragma unroll
            for (int mf = 0; mf < 4; mf++) {
                int row = warpM * 64 + mf * 16 + (lane & 15);
                int ch  = ks * 2 + (lane >> 4);
                ldsm_x4(af[mf], sA[buf] + (row * DROW + ch * 8) * 2);
            }
            uint32_t br[2][4];
#pragma unroll
            for (int g = 0; g < 2; g++) {
                int row = warpN * 32 + g * 16 + ((lane >> 4) << 3) + (lane & 7);
                int ch  = ks * 2 + ((lane >> 3) & 1);
                ldsm_x4(br[g], sB[buf] + (row * DROW + ch * 8) * 2);
            }
#pragma unroll
            for (int mf = 0; mf < 4; mf++)
#pragma unroll
                for (int g = 0; g < 2; g++) {
                    mma16816(acc[mf][g * 2],     af[mf], &br[g][0]);
                    mma16816(acc[mf][g * 2 + 1], af[mf], &br[g][2]);
                }
        }
        __syncthreads();
    }

#pragma unroll
    for (int mf = 0; mf < 4; mf++) {
        int rowA = bm + warpM * 64 + mf * 16 + (lane >> 2);
        int rowB = rowA + 8;
#pragma unroll
        for (int nf = 0; nf < 4; nf++) {
            int col = bn + warpN * 32 + nf * 8 + (lane & 3) * 2;
            float b0 = (col     < V_SZ) ? bias[col]     : 0.f;
            float b1 = (col + 1 < V_SZ) ? bias[col + 1] : 0.f;
            if (col < V_SZ)     out[(size_t)rowA * V_SZ + col]     = acc[mf][nf][0] + b0;
            if (col + 1 < V_SZ) out[(size_t)rowA * V_SZ + col + 1] = acc[mf][nf][1] + b1;
            if (col < V_SZ)     out[(size_t)rowB * V_SZ + col]     = acc[mf][nf][2] + b0;
            if (col + 1 < V_SZ) out[(size_t)rowB * V_SZ + col + 1] = acc[mf][nf][3] + b1;
        }
    }
}

// ---------------- launcher --------------------------------------------------
extern "C" void kernel_launch(void* const* d_in, const int* in_sizes, int n_in,
                              void* d_out, int out_size)
{
    const int*   tokens = (const int*)  d_in[0];
    const float* h0     = (const float*)d_in[1];
    const float* c0     = (const float*)d_in[2];
    const float* emb    = (const float*)d_in[3];
    const float* Wih    = (const float*)d_in[4];
    const float* Whh    = (const float*)d_in[5];
    const float* bih    = (const float*)d_in[6];
    const float* bhh    = (const float*)d_in[7];
    const float* Whh2   = (const float*)d_in[8];
    const float* bhh2   = (const float*)d_in[9];
    const float* Whm    = (const float*)d_in[10];
    const float* bhm    = (const float*)d_in[11];
    const float* decW   = (const float*)d_in[12];
    const float* decb   = (const float*)d_in[13];
    const int*   kp     = (const int*)  d_in[14];
    float* out = (float*)d_out;

    void *p_xW, *p_hs, *p_outb, *p_hm, *p_bar, *p_ah, *p_bh, *p_wh, *p_wl,
         *p_whh, *p_whl;
    cudaGetSymbolAddress(&p_xW,   g_xW);
    cudaGetSymbolAddress(&p_hs,   g_hs);
    cudaGetSymbolAddress(&p_outb, g_outbuf);
    cudaGetSymbolAddress(&p_hm,   g_hm);
    cudaGetSymbolAddress(&p_bar,  g_bar);
    cudaGetSymbolAddress(&p_ah,   g_a_h);
    cudaGetSymbolAddress(&p_bh,   g_b_h);
    cudaGetSymbolAddress(&p_wh,   g_wih_hi);
    cudaGetSymbolAddress(&p_wl,   g_wih_lo);
    cudaGetSymbolAddress(&p_whh,  g_whh_hi);
    cudaGetSymbolAddress(&p_whl,  g_whh_lo);
    float* xW   = (float*)p_xW;
    float* hs   = (float*)p_hs;
    float* ob   = (float*)p_outb;
    float* hm   = (float*)p_hm;
    unsigned int* bar = (unsigned int*)p_bar;
    __half* ah  = (__half*)p_ah;
    __half* bh  = (__half*)p_bh;
    __half* wh  = (__half*)p_wh;
    __half* wl  = (__half*)p_wl;
    __half* whh = (__half*)p_whh;
    __half* whl = (__half*)p_whl;

    cudaFuncSetAttribute(lstm_scan_mma,
                         cudaFuncAttributeMaxDynamicSharedMemorySize, SC_SMEM);

    const int M = S_LEN * B_SZ;   // 2048

    // 0) conversions: gather emb rows -> fp16; Wih -> hi/lo; Whh -> hi/lo; decW -> fp16
    conv_gather_k<<<M, 256>>>(emb, tokens, ah);
    split_w_k<<<(G4 * E_DIM / 4 + 255) / 256, 256>>>(Wih, wh, wl, G4 * E_DIM / 4);
    split_w_k<<<(G4 * H_DIM / 4 + 255) / 256, 256>>>(Whh, whh, whl, G4 * H_DIM / 4);
    conv_b_k<<<(V_PAD * H_DIM / 4 + 255) / 256, 256>>>(decW, bh);

    // 1) xW = a_h @ (Wih_hi+Wih_lo)^T + bih + bhh  (mma, 2-pass)
    xw_gemm<<<dim3(G4 / 128, M / 128), 256>>>(ah, wh, wl, bih, bhh, xW);

    // 2) hm = h0 @ Whm^T + bhm
    gemm_k<0><<<dim3(H_DIM / 128, 1), 256>>>(
        h0, Whm, hm, B_SZ, H_DIM, H_DIM, bhm, nullptr, nullptr);

    // 3) reset grid barrier
    cudaMemsetAsync(bar, 0, sizeof(unsigned int), 0);

    // 4) persistent tensor-core LSTM scan (one launch, 128 internal steps)
    lstm_scan_mma<<<128, 256, SC_SMEM>>>(h0, c0, whh, whl, xW, hs, bar);

    // 5) outputs = (s<k) ? hs : hs @ Whh2^T + bhh2 + hm
    gemm_k<2><<<dim3(H_DIM / 128, M / 128), 256>>>(
        hs, Whh2, ob, M, H_DIM, H_DIM, bhh2, hm, kp);

    // convert outputs -> fp16 (overwrites gathered emb — already consumed)
    conv_a_k<<<(M * H_DIM / 4 + 255) / 256, 256>>>(ob, ah, M * H_DIM / 4);

    // 6) decoded = outputs @ decW^T + decb  — mma.sync fp16 single-pass GEMM
    dec_gemm<<<dim3(V_PAD / 128, M / 128), 256>>>(ah, bh, decb, out);

    (void)in_sizes; (void)n_in; (void)out_size;
}

// round 14
// speedup vs baseline: 3.5174x; 1.2425x over previous
#include <cuda_runtime.h>
#include <cuda_bf16.h>
#include <cuda_fp16.h>
#include <cstdint>

// Problem dims (fixed by the dataset)
#define S_LEN 128
#define B_SZ  16
#define H_DIM 1024
#define E_DIM 1024
#define G4    4096
#define V_SZ  50257
#define V_PAD 50304          // 393 * 128

// ---------------- scratch (device globals; no allocation allowed) ----------
__device__ float g_xW [S_LEN * B_SZ * G4];       // plain row-major [m][4H]
__device__ float g_hs [S_LEN * B_SZ * H_DIM];
__device__ float g_outbuf[S_LEN * B_SZ * H_DIM];
__device__ float g_hm [B_SZ * H_DIM];
__device__ unsigned int g_bar;
__device__ __align__(256) __half g_a_h[S_LEN * B_SZ * H_DIM];  // gathered emb, then outputs
__device__ __align__(256) __half g_b_h[(size_t)V_PAD * H_DIM];
__device__ __align__(256) __half g_wih_hi[G4 * E_DIM];
__device__ __align__(256) __half g_wih_lo[G4 * E_DIM];
__device__ __align__(256) __half g_whh_hi[G4 * H_DIM];
__device__ __align__(256) __half g_whh_lo[G4 * H_DIM];
__device__ __align__(256) __half g_hh[(S_LEN + 1) * B_SZ * H_DIM]; // fp16 h per step

// ---------------- f32x2 helpers --------------------------------------------
__device__ __forceinline__ unsigned long long dup2(float x) {
    unsigned long long r; asm("mov.b64 %0, {%1, %1};" : "=l"(r) : "f"(x)); return r;
}
__device__ __forceinline__ unsigned long long pk2(float lo, float hi) {
    unsigned long long r; asm("mov.b64 %0, {%1, %2};" : "=l"(r) : "f"(lo), "f"(hi)); return r;
}
__device__ __forceinline__ void fma2(unsigned long long& d,
                                     unsigned long long a, unsigned long long b) {
    asm("fma.rn.f32x2 %0, %1, %2, %0;" : "+l"(d) : "l"(a), "l"(b));
}
__device__ __forceinline__ float2 up2(unsigned long long v) {
    float2 f; asm("mov.b64 {%0, %1}, %2;" : "=f"(f.x), "=f"(f.y) : "l"(v)); return f;
}
__device__ __forceinline__ float sigm(float x) { return 1.0f / (1.0f + expf(-x)); }

__device__ __forceinline__ uint32_t smem_u32(const void* p) {
    uint32_t a;
    asm("{ .reg .u64 t; cvta.to.shared.u64 t, %1; cvt.u32.u64 %0, t; }"
        : "=r"(a) : "l"(p));
    return a;
}
__device__ __forceinline__ unsigned int ld_acq(const unsigned int* p) {
    unsigned int v;
    asm volatile("ld.acquire.gpu.u32 %0, [%1];" : "=r"(v) : "l"(p) : "memory");
    return v;
}
__device__ __forceinline__ void red_rel_add(unsigned int* p, unsigned int v) {
    asm volatile("red.release.gpu.global.add.u32 [%0], %1;" :: "l"(p), "r"(v) : "memory");
}

// ---------------- mma.sync / ldmatrix / cp.async helpers (non-'a' PTX) ------
__device__ __forceinline__ void ldsm_x4(uint32_t* r, uint32_t addr) {
    asm volatile("ldmatrix.sync.aligned.m8n8.x4.shared.b16 {%0,%1,%2,%3}, [%4];"
                 : "=r"(r[0]), "=r"(r[1]), "=r"(r[2]), "=r"(r[3]) : "r"(addr));
}
__device__ __forceinline__ void mma16816(float* c, const uint32_t* a, const uint32_t* b) {
    asm volatile(
        "mma.sync.aligned.m16n8k16.row.col.f32.f16.f16.f32 "
        "{%0,%1,%2,%3}, {%4,%5,%6,%7}, {%8,%9}, {%0,%1,%2,%3};"
        : "+f"(c[0]), "+f"(c[1]), "+f"(c[2]), "+f"(c[3])
        : "r"(a[0]), "r"(a[1]), "r"(a[2]), "r"(a[3]), "r"(b[0]), "r"(b[1]));
}
__device__ __forceinline__ void cp16(uint32_t dst, const void* src) {
    asm volatile("cp.async.cg.shared.global [%0], [%1], 16;" :: "r"(dst), "l"(src));
}
#define CP_COMMIT() asm volatile("cp.async.commit_group;" ::: "memory")
#define CP_WAIT1()  asm volatile("cp.async.wait_group 1;" ::: "memory")
#define CP_WAIT0()  asm volatile("cp.async.wait_group 0;" ::: "memory")

// ---------------- generic tiled fp32 GEMM (steps 2,5) -----------------------
template <int MODE>
__global__ void __launch_bounds__(256)
gemm_k(const float* __restrict__ A, const float* __restrict__ Bm,
       float* __restrict__ C, int M, int N, int K,
       const float* __restrict__ bias0,
       const float* __restrict__ hmv, const int* __restrict__ kptr)
{
    constexpr int BM = 128, BN = 128, BK = 16;
    __shared__ float As[BK][BM + 4];
    __shared__ float Bs[BK][BN + 4];

    const int tid = threadIdx.x;
    const int bm = blockIdx.y * BM;
    const int bn = blockIdx.x * BN;
    const int tx = tid & 15;
    const int ty = tid >> 4;
    const int lr = tid >> 2;
    const int lk = (tid & 3) * 4;

    unsigned long long acc[8][4];
#pragma unroll
    for (int i = 0; i < 8; i++)
#pragma unroll
        for (int j = 0; j < 4; j++) acc[i][j] = 0ull;

    const int m0 = bm + lr, m1 = bm + lr + 64;
    const float* arow0 = (m0 < M) ? A + (size_t)m0 * K : nullptr;
    const float* arow1 = (m1 < M) ? A + (size_t)m1 * K : nullptr;
    const int n0 = bn + lr, n1 = bn + lr + 64;
    const float* brow0 = (n0 < N) ? Bm + (size_t)n0 * K : nullptr;
    const float* brow1 = (n1 < N) ? Bm + (size_t)n1 * K : nullptr;

    const float4 fz = make_float4(0.f, 0.f, 0.f, 0.f);

    for (int k0 = 0; k0 < K; k0 += BK) {
        float4 a0 = arow0 ? *(const float4*)(arow0 + k0 + lk) : fz;
        float4 a1 = arow1 ? *(const float4*)(arow1 + k0 + lk) : fz;
        float4 b0 = brow0 ? *(const float4*)(brow0 + k0 + lk) : fz;
        float4 b1 = brow1 ? *(const float4*)(brow1 + k0 + lk) : fz;

        __syncthreads();
        As[lk + 0][lr] = a0.x;  As[lk + 1][lr] = a0.y;
        As[lk + 2][lr] = a0.z;  As[lk + 3][lr] = a0.w;
        As[lk + 0][lr + 64] = a1.x;  As[lk + 1][lr + 64] = a1.y;
        As[lk + 2][lr + 64] = a1.z;  As[lk + 3][lr + 64] = a1.w;
        Bs[lk + 0][lr] = b0.x;  Bs[lk + 1][lr] = b0.y;
        Bs[lk + 2][lr] = b0.z;  Bs[lk + 3][lr] = b0.w;
        Bs[lk + 0][lr + 64] = b1.x;  Bs[lk + 1][lr + 64] = b1.y;
        Bs[lk + 2][lr + 64] = b1.z;  Bs[lk + 3][lr + 64] = b1.w;
        __syncthreads();

#pragma unroll
        for (int kk = 0; kk < BK; kk++) {
            float4 av0 = *(const float4*)&As[kk][ty * 8];
            float4 av1 = *(const float4*)&As[kk][ty * 8 + 4];
            float4 bv0 = *(const float4*)&Bs[kk][tx * 8];
            float4 bv1 = *(const float4*)&Bs[kk][tx * 8 + 4];
            unsigned long long a2[8] = {dup2(av0.x), dup2(av0.y), dup2(av0.z), dup2(av0.w),
                                        dup2(av1.x), dup2(av1.y), dup2(av1.z), dup2(av1.w)};
            unsigned long long b2[4] = {pk2(bv0.x, bv0.y), pk2(bv0.z, bv0.w),
                                        pk2(bv1.x, bv1.y), pk2(bv1.z, bv1.w)};
#pragma unroll
            for (int i = 0; i < 8; i++)
#pragma unroll
                for (int j = 0; j < 4; j++) fma2(acc[i][j], a2[i], b2[j]);
        }
    }

    const int kval = (MODE == 2) ? *kptr : 0;

#pragma unroll
    for (int i = 0; i < 8; i++) {
        int m = bm + ty * 8 + i;
        if (m >= M) continue;
        size_t crow = (size_t)m * N;
        int srow = m >> 4;
        int b    = m & 15;
        bool cp = (MODE == 2) && (srow < kval);
#pragma unroll
        for (int j = 0; j < 4; j++) {
            float2 v = up2(acc[i][j]);
            int n = bn + tx * 8 + 2 * j;
            float vals[2] = {v.x, v.y};
#pragma unroll
            for (int u = 0; u < 2; u++) {
                int nn = n + u;
                if (nn >= N) continue;
                float r;
                if (MODE == 0) r = vals[u] + bias0[nn];
                else           r = cp ? A[(size_t)m * K + nn]
                                      : vals[u] + bias0[nn] + hmv[b * H_DIM + nn];
                C[crow + nn] = r;
            }
        }
    }
}

// ---------------- persistent LSTM scan — tensor core, 2-pass, cp.async ------
// 128 blocks x 256 threads. Block owns 8 hidden cols x 4 gates = 32 gate cols.
// Whh pre-split to fp16 hi/lo, staged once. Per step: A-tile (fp16 h, produced
// by the PREVIOUS step's activation threads) staged via cp.async (no ALU);
// 2-pass mma: Ahi*Whi + Ahi*Wlo (h single-rounded fp16, calibrated ~2e-4).
#define SC_ROW 1032
#define SC_W_HALFS (32 * SC_ROW)              // 33024
#define SC_A_HALFS (16 * SC_ROW)              // 16512
#define SC_PF_STRIDE 34
#define SC_PF_FLOATS (8 * 16 * SC_PF_STRIDE)  // 4352
#define SC_SMEM ((2 * SC_W_HALFS + SC_A_HALFS) * 2 + SC_PF_FLOATS * 4) // 182528

__global__ void __launch_bounds__(256, 1)
lstm_scan_mma(const float* __restrict__ c0,
              const __half* __restrict__ whh_hi,
              const __half* __restrict__ whh_lo,
              const float* __restrict__ xW,   // [m][4H] row-major
              float* __restrict__ hs,
              __half* __restrict__ hh,        // [(t)][16][1024] fp16 h chain
              unsigned int* __restrict__ bar)
{
    extern __shared__ __half shh[];
    __half* sWhi = shh;
    __half* sWlo = shh + SC_W_HALFS;
    __half* sA   = shh + 2 * SC_W_HALFS;
    float*  pf   = (float*)(shh + 2 * SC_W_HALFS + SC_A_HALFS);

    const int tid  = threadIdx.x;
    const int lane = tid & 31;
    const int w    = tid >> 5;
    const int hb   = blockIdx.x * 8;

    // ---- preload W hi/lo slices (once): 32 rows x 1024 halves each ----
#pragma unroll
    for (int it = 0; it < 16; it++) {
        int idx = tid + it * 256;            // 0..4095 chunks of 8 halves
        int ll = idx >> 7, c8 = idx & 127;
        int j  = (ll >> 3) * H_DIM + hb + (ll & 7);
        *(uint4*)(sWhi + ll * SC_ROW + c8 * 8) =
            *(const uint4*)(whh_hi + (size_t)j * H_DIM + c8 * 8);
        *(uint4*)(sWlo + ll * SC_ROW + c8 * 8) =
            *(const uint4*)(whh_lo + (size_t)j * H_DIM + c8 * 8);
    }

    // ---- cell state in registers (threads 0..127) ----
    const int a_b = tid & 15, a_hil = (tid >> 4) & 7;
    float cloc = 0.f;
    if (tid < 128) cloc = c0[a_b * H_DIM + hb + a_hil];

    const int kc = w * 16;                   // warp's K base in 8-half chunks

    for (int t = 0; t < S_LEN; t++) {
        // ---- prefetch xW gate biases for this thread's output ----
        float xv0 = 0.f, xv1 = 0.f, xv2 = 0.f, xv3 = 0.f;
        if (tid < 128) {
            const float* xp = xW + ((size_t)t * 16 + a_b) * G4 + hb + a_hil;
            xv0 = __ldg(xp);        xv1 = __ldg(xp + 1024);
            xv2 = __ldg(xp + 2048); xv3 = __ldg(xp + 3072);
        }

        // ---- stage fp16 h A-tile via cp.async (16 rows x 1024 halves) ----
        {
            const __half* src = hh + (size_t)t * B_SZ * H_DIM;
#pragma unroll
            for (int i = 0; i < 8; i++) {
                int idx = tid + i * 256;      // 0..2047 chunks of 8 halves
                int row = idx >> 7, c8 = idx & 127;
                cp16(smem_u32(sA + row * SC_ROW + c8 * 8),
                     src + row * H_DIM + c8 * 8);
            }
        }
        CP_COMMIT();
        CP_WAIT0();
        __syncthreads();

        // ---- mma: M=16, N=32, K=128 per warp, 2-pass (Whi then Wlo) ----
        float acc[4][4];
#pragma unroll
        for (int nf = 0; nf < 4; nf++)
#pragma unroll
            for (int r = 0; r < 4; r++) acc[nf][r] = 0.f;

#pragma unroll
        for (int pass = 0; pass < 2; pass++) {
            const __half* Wsrc = pass ? sWlo : sWhi;
#pragma unroll
            for (int ks = 0; ks < 8; ks++) {
                uint32_t af[4];
                ldsm_x4(af, smem_u32(sA + (lane & 15) * SC_ROW
                                     + (kc + ks * 2 + (lane >> 4)) * 8));
                uint32_t br[2][4];
#pragma unroll
                for (int g = 0; g < 2; g++) {
                    int row = g * 16 + ((lane >> 4) << 3) + (lane & 7);
                    ldsm_x4(br[g], smem_u32(Wsrc + row * SC_ROW
                                            + (kc + ks * 2 + ((lane >> 3) & 1)) * 8));
                }
#pragma unroll
                for (int g = 0; g < 2; g++) {
                    mma16816(acc[g * 2],     af, &br[g][0]);
                    mma16816(acc[g * 2 + 1], af, &br[g][2]);
                }
            }
        }

        // ---- store partials: pf[w][m][n], stride 34 ----
        {
            float* pw = pf + w * 16 * SC_PF_STRIDE;
            int r0 = lane >> 2;
            int cb = (lane & 3) * 2;
#pragma unroll
            for (int nf = 0; nf < 4; nf++) {
                int c = nf * 8 + cb;
                *(float2*)(pw + r0 * SC_PF_STRIDE + c) =
                    make_float2(acc[nf][0], acc[nf][1]);
                *(float2*)(pw + (r0 + 8) * SC_PF_STRIDE + c) =
                    make_float2(acc[nf][2], acc[nf][3]);
            }
        }
        __syncthreads();

        // ---- reduce over 8 warps + fused activation (threads 0..127) ----
        if (tid < 128) {
            float gI = xv0, gF = xv1, gG = xv2, gO = xv3;
            const float* pw = pf + a_b * SC_PF_STRIDE + a_hil;
#pragma unroll
            for (int ww = 0; ww < 8; ww++) {
                const float* p = pw + ww * 16 * SC_PF_STRIDE;
                gI += p[0]; gF += p[8]; gG += p[16]; gO += p[24];
            }
            float cn = sigm(gF) * cloc + sigm(gI) * tanhf(gG);
            cloc = cn;
            float hv = sigm(gO) * tanhf(cn);
            hs[(size_t)t * B_SZ * H_DIM + a_b * H_DIM + hb + a_hil] = hv;
            hh[(size_t)(t + 1) * B_SZ * H_DIM + a_b * H_DIM + hb + a_hil] =
                __float2half_rn(hv);
        }
        __syncthreads();

        // ---- grid barrier: release-add + acquire-poll ----
        if (tid == 0) {
            red_rel_add(bar, 1u);
            const unsigned int target = 128u * (unsigned)(t + 1);
            while (ld_acq(bar) < target) { }
        }
        __syncthreads();
    }
}

// ---------------- fp16 convert / split kernels -------------------------------
__global__ void __launch_bounds__(256)
conv_a_k(const float* __restrict__ src, __half* __restrict__ dst, int n4)
{
    int i = blockIdx.x * blockDim.x + threadIdx.x;
    if (i >= n4) return;
    float4 v = ((const float4*)src)[i];
    __half h[4] = { __float2half_rn(v.x), __float2half_rn(v.y),
                    __float2half_rn(v.z), __float2half_rn(v.w) };
    ((__half2*)dst)[2 * i]     = __halves2half2(h[0], h[1]);
    ((__half2*)dst)[2 * i + 1] = __halves2half2(h[2], h[3]);
}

// gather rows of emb via tokens and convert to fp16 (one block per row)
__global__ void __launch_bounds__(256)
conv_gather_k(const float* __restrict__ emb, const int* __restrict__ tokens,
              __half* __restrict__ dst)
{
    const int m = blockIdx.x;
    const float4* src = (const float4*)(emb + (size_t)tokens[m] * E_DIM);
    float4 v = src[threadIdx.x];
    __half2 h0 = __halves2half2(__float2half_rn(v.x), __float2half_rn(v.y));
    __half2 h1 = __halves2half2(__float2half_rn(v.z), __float2half_rn(v.w));
    __half2* d = (__half2*)(dst + (size_t)m * E_DIM);
    d[threadIdx.x * 2]     = h0;
    d[threadIdx.x * 2 + 1] = h1;
}

__global__ void __launch_bounds__(256)
conv_b_k(const float* __restrict__ src, __half* __restrict__ out)
{
    int i = blockIdx.x * blockDim.x + threadIdx.x;
    if (i >= V_PAD * (H_DIM / 4)) return;
    int row = i >> 8;
    float4 v = make_float4(0.f, 0.f, 0.f, 0.f);
    if (row < V_SZ) v = ((const float4*)src)[i];
    __half h[4] = { __float2half_rn(v.x), __float2half_rn(v.y),
                    __float2half_rn(v.z), __float2half_rn(v.w) };
    ((__half2*)out)[2 * i]     = __halves2half2(h[0], h[1]);
    ((__half2*)out)[2 * i + 1] = __halves2half2(h[2], h[3]);
}

__global__ void __launch_bounds__(256)
split_w_k(const float* __restrict__ src, __half* __restrict__ hi,
          __half* __restrict__ lo, int n4)
{
    int i = blockIdx.x * blockDim.x + threadIdx.x;
    if (i >= n4) return;
    float4 v = ((const float4*)src)[i];
    float xs[4] = {v.x, v.y, v.z, v.w};
    __half h[4], l[4];
#pragma unroll
    for (int j = 0; j < 4; j++) {
        h[j] = __float2half_rn(xs[j]);
        l[j] = __float2half_rn(xs[j] - __half2float(h[j]));
    }
    ((__half2*)hi)[2 * i]     = __halves2half2(h[0], h[1]);
    ((__half2*)hi)[2 * i + 1] = __halves2half2(h[2], h[3]);
    ((__half2*)lo)[2 * i]     = __halves2half2(l[0], l[1]);
    ((__half2*)lo)[2 * i + 1] = __halves2half2(l[2], l[3]);
}

// ---------------- xW GEMM: fp16 mma, 2-pass (A pre-gathered) -----------------
#define DROW 40

__global__ void __launch_bounds__(256, 2)
xw_gemm(const __half* __restrict__ a_h,
        const __half* __restrict__ w_hi, const __half* __restrict__ w_lo,
        const float* __restrict__ bih, const float* __restrict__ bhh,
        float* __restrict__ out)
{
    __shared__ __align__(16) __half As[2][128 * DROW];
    __shared__ __align__(16) __half Bs[2][128 * DROW];

    const int tid  = threadIdx.x;
    const int lane = tid & 31;
    const int warp = tid >> 5;
    const int warpM = warp >> 2;
    const int warpN = warp & 3;
    const int bm = blockIdx.y * 128;
    const int bn = blockIdx.x * 128;

    const uint32_t sA[2] = { smem_u32(As[0]), smem_u32(As[1]) };
    const uint32_t sB[2] = { smem_u32(Bs[0]), smem_u32(Bs[1]) };

    float acc[4][4][4];
#pragma unroll
    for (int i = 0; i < 4; i++)
#pragma unroll
        for (int j = 0; j < 4; j++)
#pragma unroll
            for (int r = 0; r < 4; r++) acc[i][j][r] = 0.f;

    const int r0c = tid >> 2, c0c = tid & 3;
    const int r1c = r0c + 64;

    auto issue = [&](int it, int buf) {
        const int p  = it >> 5;
        const int k0 = (it & 31) * 32;
        const __half* Bp = p ? w_lo : w_hi;
        cp16(sA[buf] + (r0c * DROW + c0c * 8) * 2,
             a_h + (size_t)(bm + r0c) * E_DIM + k0 + c0c * 8);
        cp16(sA[buf] + (r1c * DROW + c0c * 8) * 2,
             a_h + (size_t)(bm + r1c) * E_DIM + k0 + c0c * 8);
        cp16(sB[buf] + (r0c * DROW + c0c * 8) * 2,
             Bp + (size_t)(bn + r0c) * E_DIM + k0 + c0c * 8);
        cp16(sB[buf] + (r1c * DROW + c0c * 8) * 2,
             Bp + (size_t)(bn + r1c) * E_DIM + k0 + c0c * 8);
    };

    issue(0, 0);
    CP_COMMIT();

    for (int it = 0; it < 64; it++) {
        const int buf = it & 1;
        if (it + 1 < 64) { issue(it + 1, buf ^ 1); CP_COMMIT(); CP_WAIT1(); }
        else             { CP_WAIT0(); }
        __syncthreads();

#pragma unroll
        for (int ks = 0; ks < 2; ks++) {
            uint32_t af[4][4];
#pragma unroll
            for (int mf = 0; mf < 4; mf++) {
                int row = warpM * 64 + mf * 16 + (lane & 15);
                int ch  = ks * 2 + (lane >> 4);
                ldsm_x4(af[mf], sA[buf] + (row * DROW + ch * 8) * 2);
            }
            uint32_t br[2][4];
#pragma unroll
            for (int g = 0; g < 2; g++) {
                int row = warpN * 32 + g * 16 + ((lane >> 4) << 3) + (lane & 7);
                int ch  = ks * 2 + ((lane >> 3) & 1);
                ldsm_x4(br[g], sB[buf] + (row * DROW + ch * 8) * 2);
            }
#pragma unroll
            for (int mf = 0; mf < 4; mf++)
#pragma unroll
                for (int g = 0; g < 2; g++) {
                    mma16816(acc[mf][g * 2],     af[mf], &br[g][0]);
                    mma16816(acc[mf][g * 2 + 1], af[mf], &br[g][2]);
                }
        }
        __syncthreads();
    }

#pragma unroll
    for (int mf = 0; mf < 4; mf++) {
        int rowA = bm + warpM * 64 + mf * 16 + (lane >> 2);
        int rowB = rowA + 8;
#pragma unroll
        for (int nf = 0; nf < 4; nf++) {
            int col = bn + warpN * 32 + nf * 8 + (lane & 3) * 2;
            float b0 = bih[col]     + bhh[col];
            float b1 = bih[col + 1] + bhh[col + 1];
            out[(size_t)rowA * G4 + col]     = acc[mf][nf][0] + b0;
            out[(size_t)rowA * G4 + col + 1] = acc[mf][nf][1] + b1;
            out[(size_t)rowB * G4 + col]     = acc[mf][nf][2] + b0;
            out[(size_t)rowB * G4 + col + 1] = acc[mf][nf][3] + b1;
        }
    }
}

// ---------------- mma.sync decoder GEMM (fp16, single pass, 2 CTAs/SM) ------
__global__ void __launch_bounds__(256, 2)
dec_gemm(const __half* __restrict__ a_h, const __half* __restrict__ b_h,
         const float* __restrict__ bias, float* __restrict__ out)
{
    __shared__ __align__(16) __half As[2][128 * DROW];
    __shared__ __align__(16) __half Bs[2][128 * DROW];

    const int tid  = threadIdx.x;
    const int lane = tid & 31;
    const int warp = tid >> 5;
    const int warpM = warp >> 2;
    const int warpN = warp & 3;
    const int bm = blockIdx.y * 128;
    const int bn = blockIdx.x * 128;

    const uint32_t sA[2] = { smem_u32(As[0]), smem_u32(As[1]) };
    const uint32_t sB[2] = { smem_u32(Bs[0]), smem_u32(Bs[1]) };

    float acc[4][4][4];
#pragma unroll
    for (int i = 0; i < 4; i++)
#pragma unroll
        for (int j = 0; j < 4; j++)
#pragma unroll
            for (int r = 0; r < 4; r++) acc[i][j][r] = 0.f;

    const int r0c = tid >> 2, c0c = tid & 3;
    const int r1c = (tid + 256) >> 2, c1c = tid & 3;

    auto issue = [&](int it, int buf) {
        const int k0 = it * 32;
        cp16(sA[buf] + (r0c * DROW + c0c * 8) * 2,
             a_h + (size_t)(bm + r0c) * H_DIM + k0 + c0c * 8);
        cp16(sA[buf] + (r1c * DROW + c1c * 8) * 2,
             a_h + (size_t)(bm + r1c) * H_DIM + k0 + c1c * 8);
        cp16(sB[buf] + (r0c * DROW + c0c * 8) * 2,
             b_h + (size_t)(bn + r0c) * H_DIM + k0 + c0c * 8);
        cp16(sB[buf] + (r1c * DROW + c1c * 8) * 2,
             b_h + (size_t)(bn + r1c) * H_DIM + k0 + c1c * 8);
    };

    issue(0, 0);
    CP_COMMIT();

    for (int it = 0; it < 32; it++) {
        const int buf = it & 1;
        if (it + 1 < 32) { issue(it + 1, buf ^ 1); CP_COMMIT(); CP_WAIT1(); }
        else             { CP_WAIT0(); }
        __syncthreads();

#pragma unroll
        for (int ks = 0; ks < 2; ks++) {
            uint32_t af[4][4];
#pragma unroll
            for (int mf = 0; mf < 4; mf++) {
                int row = warpM * 64 + mf * 16 + (lane & 15);
                int ch  = ks * 2 + (lane >> 4);
                ldsm_x4(af[mf], sA[buf] + (row * DROW + ch * 8) * 2);
            }
            uint32_t br[2][4];
#pragma unroll
            for (int g = 0; g < 2; g++) {
                int row = warpN * 32 + g * 16 + ((lane >> 4) << 3) + (lane & 7);
                int ch  = ks * 2 + ((lane >> 3) & 1);
                ldsm_x4(br[g], sB[buf] + (row * DROW + ch * 8) * 2);
            }
#pragma unroll
            for (int mf = 0; mf < 4; mf++)
#pragma unroll
                for (int g = 0; g < 2; g++) {
                    mma16816(acc[mf][g * 2],     af[mf], &br[g][0]);
                    mma16816(acc[mf][g * 2 + 1], af[mf], &br[g][2]);
                }
        }
        __syncthreads();
    }

#pragma unroll
    for (int mf = 0; mf < 4; mf++) {
        int rowA = bm + warpM * 64 + mf * 16 + (lane >> 2);
        int rowB = rowA + 8;
#pragma unroll
        for (int nf = 0; nf < 4; nf++) {
            int col = bn + warpN * 32 + nf * 8 + (lane & 3) * 2;
            float b0 = (col     < V_SZ) ? bias[col]     : 0.f;
            float b1 = (col + 1 < V_SZ) ? bias[col + 1] : 0.f;
            if (col < V_SZ)     out[(size_t)rowA * V_SZ + col]     = acc[mf][nf][0] + b0;
            if (col + 1 < V_SZ) out[(size_t)rowA * V_SZ + col + 1] = acc[mf][nf][1] + b1;
            if (col < V_SZ)     out[(size_t)rowB * V_SZ + col]     = acc[mf][nf][2] + b0;
            if (col + 1 < V_SZ) out[(size_t)rowB * V_SZ + col + 1] = acc[mf][nf][3] + b1;
        }
    }
}

// ---------------- launcher --------------------------------------------------
extern "C" void kernel_launch(void* const* d_in, const int* in_sizes, int n_in,
                              void* d_out, int out_size)
{
    const int*   tokens = (const int*)  d_in[0];
    const float* h0     = (const float*)d_in[1];
    const float* c0     = (const float*)d_in[2];
    const float* emb    = (const float*)d_in[3];
    const float* Wih    = (const float*)d_in[4];
    const float* Whh    = (const float*)d_in[5];
    const float* bih    = (const float*)d_in[6];
    const float* bhh    = (const float*)d_in[7];
    const float* Whh2   = (const float*)d_in[8];
    const float* bhh2   = (const float*)d_in[9];
    const float* Whm    = (const float*)d_in[10];
    const float* bhm    = (const float*)d_in[11];
    const float* decW   = (const float*)d_in[12];
    const float* decb   = (const float*)d_in[13];
    const int*   kp     = (const int*)  d_in[14];
    float* out = (float*)d_out;

    void *p_xW, *p_hs, *p_outb, *p_hm, *p_bar, *p_ah, *p_bh, *p_wh, *p_wl,
         *p_whh, *p_whl, *p_hh;
    cudaGetSymbolAddress(&p_xW,   g_xW);
    cudaGetSymbolAddress(&p_hs,   g_hs);
    cudaGetSymbolAddress(&p_outb, g_outbuf);
    cudaGetSymbolAddress(&p_hm,   g_hm);
    cudaGetSymbolAddress(&p_bar,  g_bar);
    cudaGetSymbolAddress(&p_ah,   g_a_h);
    cudaGetSymbolAddress(&p_bh,   g_b_h);
    cudaGetSymbolAddress(&p_wh,   g_wih_hi);
    cudaGetSymbolAddress(&p_wl,   g_wih_lo);
    cudaGetSymbolAddress(&p_whh,  g_whh_hi);
    cudaGetSymbolAddress(&p_whl,  g_whh_lo);
    cudaGetSymbolAddress(&p_hh,   g_hh);
    float* xW   = (float*)p_xW;
    float* hs   = (float*)p_hs;
    float* ob   = (float*)p_outb;
    float* hm   = (float*)p_hm;
    unsigned int* bar = (unsigned int*)p_bar;
    __half* ah  = (__half*)p_ah;
    __half* bh  = (__half*)p_bh;
    __half* wh  = (__half*)p_wh;
    __half* wl  = (__half*)p_wl;
    __half* whh = (__half*)p_whh;
    __half* whl = (__half*)p_whl;
    __half* hh  = (__half*)p_hh;

    cudaFuncSetAttribute(lstm_scan_mma,
                         cudaFuncAttributeMaxDynamicSharedMemorySize, SC_SMEM);

    const int M = S_LEN * B_SZ;   // 2048

    // 0) conversions: gather emb rows -> fp16; Wih -> hi/lo; Whh -> hi/lo;
    //    decW -> fp16; h0 -> fp16 chain slot 0
    conv_gather_k<<<M, 256>>>(emb, tokens, ah);
    split_w_k<<<(G4 * E_DIM / 4 + 255) / 256, 256>>>(Wih, wh, wl, G4 * E_DIM / 4);
    split_w_k<<<(G4 * H_DIM / 4 + 255) / 256, 256>>>(Whh, whh, whl, G4 * H_DIM / 4);
    conv_b_k<<<(V_PAD * H_DIM / 4 + 255) / 256, 256>>>(decW, bh);
    conv_a_k<<<(B_SZ * H_DIM / 4 + 255) / 256, 256>>>(h0, hh, B_SZ * H_DIM / 4);

    // 1) xW = a_h @ (Wih_hi+Wih_lo)^T + bih + bhh  (mma, 2-pass)
    xw_gemm<<<dim3(G4 / 128, M / 128), 256>>>(ah, wh, wl, bih, bhh, xW);

    // 2) hm = h0 @ Whm^T + bhm
    gemm_k<0><<<dim3(H_DIM / 128, 1), 256>>>(
        h0, Whm, hm, B_SZ, H_DIM, H_DIM, bhm, nullptr, nullptr);

    // 3) reset grid barrier
    cudaMemsetAsync(bar, 0, sizeof(unsigned int), 0);

    // 4) persistent tensor-core LSTM scan (one launch, 128 internal steps)
    lstm_scan_mma<<<128, 256, SC_SMEM>>>(c0, whh, whl, xW, hs, hh, bar);

    // 5) outputs = (s<k) ? hs : hs @ Whh2^T + bhh2 + hm
    gemm_k<2><<<dim3(H_DIM / 128, M / 128), 256>>>(
        hs, Whh2, ob, M, H_DIM, H_DIM, bhh2, hm, kp);

    // convert outputs -> fp16 (overwrites gathered emb — already consumed)
    conv_a_k<<<(M * H_DIM / 4 + 255) / 256, 256>>>(ob, ah, M * H_DIM / 4);

    // 6) decoded = outputs @ decW^T + decb  — mma.sync fp16 single-pass GEMM
    dec_gemm<<<dim3(V_PAD / 128, M / 128), 256>>>(ah, bh, decb, out);

    (void)in_sizes; (void)n_in; (void)out_size;
}

// round 15
// speedup vs baseline: 3.7311x; 1.0608x over previous
#include <cuda_runtime.h>
#include <cuda_bf16.h>
#include <cuda_fp16.h>
#include <cstdint>

// Problem dims (fixed by the dataset)
#define S_LEN 128
#define B_SZ  16
#define H_DIM 1024
#define E_DIM 1024
#define G4    4096
#define V_SZ  50257
#define V_PAD 50304          // 393 * 128

// ---------------- scratch (device globals; no allocation allowed) ----------
__device__ float g_xW [S_LEN * B_SZ * G4];       // plain row-major [m][4H]
__device__ float g_hs [S_LEN * B_SZ * H_DIM];
__device__ float g_hm [B_SZ * H_DIM];
__device__ unsigned int g_bar;
__device__ __align__(256) __half g_a_h[S_LEN * B_SZ * H_DIM];  // gathered emb, then fp16 outputs
__device__ __align__(256) __half g_b_h[(size_t)V_PAD * H_DIM];
__device__ __align__(256) __half g_wih_hi[G4 * E_DIM];
__device__ __align__(256) __half g_wih_lo[G4 * E_DIM];
__device__ __align__(256) __half g_whh_hi[G4 * H_DIM];
__device__ __align__(256) __half g_whh_lo[G4 * H_DIM];
__device__ __align__(256) __half g_w2_hi[H_DIM * H_DIM];
__device__ __align__(256) __half g_w2_lo[H_DIM * H_DIM];
__device__ __align__(256) __half g_hh[(S_LEN + 1) * B_SZ * H_DIM]; // fp16 h per step

// ---------------- f32x2 helpers --------------------------------------------
__device__ __forceinline__ unsigned long long dup2(float x) {
    unsigned long long r; asm("mov.b64 %0, {%1, %1};" : "=l"(r) : "f"(x)); return r;
}
__device__ __forceinline__ unsigned long long pk2(float lo, float hi) {
    unsigned long long r; asm("mov.b64 %0, {%1, %2};" : "=l"(r) : "f"(lo), "f"(hi)); return r;
}
__device__ __forceinline__ void fma2(unsigned long long& d,
                                     unsigned long long a, unsigned long long b) {
    asm("fma.rn.f32x2 %0, %1, %2, %0;" : "+l"(d) : "l"(a), "l"(b));
}
__device__ __forceinline__ float2 up2(unsigned long long v) {
    float2 f; asm("mov.b64 {%0, %1}, %2;" : "=f"(f.x), "=f"(f.y) : "l"(v)); return f;
}
__device__ __forceinline__ float sigm(float x) { return 1.0f / (1.0f + expf(-x)); }

__device__ __forceinline__ uint32_t smem_u32(const void* p) {
    uint32_t a;
    asm("{ .reg .u64 t; cvta.to.shared.u64 t, %1; cvt.u32.u64 %0, t; }"
        : "=r"(a) : "l"(p));
    return a;
}
__device__ __forceinline__ unsigned int ld_acq(const unsigned int* p) {
    unsigned int v;
    asm volatile("ld.acquire.gpu.u32 %0, [%1];" : "=r"(v) : "l"(p) : "memory");
    return v;
}
__device__ __forceinline__ void red_rel_add(unsigned int* p, unsigned int v) {
    asm volatile("red.release.gpu.global.add.u32 [%0], %1;" :: "l"(p), "r"(v) : "memory");
}

// ---------------- mma.sync / ldmatrix / cp.async helpers (non-'a' PTX) ------
__device__ __forceinline__ void ldsm_x4(uint32_t* r, uint32_t addr) {
    asm volatile("ldmatrix.sync.aligned.m8n8.x4.shared.b16 {%0,%1,%2,%3}, [%4];"
                 : "=r"(r[0]), "=r"(r[1]), "=r"(r[2]), "=r"(r[3]) : "r"(addr));
}
__device__ __forceinline__ void mma16816(float* c, const uint32_t* a, const uint32_t* b) {
    asm volatile(
        "mma.sync.aligned.m16n8k16.row.col.f32.f16.f16.f32 "
        "{%0,%1,%2,%3}, {%4,%5,%6,%7}, {%8,%9}, {%0,%1,%2,%3};"
        : "+f"(c[0]), "+f"(c[1]), "+f"(c[2]), "+f"(c[3])
        : "r"(a[0]), "r"(a[1]), "r"(a[2]), "r"(a[3]), "r"(b[0]), "r"(b[1]));
}
__device__ __forceinline__ void cp16(uint32_t dst, const void* src) {
    asm volatile("cp.async.cg.shared.global [%0], [%1], 16;" :: "r"(dst), "l"(src));
}
#define CP_COMMIT() asm volatile("cp.async.commit_group;" ::: "memory")
#define CP_WAIT1()  asm volatile("cp.async.wait_group 1;" ::: "memory")
#define CP_WAIT0()  asm volatile("cp.async.wait_group 0;" ::: "memory")

// ---------------- generic tiled fp32 GEMM (step 2 only) ---------------------
__global__ void __launch_bounds__(256)
gemm_k(const float* __restrict__ A, const float* __restrict__ Bm,
       float* __restrict__ C, int M, int N, int K,
       const float* __restrict__ bias0)
{
    constexpr int BM = 128, BN = 128, BK = 16;
    __shared__ float As[BK][BM + 4];
    __shared__ float Bs[BK][BN + 4];

    const int tid = threadIdx.x;
    const int bm = blockIdx.y * BM;
    const int bn = blockIdx.x * BN;
    const int tx = tid & 15;
    const int ty = tid >> 4;
    const int lr = tid >> 2;
    const int lk = (tid & 3) * 4;

    unsigned long long acc[8][4];
#pragma unroll
    for (int i = 0; i < 8; i++)
#pragma unroll
        for (int j = 0; j < 4; j++) acc[i][j] = 0ull;

    const int m0 = bm + lr, m1 = bm + lr + 64;
    const float* arow0 = (m0 < M) ? A + (size_t)m0 * K : nullptr;
    const float* arow1 = (m1 < M) ? A + (size_t)m1 * K : nullptr;
    const int n0 = bn + lr, n1 = bn + lr + 64;
    const float* brow0 = (n0 < N) ? Bm + (size_t)n0 * K : nullptr;
    const float* brow1 = (n1 < N) ? Bm + (size_t)n1 * K : nullptr;

    const float4 fz = make_float4(0.f, 0.f, 0.f, 0.f);

    for (int k0 = 0; k0 < K; k0 += BK) {
        float4 a0 = arow0 ? *(const float4*)(arow0 + k0 + lk) : fz;
        float4 a1 = arow1 ? *(const float4*)(arow1 + k0 + lk) : fz;
        float4 b0 = brow0 ? *(const float4*)(brow0 + k0 + lk) : fz;
        float4 b1 = brow1 ? *(const float4*)(brow1 + k0 + lk) : fz;

        __syncthreads();
        As[lk + 0][lr] = a0.x;  As[lk + 1][lr] = a0.y;
        As[lk + 2][lr] = a0.z;  As[lk + 3][lr] = a0.w;
        As[lk + 0][lr + 64] = a1.x;  As[lk + 1][lr + 64] = a1.y;
        As[lk + 2][lr + 64] = a1.z;  As[lk + 3][lr + 64] = a1.w;
        Bs[lk + 0][lr] = b0.x;  Bs[lk + 1][lr] = b0.y;
        Bs[lk + 2][lr] = b0.z;  Bs[lk + 3][lr] = b0.w;
        Bs[lk + 0][lr + 64] = b1.x;  Bs[lk + 1][lr + 64] = b1.y;
        Bs[lk + 2][lr + 64] = b1.z;  Bs[lk + 3][lr + 64] = b1.w;
        __syncthreads();

#pragma unroll
        for (int kk = 0; kk < BK; kk++) {
            float4 av0 = *(const float4*)&As[kk][ty * 8];
            float4 av1 = *(const float4*)&As[kk][ty * 8 + 4];
            float4 bv0 = *(const float4*)&Bs[kk][tx * 8];
            float4 bv1 = *(const float4*)&Bs[kk][tx * 8 + 4];
            unsigned long long a2[8] = {dup2(av0.x), dup2(av0.y), dup2(av0.z), dup2(av0.w),
                                        dup2(av1.x), dup2(av1.y), dup2(av1.z), dup2(av1.w)};
            unsigned long long b2[4] = {pk2(bv0.x, bv0.y), pk2(bv0.z, bv0.w),
                                        pk2(bv1.x, bv1.y), pk2(bv1.z, bv1.w)};
#pragma unroll
            for (int i = 0; i < 8; i++)
#pragma unroll
                for (int j = 0; j < 4; j++) fma2(acc[i][j], a2[i], b2[j]);
        }
    }

#pragma unroll
    for (int i = 0; i < 8; i++) {
        int m = bm + ty * 8 + i;
        if (m >= M) continue;
        size_t crow = (size_t)m * N;
#pragma unroll
        for (int j = 0; j < 4; j++) {
            float2 v = up2(acc[i][j]);
            int n = bn + tx * 8 + 2 * j;
            if (n < N)     C[crow + n]     = v.x + bias0[n];
            if (n + 1 < N) C[crow + n + 1] = v.y + bias0[n + 1];
        }
    }
}

// ---------------- persistent LSTM scan — tensor core (R14, unchanged) -------
#define SC_ROW 1032
#define SC_W_HALFS (32 * SC_ROW)
#define SC_A_HALFS (16 * SC_ROW)
#define SC_PF_STRIDE 34
#define SC_PF_FLOATS (8 * 16 * SC_PF_STRIDE)
#define SC_SMEM ((2 * SC_W_HALFS + SC_A_HALFS) * 2 + SC_PF_FLOATS * 4)

__global__ void __launch_bounds__(256, 1)
lstm_scan_mma(const float* __restrict__ c0,
              const __half* __restrict__ whh_hi,
              const __half* __restrict__ whh_lo,
              const float* __restrict__ xW,
              float* __restrict__ hs,
              __half* __restrict__ hh,
              unsigned int* __restrict__ bar)
{
    extern __shared__ __half shh[];
    __half* sWhi = shh;
    __half* sWlo = shh + SC_W_HALFS;
    __half* sA   = shh + 2 * SC_W_HALFS;
    float*  pf   = (float*)(shh + 2 * SC_W_HALFS + SC_A_HALFS);

    const int tid  = threadIdx.x;
    const int lane = tid & 31;
    const int w    = tid >> 5;
    const int hb   = blockIdx.x * 8;

#pragma unroll
    for (int it = 0; it < 16; it++) {
        int idx = tid + it * 256;
        int ll = idx >> 7, c8 = idx & 127;
        int j  = (ll >> 3) * H_DIM + hb + (ll & 7);
        *(uint4*)(sWhi + ll * SC_ROW + c8 * 8) =
            *(const uint4*)(whh_hi + (size_t)j * H_DIM + c8 * 8);
        *(uint4*)(sWlo + ll * SC_ROW + c8 * 8) =
            *(const uint4*)(whh_lo + (size_t)j * H_DIM + c8 * 8);
    }

    const int a_b = tid & 15, a_hil = (tid >> 4) & 7;
    float cloc = 0.f;
    if (tid < 128) cloc = c0[a_b * H_DIM + hb + a_hil];

    const int kc = w * 16;

    for (int t = 0; t < S_LEN; t++) {
        float xv0 = 0.f, xv1 = 0.f, xv2 = 0.f, xv3 = 0.f;
        if (tid < 128) {
            const float* xp = xW + ((size_t)t * 16 + a_b) * G4 + hb + a_hil;
            xv0 = __ldg(xp);        xv1 = __ldg(xp + 1024);
            xv2 = __ldg(xp + 2048); xv3 = __ldg(xp + 3072);
        }

        {
            const __half* src = hh + (size_t)t * B_SZ * H_DIM;
#pragma unroll
            for (int i = 0; i < 8; i++) {
                int idx = tid + i * 256;
                int row = idx >> 7, c8 = idx & 127;
                cp16(smem_u32(sA + row * SC_ROW + c8 * 8),
                     src + row * H_DIM + c8 * 8);
            }
        }
        CP_COMMIT();
        CP_WAIT0();
        __syncthreads();

        float acc[4][4];
#pragma unroll
        for (int nf = 0; nf < 4; nf++)
#pragma unroll
            for (int r = 0; r < 4; r++) acc[nf][r] = 0.f;

#pragma unroll
        for (int pass = 0; pass < 2; pass++) {
            const __half* Wsrc = pass ? sWlo : sWhi;
#pragma unroll
            for (int ks = 0; ks < 8; ks++) {
                uint32_t af[4];
                ldsm_x4(af, smem_u32(sA + (lane & 15) * SC_ROW
                                     + (kc + ks * 2 + (lane >> 4)) * 8));
                uint32_t br[2][4];
#pragma unroll
                for (int g = 0; g < 2; g++) {
                    int row = g * 16 + ((lane >> 4) << 3) + (lane & 7);
                    ldsm_x4(br[g], smem_u32(Wsrc + row * SC_ROW
                                            + (kc + ks * 2 + ((lane >> 3) & 1)) * 8));
                }
#pragma unroll
                for (int g = 0; g < 2; g++) {
                    mma16816(acc[g * 2],     af, &br[g][0]);
                    mma16816(acc[g * 2 + 1], af, &br[g][2]);
                }
            }
        }

        {
            float* pw = pf + w * 16 * SC_PF_STRIDE;
            int r0 = lane >> 2;
            int cb = (lane & 3) * 2;
#pragma unroll
            for (int nf = 0; nf < 4; nf++) {
                int c = nf * 8 + cb;
                *(float2*)(pw + r0 * SC_PF_STRIDE + c) =
                    make_float2(acc[nf][0], acc[nf][1]);
                *(float2*)(pw + (r0 + 8) * SC_PF_STRIDE + c) =
                    make_float2(acc[nf][2], acc[nf][3]);
            }
        }
        __syncthreads();

        if (tid < 128) {
            float gI = xv0, gF = xv1, gG = xv2, gO = xv3;
            const float* pw = pf + a_b * SC_PF_STRIDE + a_hil;
#pragma unroll
            for (int ww = 0; ww < 8; ww++) {
                const float* p = pw + ww * 16 * SC_PF_STRIDE;
                gI += p[0]; gF += p[8]; gG += p[16]; gO += p[24];
            }
            float cn = sigm(gF) * cloc + sigm(gI) * tanhf(gG);
            cloc = cn;
            float hv = sigm(gO) * tanhf(cn);
            hs[(size_t)t * B_SZ * H_DIM + a_b * H_DIM + hb + a_hil] = hv;
            hh[(size_t)(t + 1) * B_SZ * H_DIM + a_b * H_DIM + hb + a_hil] =
                __float2half_rn(hv);
        }
        __syncthreads();

        if (tid == 0) {
            red_rel_add(bar, 1u);
            const unsigned int target = 128u * (unsigned)(t + 1);
            while (ld_acq(bar) < target) { }
        }
        __syncthreads();
    }
}

// ---------------- fp16 convert / split kernels -------------------------------
__global__ void __launch_bounds__(256)
conv_a_k(const float* __restrict__ src, __half* __restrict__ dst, int n4)
{
    int i = blockIdx.x * blockDim.x + threadIdx.x;
    if (i >= n4) return;
    float4 v = ((const float4*)src)[i];
    __half h[4] = { __float2half_rn(v.x), __float2half_rn(v.y),
                    __float2half_rn(v.z), __float2half_rn(v.w) };
    ((__half2*)dst)[2 * i]     = __halves2half2(h[0], h[1]);
    ((__half2*)dst)[2 * i + 1] = __halves2half2(h[2], h[3]);
}

__global__ void __launch_bounds__(256)
conv_gather_k(const float* __restrict__ emb, const int* __restrict__ tokens,
              __half* __restrict__ dst)
{
    const int m = blockIdx.x;
    const float4* src = (const float4*)(emb + (size_t)tokens[m] * E_DIM);
    float4 v = src[threadIdx.x];
    __half2 h0 = __halves2half2(__float2half_rn(v.x), __float2half_rn(v.y));
    __half2 h1 = __halves2half2(__float2half_rn(v.z), __float2half_rn(v.w));
    __half2* d = (__half2*)(dst + (size_t)m * E_DIM);
    d[threadIdx.x * 2]     = h0;
    d[threadIdx.x * 2 + 1] = h1;
}

__global__ void __launch_bounds__(256)
conv_b_k(const float* __restrict__ src, __half* __restrict__ out)
{
    int i = blockIdx.x * blockDim.x + threadIdx.x;
    if (i >= V_PAD * (H_DIM / 4)) return;
    int row = i >> 8;
    float4 v = make_float4(0.f, 0.f, 0.f, 0.f);
    if (row < V_SZ) v = ((const float4*)src)[i];
    __half h[4] = { __float2half_rn(v.x), __float2half_rn(v.y),
                    __float2half_rn(v.z), __float2half_rn(v.w) };
    ((__half2*)out)[2 * i]     = __halves2half2(h[0], h[1]);
    ((__half2*)out)[2 * i + 1] = __halves2half2(h[2], h[3]);
}

__global__ void __launch_bounds__(256)
split_w_k(const float* __restrict__ src, __half* __restrict__ hi,
          __half* __restrict__ lo, int n4)
{
    int i = blockIdx.x * blockDim.x + threadIdx.x;
    if (i >= n4) return;
    float4 v = ((const float4*)src)[i];
    float xs[4] = {v.x, v.y, v.z, v.w};
    __half h[4], l[4];
#pragma unroll
    for (int j = 0; j < 4; j++) {
        h[j] = __float2half_rn(xs[j]);
        l[j] = __float2half_rn(xs[j] - __half2float(h[j]));
    }
    ((__half2*)hi)[2 * i]     = __halves2half2(h[0], h[1]);
    ((__half2*)hi)[2 * i + 1] = __halves2half2(h[2], h[3]);
    ((__half2*)lo)[2 * i]     = __halves2half2(l[0], l[1]);
    ((__half2*)lo)[2 * i + 1] = __halves2half2(l[2], l[3]);
}

// ---------------- xW GEMM: fp16 mma, 2-pass (A pre-gathered) -----------------
#define DROW 40

__global__ void __launch_bounds__(256, 2)
xw_gemm(const __half* __restrict__ a_h,
        const __half* __restrict__ w_hi, const __half* __restrict__ w_lo,
        const float* __restrict__ bih, const float* __restrict__ bhh,
        float* __restrict__ out)
{
    __shared__ __align__(16) __half As[2][128 * DROW];
    __shared__ __align__(16) __half Bs[2][128 * DROW];

    const int tid  = threadIdx.x;
    const int lane = tid & 31;
    const int warp = tid >> 5;
    const int warpM = warp >> 2;
    const int warpN = warp & 3;
    const int bm = blockIdx.y * 128;
    const int bn = blockIdx.x * 128;

    const uint32_t sA[2] = { smem_u32(As[0]), smem_u32(As[1]) };
    const uint32_t sB[2] = { smem_u32(Bs[0]), smem_u32(Bs[1]) };

    float acc[4][4][4];
#pragma unroll
    for (int i = 0; i < 4; i++)
#pragma unroll
        for (int j = 0; j < 4; j++)
#pragma unroll
            for (int r = 0; r < 4; r++) acc[i][j][r] = 0.f;

    const int r0c = tid >> 2, c0c = tid & 3;
    const int r1c = r0c + 64;

    auto issue = [&](int it, int buf) {
        const int p  = it >> 5;
        const int k0 = (it & 31) * 32;
        const __half* Bp = p ? w_lo : w_hi;
        cp16(sA[buf] + (r0c * DROW + c0c * 8) * 2,
             a_h + (size_t)(bm + r0c) * E_DIM + k0 + c0c * 8);
        cp16(sA[buf] + (r1c * DROW + c0c * 8) * 2,
             a_h + (size_t)(bm + r1c) * E_DIM + k0 + c0c * 8);
        cp16(sB[buf] + (r0c * DROW + c0c * 8) * 2,
             Bp + (size_t)(bn + r0c) * E_DIM + k0 + c0c * 8);
        cp16(sB[buf] + (r1c * DROW + c0c * 8) * 2,
             Bp + (size_t)(bn + r1c) * E_DIM + k0 + c0c * 8);
    };

    issue(0, 0);
    CP_COMMIT();

    for (int it = 0; it < 64; it++) {
        const int buf = it & 1;
        if (it + 1 < 64) { issue(it + 1, buf ^ 1); CP_COMMIT(); CP_WAIT1(); }
        else             { CP_WAIT0(); }
        __syncthreads();

#pragma unroll
        for (int ks = 0; ks < 2; ks++) {
            uint32_t af[4][4];
#pragma unroll
            for (int mf = 0; mf < 4; mf++) {
                int row = warpM * 64 + mf * 16 + (lane & 15);
                int ch  = ks * 2 + (lane >> 4);
                ldsm_x4(af[mf], sA[buf] + (row * DROW + ch * 8) * 2);
            }
            uint32_t br[2][4];
#pragma unroll
            for (int g = 0; g < 2; g++) {
                int row = warpN * 32 + g * 16 + ((lane >> 4) << 3) + (lane & 7);
                int ch  = ks * 2 + ((lane >> 3) & 1);
                ldsm_x4(br[g], sB[buf] + (row * DROW + ch * 8) * 2);
            }
#pragma unroll
            for (int mf = 0; mf < 4; mf++)
#pragma unroll
                for (int g = 0; g < 2; g++) {
                    mma16816(acc[mf][g * 2],     af[mf], &br[g][0]);
                    mma16816(acc[mf][g * 2 + 1], af[mf], &br[g][2]);
                }
        }
        __syncthreads();
    }

#pragma unroll
    for (int mf = 0; mf < 4; mf++) {
        int rowA = bm + warpM * 64 + mf * 16 + (lane >> 2);
        int rowB = rowA + 8;
#pragma unroll
        for (int nf = 0; nf < 4; nf++) {
            int col = bn + warpN * 32 + nf * 8 + (lane & 3) * 2;
            float b0 = bih[col]     + bhh[col];
            float b1 = bih[col + 1] + bhh[col + 1];
            out[(size_t)rowA * G4 + col]     = acc[mf][nf][0] + b0;
            out[(size_t)rowA * G4 + col + 1] = acc[mf][nf][1] + b1;
            out[(size_t)rowB * G4 + col]     = acc[mf][nf][2] + b0;
            out[(size_t)rowB * G4 + col + 1] = acc[mf][nf][3] + b1;
        }
    }
}

// ---------------- step-5 GEMM: fp16 mma 2-pass, fused mask+hm, fp16 out -----
// outputs[m][n] = (m/16 < k) ? hs[m][n]
//                            : hs_h[m] @ (W2hi+W2lo)[n]^T + bhh2[n] + hm[m%16][n]
// A = hh + 16*1024 (fp16 h chain, slot t+1 == hs row-major). Writes fp16 to a_h.
__global__ void __launch_bounds__(256, 2)
out_gemm(const __half* __restrict__ a_h,
         const __half* __restrict__ w_hi, const __half* __restrict__ w_lo,
         const float* __restrict__ bhh2, const float* __restrict__ hmv,
         const float* __restrict__ hs, const int* __restrict__ kptr,
         __half* __restrict__ outh)
{
    __shared__ __align__(16) __half As[2][128 * DROW];
    __shared__ __align__(16) __half Bs[2][128 * DROW];

    const int tid  = threadIdx.x;
    const int lane = tid & 31;
    const int warp = tid >> 5;
    const int warpM = warp >> 2;
    const int warpN = warp & 3;
    const int bm = blockIdx.y * 128;
    const int bn = blockIdx.x * 128;

    const uint32_t sA[2] = { smem_u32(As[0]), smem_u32(As[1]) };
    const uint32_t sB[2] = { smem_u32(Bs[0]), smem_u32(Bs[1]) };

    float acc[4][4][4];
#pragma unroll
    for (int i = 0; i < 4; i++)
#pragma unroll
        for (int j = 0; j < 4; j++)
#pragma unroll
            for (int r = 0; r < 4; r++) acc[i][j][r] = 0.f;

    const int r0c = tid >> 2, c0c = tid & 3;
    const int r1c = r0c + 64;

    auto issue = [&](int it, int buf) {
        const int p  = it >> 5;
        const int k0 = (it & 31) * 32;
        const __half* Bp = p ? w_lo : w_hi;
        cp16(sA[buf] + (r0c * DROW + c0c * 8) * 2,
             a_h + (size_t)(bm + r0c) * H_DIM + k0 + c0c * 8);
        cp16(sA[buf] + (r1c * DROW + c0c * 8) * 2,
             a_h + (size_t)(bm + r1c) * H_DIM + k0 + c0c * 8);
        cp16(sB[buf] + (r0c * DROW + c0c * 8) * 2,
             Bp + (size_t)(bn + r0c) * H_DIM + k0 + c0c * 8);
        cp16(sB[buf] + (r1c * DROW + c0c * 8) * 2,
             Bp + (size_t)(bn + r1c) * H_DIM + k0 + c0c * 8);
    };

    issue(0, 0);
    CP_COMMIT();

    for (int it = 0; it < 64; it++) {
        const int buf = it & 1;
        if (it + 1 < 64) { issue(it + 1, buf ^ 1); CP_COMMIT(); CP_WAIT1(); }
        else             { CP_WAIT0(); }
        __syncthreads();

#pragma unroll
        for (int ks = 0; ks < 2; ks++) {
            uint32_t af[4][4];
#pragma unroll
            for (int mf = 0; mf < 4; mf++) {
                int row = warpM * 64 + mf * 16 + (lane & 15);
                int ch  = ks * 2 + (lane >> 4);
                ldsm_x4(af[mf], sA[buf] + (row * DROW + ch * 8) * 2);
            }
            uint32_t br[2][4];
#pragma unroll
            for (int g = 0; g < 2; g++) {
                int row = warpN * 32 + g * 16 + ((lane >> 4) << 3) + (lane & 7);
                int ch  = ks * 2 + ((lane >> 3) & 1);
                ldsm_x4(br[g], sB[buf] + (row * DROW + ch * 8) * 2);
            }
#pragma unroll
            for (int mf = 0; mf < 4; mf++)
#pragma unroll
                for (int g = 0; g < 2; g++) {
                    mma16816(acc[mf][g * 2],     af[mf], &br[g][0]);
                    mma16816(acc[mf][g * 2 + 1], af[mf], &br[g][2]);
                }
        }
        __syncthreads();
    }

    const int kval = *kptr;
#pragma unroll
    for (int mf = 0; mf < 4; mf++) {
        int rows[2];
        rows[0] = bm + warpM * 64 + mf * 16 + (lane >> 2);
        rows[1] = rows[0] + 8;
#pragma unroll
        for (int rr = 0; rr < 2; rr++) {
            int row = rows[rr];
            int srow = row >> 4;
            int b    = row & 15;
            bool cp = (srow < kval);
#pragma unroll
            for (int nf = 0; nf < 4; nf++) {
                int col = bn + warpN * 32 + nf * 8 + (lane & 3) * 2;
                float v0, v1;
                if (cp) {
                    v0 = hs[(size_t)row * H_DIM + col];
                    v1 = hs[(size_t)row * H_DIM + col + 1];
                } else {
                    v0 = acc[mf][nf][rr * 2]     + bhh2[col]     + hmv[b * H_DIM + col];
                    v1 = acc[mf][nf][rr * 2 + 1] + bhh2[col + 1] + hmv[b * H_DIM + col + 1];
                }
                outh[(size_t)row * H_DIM + col]     = __float2half_rn(v0);
                outh[(size_t)row * H_DIM + col + 1] = __float2half_rn(v1);
            }
        }
    }
}

// ---------------- mma.sync decoder GEMM (fp16, single pass, 2 CTAs/SM) ------
__global__ void __launch_bounds__(256, 2)
dec_gemm(const __half* __restrict__ a_h, const __half* __restrict__ b_h,
         const float* __restrict__ bias, float* __restrict__ out)
{
    __shared__ __align__(16) __half As[2][128 * DROW];
    __shared__ __align__(16) __half Bs[2][128 * DROW];

    const int tid  = threadIdx.x;
    const int lane = tid & 31;
    const int warp = tid >> 5;
    const int warpM = warp >> 2;
    const int warpN = warp & 3;
    const int bm = blockIdx.y * 128;
    const int bn = blockIdx.x * 128;

    const uint32_t sA[2] = { smem_u32(As[0]), smem_u32(As[1]) };
    const uint32_t sB[2] = { smem_u32(Bs[0]), smem_u32(Bs[1]) };

    float acc[4][4][4];
#pragma unroll
    for (int i = 0; i < 4; i++)
#pragma unroll
        for (int j = 0; j < 4; j++)
#pragma unroll
            for (int r = 0; r < 4; r++) acc[i][j][r] = 0.f;

    const int r0c = tid >> 2, c0c = tid & 3;
    const int r1c = (tid + 256) >> 2, c1c = tid & 3;

    auto issue = [&](int it, int buf) {
        const int k0 = it * 32;
        cp16(sA[buf] + (r0c * DROW + c0c * 8) * 2,
             a_h + (size_t)(bm + r0c) * H_DIM + k0 + c0c * 8);
        cp16(sA[buf] + (r1c * DROW + c1c * 8) * 2,
             a_h + (size_t)(bm + r1c) * H_DIM + k0 + c1c * 8);
        cp16(sB[buf] + (r0c * DROW + c0c * 8) * 2,
             b_h + (size_t)(bn + r0c) * H_DIM + k0 + c0c * 8);
        cp16(sB[buf] + (r1c * DROW + c1c * 8) * 2,
             b_h + (size_t)(bn + r1c) * H_DIM + k0 + c1c * 8);
    };

    issue(0, 0);
    CP_COMMIT();

    for (int it = 0; it < 32; it++) {
        const int buf = it & 1;
        if (it + 1 < 32) { issue(it + 1, buf ^ 1); CP_COMMIT(); CP_WAIT1(); }
        else             { CP_WAIT0(); }
        __syncthreads();

#pragma unroll
        for (int ks = 0; ks < 2; ks++) {
            uint32_t af[4][4];
#pragma unroll
            for (int mf = 0; mf < 4; mf++) {
                int row = warpM * 64 + mf * 16 + (lane & 15);
                int ch  = ks * 2 + (lane >> 4);
                ldsm_x4(af[mf], sA[buf] + (row * DROW + ch * 8) * 2);
            }
            uint32_t br[2][4];
#pragma unroll
            for (int g = 0; g < 2; g++) {
                int row = warpN * 32 + g * 16 + ((lane >> 4) << 3) + (lane & 7);
                int ch  = ks * 2 + ((lane >> 3) & 1);
                ldsm_x4(br[g], sB[buf] + (row * DROW + ch * 8) * 2);
            }
#pragma unroll
            for (int mf = 0; mf < 4; mf++)
#pragma unroll
                for (int g = 0; g < 2; g++) {
                    mma16816(acc[mf][g * 2],     af[mf], &br[g][0]);
                    mma16816(acc[mf][g * 2 + 1], af[mf], &br[g][2]);
                }
        }
        __syncthreads();
    }

#pragma unroll
    for (int mf = 0; mf < 4; mf++) {
        int rowA = bm + warpM * 64 + mf * 16 + (lane >> 2);
        int rowB = rowA + 8;
#pragma unroll
        for (int nf = 0; nf < 4; nf++) {
            int col = bn + warpN * 32 + nf * 8 + (lane & 3) * 2;
            float b0 = (col     < V_SZ) ? bias[col]     : 0.f;
            float b1 = (col + 1 < V_SZ) ? bias[col + 1] : 0.f;
            if (col < V_SZ)     out[(size_t)rowA * V_SZ + col]     = acc[mf][nf][0] + b0;
            if (col + 1 < V_SZ) out[(size_t)rowA * V_SZ + col + 1] = acc[mf][nf][1] + b1;
            if (col < V_SZ)     out[(size_t)rowB * V_SZ + col]     = acc[mf][nf][2] + b0;
            if (col + 1 < V_SZ) out[(size_t)rowB * V_SZ + col + 1] = acc[mf][nf][3] + b1;
        }
    }
}

// ---------------- launcher --------------------------------------------------
extern "C" void kernel_launch(void* const* d_in, const int* in_sizes, int n_in,
                              void* d_out, int out_size)
{
    const int*   tokens = (const int*)  d_in[0];
    const float* h0     = (const float*)d_in[1];
    const float* c0     = (const float*)d_in[2];
    const float* emb    = (const float*)d_in[3];
    const float* Wih    = (const float*)d_in[4];
    const float* Whh    = (const float*)d_in[5];
    const float* bih    = (const float*)d_in[6];
    const float* bhh    = (const float*)d_in[7];
    const float* Whh2   = (const float*)d_in[8];
    const float* bhh2   = (const float*)d_in[9];
    const float* Whm    = (const float*)d_in[10];
    const float* bhm    = (const float*)d_in[11];
    const float* decW   = (const float*)d_in[12];
    const float* decb   = (const float*)d_in[13];
    const int*   kp     = (const int*)  d_in[14];
    float* out = (float*)d_out;

    void *p_xW, *p_hs, *p_hm, *p_bar, *p_ah, *p_bh, *p_wh, *p_wl,
         *p_whh, *p_whl, *p_w2h, *p_w2l, *p_hh;
    cudaGetSymbolAddress(&p_xW,   g_xW);
    cudaGetSymbolAddress(&p_hs,   g_hs);
    cudaGetSymbolAddress(&p_hm,   g_hm);
    cudaGetSymbolAddress(&p_bar,  g_bar);
    cudaGetSymbolAddress(&p_ah,   g_a_h);
    cudaGetSymbolAddress(&p_bh,   g_b_h);
    cudaGetSymbolAddress(&p_wh,   g_wih_hi);
    cudaGetSymbolAddress(&p_wl,   g_wih_lo);
    cudaGetSymbolAddress(&p_whh,  g_whh_hi);
    cudaGetSymbolAddress(&p_whl,  g_whh_lo);
    cudaGetSymbolAddress(&p_w2h,  g_w2_hi);
    cudaGetSymbolAddress(&p_w2l,  g_w2_lo);
    cudaGetSymbolAddress(&p_hh,   g_hh);
    float* xW   = (float*)p_xW;
    float* hs   = (float*)p_hs;
    float* hm   = (float*)p_hm;
    unsigned int* bar = (unsigned int*)p_bar;
    __half* ah  = (__half*)p_ah;
    __half* bh  = (__half*)p_bh;
    __half* wh  = (__half*)p_wh;
    __half* wl  = (__half*)p_wl;
    __half* whh = (__half*)p_whh;
    __half* whl = (__half*)p_whl;
    __half* w2h = (__half*)p_w2h;
    __half* w2l = (__half*)p_w2l;
    __half* hh  = (__half*)p_hh;

    cudaFuncSetAttribute(lstm_scan_mma,
                         cudaFuncAttributeMaxDynamicSharedMemorySize, SC_SMEM);

    const int M = S_LEN * B_SZ;   // 2048

    // 0) conversions: gather emb -> fp16; Wih/Whh/Whh2 -> hi/lo; decW -> fp16;
    //    h0 -> fp16 chain slot 0
    conv_gather_k<<<M, 256>>>(emb, tokens, ah);
    split_w_k<<<(G4 * E_DIM / 4 + 255) / 256, 256>>>(Wih, wh, wl, G4 * E_DIM / 4);
    split_w_k<<<(G4 * H_DIM / 4 + 255) / 256, 256>>>(Whh, whh, whl, G4 * H_DIM / 4);
    split_w_k<<<(H_DIM * H_DIM / 4 + 255) / 256, 256>>>(Whh2, w2h, w2l,
                                                        H_DIM * H_DIM / 4);
    conv_b_k<<<(V_PAD * H_DIM / 4 + 255) / 256, 256>>>(decW, bh);
    conv_a_k<<<(B_SZ * H_DIM / 4 + 255) / 256, 256>>>(h0, hh, B_SZ * H_DIM / 4);

    // 1) xW = a_h @ (Wih_hi+Wih_lo)^T + bih + bhh  (mma, 2-pass)
    xw_gemm<<<dim3(G4 / 128, M / 128), 256>>>(ah, wh, wl, bih, bhh, xW);

    // 2) hm = h0 @ Whm^T + bhm  (fp32 SIMT, tiny)
    gemm_k<<<dim3(H_DIM / 128, 1), 256>>>(
        h0, Whm, hm, B_SZ, H_DIM, H_DIM, bhm);

    // 3) reset grid barrier
    cudaMemsetAsync(bar, 0, sizeof(unsigned int), 0);

    // 4) persistent tensor-core LSTM scan
    lstm_scan_mma<<<128, 256, SC_SMEM>>>(c0, whh, whl, xW, hs, hh, bar);

    // 5) outputs (fp16, fused mask+hm+bias) = hs_h @ Whh2^T ...  -> g_a_h
    out_gemm<<<dim3(H_DIM / 128, M / 128), 256>>>(
        hh + B_SZ * H_DIM, w2h, w2l, bhh2, hm, hs, kp, ah);

    // 6) decoded = outputs @ decW^T + decb  — mma.sync fp16 single-pass GEMM
    dec_gemm<<<dim3(V_PAD / 128, M / 128), 256>>>(ah, bh, decb, out);

    (void)in_sizes; (void)n_in; (void)out_size;
}

// round 17
// speedup vs baseline: 3.8085x; 1.0207x over previous
#include <cuda_runtime.h>
#include <cuda_bf16.h>
#include <cuda_fp16.h>
#include <cstdint>

// Problem dims (fixed by the dataset)
#define S_LEN 128
#define B_SZ  16
#define H_DIM 1024
#define E_DIM 1024
#define G4    4096
#define V_SZ  50257
#define V_PAD 50304          // 393 * 128

// ---------------- scratch (device globals; no allocation allowed) ----------
__device__ float g_xW [S_LEN * B_SZ * G4];       // plain row-major [m][4H]
__device__ float g_hm [B_SZ * H_DIM];
__device__ unsigned int g_bar;
__device__ __align__(256) __half g_a_h[S_LEN * B_SZ * H_DIM];  // gathered emb, then fp16 outputs
__device__ __align__(256) __half g_b_h[(size_t)V_PAD * H_DIM];
__device__ __align__(256) __half g_wih_hi[G4 * E_DIM];
__device__ __align__(256) __half g_wih_lo[G4 * E_DIM];
__device__ __align__(256) __half g_whh_hi[G4 * H_DIM];
__device__ __align__(256) __half g_whh_lo[G4 * H_DIM];
__device__ __align__(256) __half g_w2_hi[H_DIM * H_DIM];
__device__ __align__(256) __half g_w2_lo[H_DIM * H_DIM];
__device__ __align__(256) __half g_hh[(S_LEN + 1) * B_SZ * H_DIM]; // fp16 h per step

// ---------------- f32x2 helpers --------------------------------------------
__device__ __forceinline__ unsigned long long dup2(float x) {
    unsigned long long r; asm("mov.b64 %0, {%1, %1};" : "=l"(r) : "f"(x)); return r;
}
__device__ __forceinline__ unsigned long long pk2(float lo, float hi) {
    unsigned long long r; asm("mov.b64 %0, {%1, %2};" : "=l"(r) : "f"(lo), "f"(hi)); return r;
}
__device__ __forceinline__ void fma2(unsigned long long& d,
                                     unsigned long long a, unsigned long long b) {
    asm("fma.rn.f32x2 %0, %1, %2, %0;" : "+l"(d) : "l"(a), "l"(b));
}
__device__ __forceinline__ float2 up2(unsigned long long v) {
    float2 f; asm("mov.b64 {%0, %1}, %2;" : "=f"(f.x), "=f"(f.y) : "l"(v)); return f;
}
__device__ __forceinline__ float sigm(float x) { return 1.0f / (1.0f + expf(-x)); }

__device__ __forceinline__ uint32_t smem_u32(const void* p) {
    uint32_t a;
    asm("{ .reg .u64 t; cvta.to.shared.u64 t, %1; cvt.u32.u64 %0, t; }"
        : "=r"(a) : "l"(p));
    return a;
}
__device__ __forceinline__ unsigned int ld_acq(const unsigned int* p) {
    unsigned int v;
    asm volatile("ld.acquire.gpu.u32 %0, [%1];" : "=r"(v) : "l"(p) : "memory");
    return v;
}
__device__ __forceinline__ void red_rel_add(unsigned int* p, unsigned int v) {
    asm volatile("red.release.gpu.global.add.u32 [%0], %1;" :: "l"(p), "r"(v) : "memory");
}

// ---------------- mma.sync / ldmatrix / cp.async helpers (non-'a' PTX) ------
__device__ __forceinline__ void ldsm_x4(uint32_t* r, uint32_t addr) {
    asm volatile("ldmatrix.sync.aligned.m8n8.x4.shared.b16 {%0,%1,%2,%3}, [%4];"
                 : "=r"(r[0]), "=r"(r[1]), "=r"(r[2]), "=r"(r[3]) : "r"(addr));
}
__device__ __forceinline__ void mma16816(float* c, const uint32_t* a, const uint32_t* b) {
    asm volatile(
        "mma.sync.aligned.m16n8k16.row.col.f32.f16.f16.f32 "
        "{%0,%1,%2,%3}, {%4,%5,%6,%7}, {%8,%9}, {%0,%1,%2,%3};"
        : "+f"(c[0]), "+f"(c[1]), "+f"(c[2]), "+f"(c[3])
        : "r"(a[0]), "r"(a[1]), "r"(a[2]), "r"(a[3]), "r"(b[0]), "r"(b[1]));
}
__device__ __forceinline__ void cp16(uint32_t dst, const void* src) {
    asm volatile("cp.async.cg.shared.global [%0], [%1], 16;" :: "r"(dst), "l"(src));
}
#define CP_COMMIT() asm volatile("cp.async.commit_group;" ::: "memory")
#define CP_WAIT1()  asm volatile("cp.async.wait_group 1;" ::: "memory")
#define CP_WAIT0()  asm volatile("cp.async.wait_group 0;" ::: "memory")

// ---------------- generic tiled fp32 GEMM (step 2 only) ---------------------
__global__ void __launch_bounds__(256)
gemm_k(const float* __restrict__ A, const float* __restrict__ Bm,
       float* __restrict__ C, int M, int N, int K,
       const float* __restrict__ bias0)
{
    constexpr int BM = 128, BN = 128, BK = 16;
    __shared__ float As[BK][BM + 4];
    __shared__ float Bs[BK][BN + 4];

    const int tid = threadIdx.x;
    const int bm = blockIdx.y * BM;
    const int bn = blockIdx.x * BN;
    const int tx = tid & 15;
    const int ty = tid >> 4;
    const int lr = tid >> 2;
    const int lk = (tid & 3) * 4;

    unsigned long long acc[8][4];
#pragma unroll
    for (int i = 0; i < 8; i++)
#pragma unroll
        for (int j = 0; j < 4; j++) acc[i][j] = 0ull;

    const int m0 = bm + lr, m1 = bm + lr + 64;
    const float* arow0 = (m0 < M) ? A + (size_t)m0 * K : nullptr;
    const float* arow1 = (m1 < M) ? A + (size_t)m1 * K : nullptr;
    const int n0 = bn + lr, n1 = bn + lr + 64;
    const float* brow0 = (n0 < N) ? Bm + (size_t)n0 * K : nullptr;
    const float* brow1 = (n1 < N) ? Bm + (size_t)n1 * K : nullptr;

    const float4 fz = make_float4(0.f, 0.f, 0.f, 0.f);

    for (int k0 = 0; k0 < K; k0 += BK) {
        float4 a0 = arow0 ? *(const float4*)(arow0 + k0 + lk) : fz;
        float4 a1 = arow1 ? *(const float4*)(arow1 + k0 + lk) : fz;
        float4 b0 = brow0 ? *(const float4*)(brow0 + k0 + lk) : fz;
        float4 b1 = brow1 ? *(const float4*)(brow1 + k0 + lk) : fz;

        __syncthreads();
        As[lk + 0][lr] = a0.x;  As[lk + 1][lr] = a0.y;
        As[lk + 2][lr] = a0.z;  As[lk + 3][lr] = a0.w;
        As[lk + 0][lr + 64] = a1.x;  As[lk + 1][lr + 64] = a1.y;
        As[lk + 2][lr + 64] = a1.z;  As[lk + 3][lr + 64] = a1.w;
        Bs[lk + 0][lr] = b0.x;  Bs[lk + 1][lr] = b0.y;
        Bs[lk + 2][lr] = b0.z;  Bs[lk + 3][lr] = b0.w;
        Bs[lk + 0][lr + 64] = b1.x;  Bs[lk + 1][lr + 64] = b1.y;
        Bs[lk + 2][lr + 64] = b1.z;  Bs[lk + 3][lr + 64] = b1.w;
        __syncthreads();

#pragma unroll
        for (int kk = 0; kk < BK; kk++) {
            float4 av0 = *(const float4*)&As[kk][ty * 8];
            float4 av1 = *(const float4*)&As[kk][ty * 8 + 4];
            float4 bv0 = *(const float4*)&Bs[kk][tx * 8];
            float4 bv1 = *(const float4*)&Bs[kk][tx * 8 + 4];
            unsigned long long a2[8] = {dup2(av0.x), dup2(av0.y), dup2(av0.z), dup2(av0.w),
                                        dup2(av1.x), dup2(av1.y), dup2(av1.z), dup2(av1.w)};
            unsigned long long b2[4] = {pk2(bv0.x, bv0.y), pk2(bv0.z, bv0.w),
                                        pk2(bv1.x, bv1.y), pk2(bv1.z, bv1.w)};
#pragma unroll
            for (int i = 0; i < 8; i++)
#pragma unroll
                for (int j = 0; j < 4; j++) fma2(acc[i][j], a2[i], b2[j]);
        }
    }

#pragma unroll
    for (int i = 0; i < 8; i++) {
        int m = bm + ty * 8 + i;
        if (m >= M) continue;
        size_t crow = (size_t)m * N;
#pragma unroll
        for (int j = 0; j < 4; j++) {
            float2 v = up2(acc[i][j]);
            int n = bn + tx * 8 + 2 * j;
            if (n < N)     C[crow + n]     = v.x + bias0[n];
            if (n + 1 < N) C[crow + n + 1] = v.y + bias0[n + 1];
        }
    }
}

// ---------------- persistent LSTM scan — tensor core + helper CTAs ----------
// Blocks 0..127: scan (unchanged R14 internals, minus fp32 hs store).
// Blocks 128..147: helpers — convert decW -> fp16 and split Whh2 -> hi/lo
// (consumed only after the scan), then exit. Barrier counts 128 only.
#define SC_ROW 1032
#define SC_W_HALFS (32 * SC_ROW)
#define SC_A_HALFS (16 * SC_ROW)
#define SC_PF_STRIDE 34
#define SC_PF_FLOATS (8 * 16 * SC_PF_STRIDE)
#define SC_SMEM ((2 * SC_W_HALFS + SC_A_HALFS) * 2 + SC_PF_FLOATS * 4)
#define SC_HELPERS 20
#define SC_GRID (128 + SC_HELPERS)

__global__ void __launch_bounds__(256, 1)
lstm_scan_mma(const float* __restrict__ c0,
              const __half* __restrict__ whh_hi,
              const __half* __restrict__ whh_lo,
              const float* __restrict__ xW,
              __half* __restrict__ hh,
              unsigned int* __restrict__ bar,
              const float* __restrict__ decW, __half* __restrict__ b_h,
              const float* __restrict__ Whh2,
              __half* __restrict__ w2_hi, __half* __restrict__ w2_lo)
{
    const int tid = threadIdx.x;

    // ================= helper CTAs =================
    if (blockIdx.x >= 128) {
        const int gtid = (blockIdx.x - 128) * 256 + tid;
        const int nthr = SC_HELPERS * 256;
        // decW -> fp16, padded to V_PAD rows
        for (int i = gtid; i < V_PAD * (H_DIM / 4); i += nthr) {
            int row = i >> 8;
            float4 v = make_float4(0.f, 0.f, 0.f, 0.f);
            if (row < V_SZ) v = ((const float4*)decW)[i];
            __half h[4] = { __float2half_rn(v.x), __float2half_rn(v.y),
                            __float2half_rn(v.z), __float2half_rn(v.w) };
            ((__half2*)b_h)[2 * i]     = __halves2half2(h[0], h[1]);
            ((__half2*)b_h)[2 * i + 1] = __halves2half2(h[2], h[3]);
        }
        // Whh2 -> fp16 hi/lo split
        for (int i = gtid; i < H_DIM * H_DIM / 4; i += nthr) {
            float4 v = ((const float4*)Whh2)[i];
            float xs[4] = {v.x, v.y, v.z, v.w};
            __half h[4], l[4];
#pragma unroll
            for (int j = 0; j < 4; j++) {
                h[j] = __float2half_rn(xs[j]);
                l[j] = __float2half_rn(xs[j] - __half2float(h[j]));
            }
            ((__half2*)w2_hi)[2 * i]     = __halves2half2(h[0], h[1]);
            ((__half2*)w2_hi)[2 * i + 1] = __halves2half2(h[2], h[3]);
            ((__half2*)w2_lo)[2 * i]     = __halves2half2(l[0], l[1]);
            ((__half2*)w2_lo)[2 * i + 1] = __halves2half2(l[2], l[3]);
        }
        return;
    }

    // ================= scan CTAs =================
    extern __shared__ __half shh[];
    __half* sWhi = shh;
    __half* sWlo = shh + SC_W_HALFS;
    __half* sA   = shh + 2 * SC_W_HALFS;
    float*  pf   = (float*)(shh + 2 * SC_W_HALFS + SC_A_HALFS);

    const int lane = tid & 31;
    const int w    = tid >> 5;
    const int hb   = blockIdx.x * 8;

#pragma unroll
    for (int it = 0; it < 16; it++) {
        int idx = tid + it * 256;
        int ll = idx >> 7, c8 = idx & 127;
        int j  = (ll >> 3) * H_DIM + hb + (ll & 7);
        *(uint4*)(sWhi + ll * SC_ROW + c8 * 8) =
            *(const uint4*)(whh_hi + (size_t)j * H_DIM + c8 * 8);
        *(uint4*)(sWlo + ll * SC_ROW + c8 * 8) =
            *(const uint4*)(whh_lo + (size_t)j * H_DIM + c8 * 8);
    }

    const int a_b = tid & 15, a_hil = (tid >> 4) & 7;
    float cloc = 0.f;
    if (tid < 128) cloc = c0[a_b * H_DIM + hb + a_hil];

    const int kc = w * 16;

    for (int t = 0; t < S_LEN; t++) {
        float xv0 = 0.f, xv1 = 0.f, xv2 = 0.f, xv3 = 0.f;
        if (tid < 128) {
            const float* xp = xW + ((size_t)t * 16 + a_b) * G4 + hb + a_hil;
            xv0 = __ldg(xp);        xv1 = __ldg(xp + 1024);
            xv2 = __ldg(xp + 2048); xv3 = __ldg(xp + 3072);
        }

        {
            const __half* src = hh + (size_t)t * B_SZ * H_DIM;
#pragma unroll
            for (int i = 0; i < 8; i++) {
                int idx = tid + i * 256;
                int row = idx >> 7, c8 = idx & 127;
                cp16(smem_u32(sA + row * SC_ROW + c8 * 8),
                     src + row * H_DIM + c8 * 8);
            }
        }
        CP_COMMIT();
        CP_WAIT0();
        __syncthreads();

        float acc[4][4];
#pragma unroll
        for (int nf = 0; nf < 4; nf++)
#pragma unroll
            for (int r = 0; r < 4; r++) acc[nf][r] = 0.f;

#pragma unroll
        for (int pass = 0; pass < 2; pass++) {
            const __half* Wsrc = pass ? sWlo : sWhi;
#pragma unroll
            for (int ks = 0; ks < 8; ks++) {
                uint32_t af[4];
                ldsm_x4(af, smem_u32(sA + (lane & 15) * SC_ROW
                                     + (kc + ks * 2 + (lane >> 4)) * 8));
                uint32_t br[2][4];
#pragma unroll
                for (int g = 0; g < 2; g++) {
                    int row = g * 16 + ((lane >> 4) << 3) + (lane & 7);
                    ldsm_x4(br[g], smem_u32(Wsrc + row * SC_ROW
                                            + (kc + ks * 2 + ((lane >> 3) & 1)) * 8));
                }
#pragma unroll
                for (int g = 0; g < 2; g++) {
                    mma16816(acc[g * 2],     af, &br[g][0]);
                    mma16816(acc[g * 2 + 1], af, &br[g][2]);
                }
            }
        }

        {
            float* pw = pf + w * 16 * SC_PF_STRIDE;
            int r0 = lane >> 2;
            int cb = (lane & 3) * 2;
#pragma unroll
            for (int nf = 0; nf < 4; nf++) {
                int c = nf * 8 + cb;
                *(float2*)(pw + r0 * SC_PF_STRIDE + c) =
                    make_float2(acc[nf][0], acc[nf][1]);
                *(float2*)(pw + (r0 + 8) * SC_PF_STRIDE + c) =
                    make_float2(acc[nf][2], acc[nf][3]);
            }
        }
        __syncthreads();

        if (tid < 128) {
            float gI = xv0, gF = xv1, gG = xv2, gO = xv3;
            const float* pw = pf + a_b * SC_PF_STRIDE + a_hil;
#pragma unroll
            for (int ww = 0; ww < 8; ww++) {
                const float* p = pw + ww * 16 * SC_PF_STRIDE;
                gI += p[0]; gF += p[8]; gG += p[16]; gO += p[24];
            }
            float cn = sigm(gF) * cloc + sigm(gI) * tanhf(gG);
            cloc = cn;
            float hv = sigm(gO) * tanhf(cn);
            hh[(size_t)(t + 1) * B_SZ * H_DIM + a_b * H_DIM + hb + a_hil] =
                __float2half_rn(hv);
        }
        __syncthreads();

        if (tid == 0) {
            red_rel_add(bar, 1u);
            const unsigned int target = 128u * (unsigned)(t + 1);
            while (ld_acq(bar) < target) { }
        }
        __syncthreads();
    }
}

// ---------------- fp16 convert / split kernels -------------------------------
__global__ void __launch_bounds__(256)
conv_a_k(const float* __restrict__ src, __half* __restrict__ dst, int n4)
{
    int i = blockIdx.x * blockDim.x + threadIdx.x;
    if (i >= n4) return;
    float4 v = ((const float4*)src)[i];
    __half h[4] = { __float2half_rn(v.x), __float2half_rn(v.y),
                    __float2half_rn(v.z), __float2half_rn(v.w) };
    ((__half2*)dst)[2 * i]     = __halves2half2(h[0], h[1]);
    ((__half2*)dst)[2 * i + 1] = __halves2half2(h[2], h[3]);
}

__global__ void __launch_bounds__(256)
conv_gather_k(const float* __restrict__ emb, const int* __restrict__ tokens,
              __half* __restrict__ dst)
{
    const int m = blockIdx.x;
    const float4* src = (const float4*)(emb + (size_t)tokens[m] * E_DIM);
    float4 v = src[threadIdx.x];
    __half2 h0 = __halves2half2(__float2half_rn(v.x), __float2half_rn(v.y));
    __half2 h1 = __halves2half2(__float2half_rn(v.z), __float2half_rn(v.w));
    __half2* d = (__half2*)(dst + (size_t)m * E_DIM);
    d[threadIdx.x * 2]     = h0;
    d[threadIdx.x * 2 + 1] = h1;
}

__global__ void __launch_bounds__(256)
split_w_k(const float* __restrict__ src, __half* __restrict__ hi,
          __half* __restrict__ lo, int n4)
{
    int i = blockIdx.x * blockDim.x + threadIdx.x;
    if (i >= n4) return;
    float4 v = ((const float4*)src)[i];
    float xs[4] = {v.x, v.y, v.z, v.w};
    __half h[4], l[4];
#pragma unroll
    for (int j = 0; j < 4; j++) {
        h[j] = __float2half_rn(xs[j]);
        l[j] = __float2half_rn(xs[j] - __half2float(h[j]));
    }
    ((__half2*)hi)[2 * i]     = __halves2half2(h[0], h[1]);
    ((__half2*)hi)[2 * i + 1] = __halves2half2(h[2], h[3]);
    ((__half2*)lo)[2 * i]     = __halves2half2(l[0], l[1]);
    ((__half2*)lo)[2 * i + 1] = __halves2half2(l[2], l[3]);
}

// ---------------- xW GEMM: fp16 mma, 2-pass (A pre-gathered) -----------------
#define DROW 40

__global__ void __launch_bounds__(256, 2)
xw_gemm(const __half* __restrict__ a_h,
        const __half* __restrict__ w_hi, const __half* __restrict__ w_lo,
        const float* __restrict__ bih, const float* __restrict__ bhh,
        float* __restrict__ out)
{
    __shared__ __align__(16) __half As[2][128 * DROW];
    __shared__ __align__(16) __half Bs[2][128 * DROW];

    const int tid  = threadIdx.x;
    const int lane = tid & 31;
    const int warp = tid >> 5;
    const int warpM = warp >> 2;
    const int warpN = warp & 3;
    const int bm = blockIdx.y * 128;
    const int bn = blockIdx.x * 128;

    const uint32_t sA[2] = { smem_u32(As[0]), smem_u32(As[1]) };
    const uint32_t sB[2] = { smem_u32(Bs[0]), smem_u32(Bs[1]) };

    float acc[4][4][4];
#pragma unroll
    for (int i = 0; i < 4; i++)
#pragma unroll
        for (int j = 0; j < 4; j++)
#pragma unroll
            for (int r = 0; r < 4; r++) acc[i][j][r] = 0.f;

    const int r0c = tid >> 2, c0c = tid & 3;
    const int r1c = r0c + 64;

    auto issue = [&](int it, int buf) {
        const int p  = it >> 5;
        const int k0 = (it & 31) * 32;
        const __half* Bp = p ? w_lo : w_hi;
        cp16(sA[buf] + (r0c * DROW + c0c * 8) * 2,
             a_h + (size_t)(bm + r0c) * E_DIM + k0 + c0c * 8);
        cp16(sA[buf] + (r1c * DROW + c0c * 8) * 2,
             a_h + (size_t)(bm + r1c) * E_DIM + k0 + c0c * 8);
        cp16(sB[buf] + (r0c * DROW + c0c * 8) * 2,
             Bp + (size_t)(bn + r0c) * E_DIM + k0 + c0c * 8);
        cp16(sB[buf] + (r1c * DROW + c0c * 8) * 2,
             Bp + (size_t)(bn + r1c) * E_DIM + k0 + c0c * 8);
    };

    issue(0, 0);
    CP_COMMIT();

    for (int it = 0; it < 64; it++) {
        const int buf = it & 1;
        if (it + 1 < 64) { issue(it + 1, buf ^ 1); CP_COMMIT(); CP_WAIT1(); }
        else             { CP_WAIT0(); }
        __syncthreads();

#pragma unroll
        for (int ks = 0; ks < 2; ks++) {
            uint32_t af[4][4];
#pragma unroll
            for (int mf = 0; mf < 4; mf++) {
                int row = warpM * 64 + mf * 16 + (lane & 15);
                int ch  = ks * 2 + (lane >> 4);
                ldsm_x4(af[mf], sA[buf] + (row * DROW + ch * 8) * 2);
            }
            uint32_t br[2][4];
#pragma unroll
            for (int g = 0; g < 2; g++) {
                int row = warpN * 32 + g * 16 + ((lane >> 4) << 3) + (lane & 7);
                int ch  = ks * 2 + ((lane >> 3) & 1);
                ldsm_x4(br[g], sB[buf] + (row * DROW + ch * 8) * 2);
            }
#pragma unroll
            for (int mf = 0; mf < 4; mf++)
#pragma unroll
                for (int g = 0; g < 2; g++) {
                    mma16816(acc[mf][g * 2],     af[mf], &br[g][0]);
                    mma16816(acc[mf][g * 2 + 1], af[mf], &br[g][2]);
                }
        }
        __syncthreads();
    }

#pragma unroll
    for (int mf = 0; mf < 4; mf++) {
        int rowA = bm + warpM * 64 + mf * 16 + (lane >> 2);
        int rowB = rowA + 8;
#pragma unroll
        for (int nf = 0; nf < 4; nf++) {
            int col = bn + warpN * 32 + nf * 8 + (lane & 3) * 2;
            float b0 = bih[col]     + bhh[col];
            float b1 = bih[col + 1] + bhh[col + 1];
            out[(size_t)rowA * G4 + col]     = acc[mf][nf][0] + b0;
            out[(size_t)rowA * G4 + col + 1] = acc[mf][nf][1] + b1;
            out[(size_t)rowB * G4 + col]     = acc[mf][nf][2] + b0;
            out[(size_t)rowB * G4 + col + 1] = acc[mf][nf][3] + b1;
        }
    }
}

// ---------------- step-5 GEMM: fp16 mma 2-pass, fused mask+hm, fp16 out -----
// outputs[m][n] = (m/16 < k) ? a_h_in[m][n] (fp16 h chain)
//                            : a_h_in[m] @ (W2hi+W2lo)[n]^T + bhh2[n] + hm[m%16][n]
__global__ void __launch_bounds__(256, 2)
out_gemm(const __half* __restrict__ a_h,
         const __half* __restrict__ w_hi, const __half* __restrict__ w_lo,
         const float* __restrict__ bhh2, const float* __restrict__ hmv,
         const int* __restrict__ kptr,
         __half* __restrict__ outh)
{
    __shared__ __align__(16) __half As[2][128 * DROW];
    __shared__ __align__(16) __half Bs[2][128 * DROW];

    const int tid  = threadIdx.x;
    const int lane = tid & 31;
    const int warp = tid >> 5;
    const int warpM = warp >> 2;
    const int warpN = warp & 3;
    const int bm = blockIdx.y * 128;
    const int bn = blockIdx.x * 128;

    const uint32_t sA[2] = { smem_u32(As[0]), smem_u32(As[1]) };
    const uint32_t sB[2] = { smem_u32(Bs[0]), smem_u32(Bs[1]) };

    float acc[4][4][4];
#pragma unroll
    for (int i = 0; i < 4; i++)
#pragma unroll
        for (int j = 0; j < 4; j++)
#pragma unroll
            for (int r = 0; r < 4; r++) acc[i][j][r] = 0.f;

    const int r0c = tid >> 2, c0c = tid & 3;
    const int r1c = r0c + 64;

    auto issue = [&](int it, int buf) {
        const int p  = it >> 5;
        const int k0 = (it & 31) * 32;
        const __half* Bp = p ? w_lo : w_hi;
        cp16(sA[buf] + (r0c * DROW + c0c * 8) * 2,
             a_h + (size_t)(bm + r0c) * H_DIM + k0 + c0c * 8);
        cp16(sA[buf] + (r1c * DROW + c0c * 8) * 2,
             a_h + (size_t)(bm + r1c) * H_DIM + k0 + c0c * 8);
        cp16(sB[buf] + (r0c * DROW + c0c * 8) * 2,
             Bp + (size_t)(bn + r0c) * H_DIM + k0 + c0c * 8);
        cp16(sB[buf] + (r1c * DROW + c0c * 8) * 2,
             Bp + (size_t)(bn + r1c) * H_DIM + k0 + c0c * 8);
    };

    issue(0, 0);
    CP_COMMIT();

    for (int it = 0; it < 64; it++) {
        const int buf = it & 1;
        if (it + 1 < 64) { issue(it + 1, buf ^ 1); CP_COMMIT(); CP_WAIT1(); }
        else             { CP_WAIT0(); }
        __syncthreads();

#pragma unroll
        for (int ks = 0; ks < 2; ks++) {
            uint32_t af[4][4];
#pragma unroll
            for (int mf = 0; mf < 4; mf++) {
                int row = warpM * 64 + mf * 16 + (lane & 15);
                int ch  = ks * 2 + (lane >> 4);
                ldsm_x4(af[mf], sA[buf] + (row * DROW + ch * 8) * 2);
            }
            uint32_t br[2][4];
#pragma unroll
            for (int g = 0; g < 2; g++) {
                int row = warpN * 32 + g * 16 + ((lane >> 4) << 3) + (lane & 7);
                int ch  = ks * 2 + ((lane >> 3) & 1);
                ldsm_x4(br[g], sB[buf] + (row * DROW + ch * 8) * 2);
            }
#pragma unroll
            for (int mf = 0; mf < 4; mf++)
#pragma unroll
                for (int g = 0; g < 2; g++) {
                    mma16816(acc[mf][g * 2],     af[mf], &br[g][0]);
                    mma16816(acc[mf][g * 2 + 1], af[mf], &br[g][2]);
                }
        }
        __syncthreads();
    }

    const int kval = *kptr;
#pragma unroll
    for (int mf = 0; mf < 4; mf++) {
        int rows[2];
        rows[0] = bm + warpM * 64 + mf * 16 + (lane >> 2);
        rows[1] = rows[0] + 8;
#pragma unroll
        for (int rr = 0; rr < 2; rr++) {
            int row = rows[rr];
            int srow = row >> 4;
            int b    = row & 15;
            bool cp = (srow < kval);
#pragma unroll
            for (int nf = 0; nf < 4; nf++) {
                int col = bn + warpN * 32 + nf * 8 + (lane & 3) * 2;
                if (cp) {
                    outh[(size_t)row * H_DIM + col]     = a_h[(size_t)row * H_DIM + col];
                    outh[(size_t)row * H_DIM + col + 1] = a_h[(size_t)row * H_DIM + col + 1];
                } else {
                    float v0 = acc[mf][nf][rr * 2]     + bhh2[col]     + hmv[b * H_DIM + col];
                    float v1 = acc[mf][nf][rr * 2 + 1] + bhh2[col + 1] + hmv[b * H_DIM + col + 1];
                    outh[(size_t)row * H_DIM + col]     = __float2half_rn(v0);
                    outh[(size_t)row * H_DIM + col + 1] = __float2half_rn(v1);
                }
            }
        }
    }
}

// ---------------- mma.sync decoder GEMM (fp16, single pass, 2 CTAs/SM) ------
__global__ void __launch_bounds__(256, 2)
dec_gemm(const __half* __restrict__ a_h, const __half* __restrict__ b_h,
         const float* __restrict__ bias, float* __restrict__ out)
{
    __shared__ __align__(16) __half As[2][128 * DROW];
    __shared__ __align__(16) __half Bs[2][128 * DROW];

    const int tid  = threadIdx.x;
    const int lane = tid & 31;
    const int warp = tid >> 5;
    const int warpM = warp >> 2;
    const int warpN = warp & 3;
    const int bm = blockIdx.y * 128;
    const int bn = blockIdx.x * 128;

    const uint32_t sA[2] = { smem_u32(As[0]), smem_u32(As[1]) };
    const uint32_t sB[2] = { smem_u32(Bs[0]), smem_u32(Bs[1]) };

    float acc[4][4][4];
#pragma unroll
    for (int i = 0; i < 4; i++)
#pragma unroll
        for (int j = 0; j < 4; j++)
#pragma unroll
            for (int r = 0; r < 4; r++) acc[i][j][r] = 0.f;

    const int r0c = tid >> 2, c0c = tid & 3;
    const int r1c = (tid + 256) >> 2, c1c = tid & 3;

    auto issue = [&](int it, int buf) {
        const int k0 = it * 32;
        cp16(sA[buf] + (r0c * DROW + c0c * 8) * 2,
             a_h + (size_t)(bm + r0c) * H_DIM + k0 + c0c * 8);
        cp16(sA[buf] + (r1c * DROW + c1c * 8) * 2,
             a_h + (size_t)(bm + r1c) * H_DIM + k0 + c1c * 8);
        cp16(sB[buf] + (r0c * DROW + c0c * 8) * 2,
             b_h + (size_t)(bn + r0c) * H_DIM + k0 + c0c * 8);
        cp16(sB[buf] + (r1c * DROW + c1c * 8) * 2,
             b_h + (size_t)(bn + r1c) * H_DIM + k0 + c1c * 8);
    };

    issue(0, 0);
    CP_COMMIT();

    for (int it = 0; it < 32; it++) {
        const int buf = it & 1;
        if (it + 1 < 32) { issue(it + 1, buf ^ 1); CP_COMMIT(); CP_WAIT1(); }
        else             { CP_WAIT0(); }
        __syncthreads();

#pragma unroll
        for (int ks = 0; ks < 2; ks++) {
            uint32_t af[4][4];
#pragma unroll
            for (int mf = 0; mf < 4; mf++) {
                int row = warpM * 64 + mf * 16 + (lane & 15);
                int ch  = ks * 2 + (lane >> 4);
                ldsm_x4(af[mf], sA[buf] + (row * DROW + ch * 8) * 2);
            }
            uint32_t br[2][4];
#pragma unroll
            for (int g = 0; g < 2; g++) {
                int row = warpN * 32 + g * 16 + ((lane >> 4) << 3) + (lane & 7);
                int ch  = ks * 2 + ((lane >> 3) & 1);
                ldsm_x4(br[g], sB[buf] + (row * DROW + ch * 8) * 2);
            }
#pragma unroll
            for (int mf = 0; mf < 4; mf++)
#pragma unroll
                for (int g = 0; g < 2; g++) {
                    mma16816(acc[mf][g * 2],     af[mf], &br[g][0]);
                    mma16816(acc[mf][g * 2 + 1], af[mf], &br[g][2]);
                }
        }
        __syncthreads();
    }

#pragma unroll
    for (int mf = 0; mf < 4; mf++) {
        int rowA = bm + warpM * 64 + mf * 16 + (lane >> 2);
        int rowB = rowA + 8;
#pragma unroll
        for (int nf = 0; nf < 4; nf++) {
            int col = bn + warpN * 32 + nf * 8 + (lane & 3) * 2;
            float b0 = (col     < V_SZ) ? bias[col]     : 0.f;
            float b1 = (col + 1 < V_SZ) ? bias[col + 1] : 0.f;
            if (col < V_SZ)     out[(size_t)rowA * V_SZ + col]     = acc[mf][nf][0] + b0;
            if (col + 1 < V_SZ) out[(size_t)rowA * V_SZ + col + 1] = acc[mf][nf][1] + b1;
            if (col < V_SZ)     out[(size_t)rowB * V_SZ + col]     = acc[mf][nf][2] + b0;
            if (col + 1 < V_SZ) out[(size_t)rowB * V_SZ + col + 1] = acc[mf][nf][3] + b1;
        }
    }
}

// ---------------- launcher --------------------------------------------------
extern "C" void kernel_launch(void* const* d_in, const int* in_sizes, int n_in,
                              void* d_out, int out_size)
{
    const int*   tokens = (const int*)  d_in[0];
    const float* h0     = (const float*)d_in[1];
    const float* c0     = (const float*)d_in[2];
    const float* emb    = (const float*)d_in[3];
    const float* Wih    = (const float*)d_in[4];
    const float* Whh    = (const float*)d_in[5];
    const float* bih    = (const float*)d_in[6];
    const float* bhh    = (const float*)d_in[7];
    const float* Whh2   = (const float*)d_in[8];
    const float* bhh2   = (const float*)d_in[9];
    const float* Whm    = (const float*)d_in[10];
    const float* bhm    = (const float*)d_in[11];
    const float* decW   = (const float*)d_in[12];
    const float* decb   = (const float*)d_in[13];
    const int*   kp     = (const int*)  d_in[14];
    float* out = (float*)d_out;

    void *p_xW, *p_hm, *p_bar, *p_ah, *p_bh, *p_wh, *p_wl,
         *p_whh, *p_whl, *p_w2h, *p_w2l, *p_hh;
    cudaGetSymbolAddress(&p_xW,   g_xW);
    cudaGetSymbolAddress(&p_hm,   g_hm);
    cudaGetSymbolAddress(&p_bar,  g_bar);
    cudaGetSymbolAddress(&p_ah,   g_a_h);
    cudaGetSymbolAddress(&p_bh,   g_b_h);
    cudaGetSymbolAddress(&p_wh,   g_wih_hi);
    cudaGetSymbolAddress(&p_wl,   g_wih_lo);
    cudaGetSymbolAddress(&p_whh,  g_whh_hi);
    cudaGetSymbolAddress(&p_whl,  g_whh_lo);
    cudaGetSymbolAddress(&p_w2h,  g_w2_hi);
    cudaGetSymbolAddress(&p_w2l,  g_w2_lo);
    cudaGetSymbolAddress(&p_hh,   g_hh);
    float* xW   = (float*)p_xW;
    float* hm   = (float*)p_hm;
    unsigned int* bar = (unsigned int*)p_bar;
    __half* ah  = (__half*)p_ah;
    __half* bh  = (__half*)p_bh;
    __half* wh  = (__half*)p_wh;
    __half* wl  = (__half*)p_wl;
    __half* whh = (__half*)p_whh;
    __half* whl = (__half*)p_whl;
    __half* w2h = (__half*)p_w2h;
    __half* w2l = (__half*)p_w2l;
    __half* hh  = (__half*)p_hh;

    cudaFuncSetAttribute(lstm_scan_mma,
                         cudaFuncAttributeMaxDynamicSharedMemorySize, SC_SMEM);

    const int M = S_LEN * B_SZ;   // 2048

    // 0) conversions needed BEFORE the scan: gather emb -> fp16; Wih/Whh -> hi/lo;
    //    h0 -> fp16 chain slot 0   (decW + Whh2 conversions moved into scan helpers)
    conv_gather_k<<<M, 256>>>(emb, tokens, ah);
    split_w_k<<<(G4 * E_DIM / 4 + 255) / 256, 256>>>(Wih, wh, wl, G4 * E_DIM / 4);
    split_w_k<<<(G4 * H_DIM / 4 + 255) / 256, 256>>>(Whh, whh, whl, G4 * H_DIM / 4);
    conv_a_k<<<(B_SZ * H_DIM / 4 + 255) / 256, 256>>>(h0, hh, B_SZ * H_DIM / 4);

    // 1) xW = a_h @ (Wih_hi+Wih_lo)^T + bih + bhh  (mma, 2-pass)
    xw_gemm<<<dim3(G4 / 128, M / 128), 256>>>(ah, wh, wl, bih, bhh, xW);

    // 2) hm = h0 @ Whm^T + bhm  (fp32 SIMT, tiny)
    gemm_k<<<dim3(H_DIM / 128, 1), 256>>>(
        h0, Whm, hm, B_SZ, H_DIM, H_DIM, bhm);

    // 3) reset grid barrier
    cudaMemsetAsync(bar, 0, sizeof(unsigned int), 0);

    // 4) persistent tensor-core LSTM scan + helper CTAs converting decW/Whh2
    lstm_scan_mma<<<SC_GRID, 256, SC_SMEM>>>(
        c0, whh, whl, xW, hh, bar, decW, bh, Whh2, w2h, w2l);

    // 5) outputs (fp16, fused mask+hm+bias) = hs_h @ Whh2^T ...  -> g_a_h
    out_gemm<<<dim3(H_DIM / 128, M / 128), 256>>>(
        hh + B_SZ * H_DIM, w2h, w2l, bhh2, hm, kp, ah);

    // 6) decoded = outputs @ decW^T + decb  — mma.sync fp16 single-pass GEMM
    dec_gemm<<<dim3(V_PAD / 128, M / 128), 256>>>(ah, bh, decb, out);

    (void)in_sizes; (void)n_in; (void)out_size;
}